// round 1
// baseline (speedup 1.0000x reference)
#include <cuda_runtime.h>
#include <cstdint>
#include <cstddef>

// ---------------------------------------------------------------------------
// Problem dims
// ---------------------------------------------------------------------------
constexpr int Bd = 16, Ld = 128, Rd = 512, Fd = 256, Hd = 8, FHd = 32, FEd = 64, Ed = 16384;
constexpr int HFd = 256;

__device__ __forceinline__ float lrelu(float x) { return x > 0.f ? x : 0.01f * x; }

// Scratch for expand branch (device globals: allocation-free)
__device__ float g_xf[Bd * Ld * HFd];   // 2 MB
__device__ float g_yf[Bd * Rd * HFd];   // 8 MB

// ---------------------------------------------------------------------------
// Contract kernel: one block per (b, x).
// GEMM: of[y, n] = lrelu(ll[b,x,y,:]) @ Wc^T + bc   (128 x 256 x 256)
// logits[y,h] accumulated in same k-loop; layernorm rows; masked softmax over y;
// contracted[n] = sum_y atn[y, n/32] * of[y, n].
// ---------------------------------------------------------------------------
constexpr int OF_LD = 260;
constexpr int A_LD  = 17;
constexpr int W_LD  = 260;
constexpr int SM_OF  = 0;
constexpr int SM_A   = SM_OF + 128 * OF_LD;          // 33280
constexpr int SM_W   = SM_A + 128 * A_LD;            // 35456
constexpr int SM_WCA = SM_W + 16 * W_LD;             // 39616
constexpr int SM_LG  = SM_WCA + 8 * 256;             // 41664
constexpr int SM_G   = SM_LG + 128 * 8;              // 42688
constexpr int SM_BE  = SM_G + 256;                   // 42944
constexpr int SM_SUM = SM_BE + 256;                  // 43200
constexpr int SM_CONTRACT_FLOATS = SM_SUM + 16;      // 43216
constexpr int SM_CONTRACT_BYTES  = SM_CONTRACT_FLOATS * 4;   // ~172.9 KB

__global__ void __launch_bounds__(512, 1)
k_contract(const float* __restrict__ ll, const unsigned* __restrict__ mask,
           const float* __restrict__ Wc, const float* __restrict__ bc,
           const float* __restrict__ gc, const float* __restrict__ bec,
           const float* __restrict__ Wca, const float* __restrict__ bca,
           float* __restrict__ out)
{
    extern __shared__ float sm[];
    const int t = threadIdx.x;
    const int x = blockIdx.x, b = blockIdx.y;
    const int warp = t >> 5, lane = t & 31;
    const int wy = warp >> 2, wn = warp & 3;
    const int ly = lane >> 3, ln = lane & 7;
    const int ybase = wy * 32 + ly * 8;
    const int nbase = wn * 64 + ln * 8;

    // static smem: gamma/beta, Wca
    if (t < 256) { sm[SM_G + t] = gc[t]; sm[SM_BE + t] = bec[t]; }
#pragma unroll
    for (int s = 0; s < 4; s++) { int m = t + s * 512; sm[SM_WCA + m] = Wca[m]; }

    float acc[8][8];
#pragma unroll
    for (int i = 0; i < 8; i++)
#pragma unroll
        for (int j = 0; j < 8; j++) acc[i][j] = 0.f;

    float lg0 = 0.f, lg1 = 0.f;
    const int ylg = t & 127, hlg = t >> 7;   // (y, h) and (y, h+4)

    const float* Arow = ll + (size_t)(b * Ld + x) * Ld * Fd;

    for (int k0 = 0; k0 < Fd; k0 += 16) {
        __syncthreads();
        // stage A chunk (activated): 128 y x 16 k
        {
            int y = t >> 2, kq = (t & 3) * 4;
            float4 v = *(const float4*)(Arow + y * Fd + k0 + kq);
            sm[SM_A + y * A_LD + kq + 0] = lrelu(v.x);
            sm[SM_A + y * A_LD + kq + 1] = lrelu(v.y);
            sm[SM_A + y * A_LD + kq + 2] = lrelu(v.z);
            sm[SM_A + y * A_LD + kq + 3] = lrelu(v.w);
        }
        // stage W chunk transposed: sW[k][n] = Wc[n][k0+k]
#pragma unroll
        for (int s = 0; s < 2; s++) {
            int m = t + s * 512;
            int n = m >> 2, kq = (m & 3) * 4;
            float4 v = *(const float4*)(Wc + n * Fd + k0 + kq);
            sm[SM_W + (kq + 0) * W_LD + n] = v.x;
            sm[SM_W + (kq + 1) * W_LD + n] = v.y;
            sm[SM_W + (kq + 2) * W_LD + n] = v.z;
            sm[SM_W + (kq + 3) * W_LD + n] = v.w;
        }
        __syncthreads();
#pragma unroll
        for (int kk = 0; kk < 16; kk++) {
            float a[8];
#pragma unroll
            for (int i = 0; i < 8; i++) a[i] = sm[SM_A + (ybase + i) * A_LD + kk];
            float4 b0 = *(const float4*)&sm[SM_W + kk * W_LD + nbase];
            float4 b1 = *(const float4*)&sm[SM_W + kk * W_LD + nbase + 4];
            float bb[8] = {b0.x, b0.y, b0.z, b0.w, b1.x, b1.y, b1.z, b1.w};
#pragma unroll
            for (int i = 0; i < 8; i++)
#pragma unroll
                for (int j = 0; j < 8; j++) acc[i][j] += a[i] * bb[j];
            // attention logits (each thread: 2 of the 128*8 items)
            float av = sm[SM_A + ylg * A_LD + kk];
            lg0 += av * sm[SM_WCA + hlg * 256 + k0 + kk];
            lg1 += av * sm[SM_WCA + (hlg + 4) * 256 + k0 + kk];
        }
    }

    // epilogue: bias, store of + logits
    float bcv[8];
    *(float4*)&bcv[0] = *(const float4*)(bc + nbase);
    *(float4*)&bcv[4] = *(const float4*)(bc + nbase + 4);
    sm[SM_LG + ylg * 8 + hlg]     = lg0 + bca[hlg];
    sm[SM_LG + ylg * 8 + hlg + 4] = lg1 + bca[hlg + 4];
#pragma unroll
    for (int i = 0; i < 8; i++)
#pragma unroll
        for (int j = 0; j < 8; j++)
            sm[SM_OF + (ybase + i) * OF_LD + nbase + j] = acc[i][j] + bcv[j];
    __syncthreads();

    // layernorm: warp w handles rows w*8 .. w*8+7
#pragma unroll
    for (int rr = 0; rr < 8; rr++) {
        int y = warp * 8 + rr;
        float vals[8], s = 0.f;
#pragma unroll
        for (int q = 0; q < 8; q++) { vals[q] = sm[SM_OF + y * OF_LD + lane + q * 32]; s += vals[q]; }
#pragma unroll
        for (int o = 16; o; o >>= 1) s += __shfl_xor_sync(0xffffffffu, s, o);
        float mu = s * (1.f / 256.f);
        float vs = 0.f;
#pragma unroll
        for (int q = 0; q < 8; q++) { float d = vals[q] - mu; vs += d * d; }
#pragma unroll
        for (int o = 16; o; o >>= 1) vs += __shfl_xor_sync(0xffffffffu, vs, o);
        float rs = rsqrtf(vs * (1.f / 256.f) + 1e-5f);
#pragma unroll
        for (int q = 0; q < 8; q++) {
            int c = lane + q * 32;
            sm[SM_OF + y * OF_LD + c] = sm[SM_G + c] * ((vals[q] - mu) * rs) + sm[SM_BE + c];
        }
    }
    __syncthreads();

    // masked softmax over y, per h (warps 0..7). max over ALL y (ref semantics),
    // masked entries zeroed before sum; denom = sum + 1e-10.
    if (warp < 8) {
        int h = warp;
        float lv[4];
#pragma unroll
        for (int q = 0; q < 4; q++) lv[q] = sm[SM_LG + (lane + q * 32) * 8 + h];
        float mx = fmaxf(fmaxf(lv[0], lv[1]), fmaxf(lv[2], lv[3]));
#pragma unroll
        for (int o = 16; o; o >>= 1) mx = fmaxf(mx, __shfl_xor_sync(0xffffffffu, mx, o));
        const unsigned* mrow = mask + (size_t)(b * Ld + x) * Ld;
        float e[4], sum = 0.f;
#pragma unroll
        for (int q = 0; q < 4; q++) {
            int y = lane + q * 32;
            float ee = (mrow[y] != 0u) ? expf(lv[q] - mx) : 0.f;
            e[q] = ee; sum += ee;
        }
#pragma unroll
        for (int o = 16; o; o >>= 1) sum += __shfl_xor_sync(0xffffffffu, sum, o);
#pragma unroll
        for (int q = 0; q < 4; q++) sm[SM_LG + (lane + q * 32) * 8 + h] = e[q];
        if (lane == 0) sm[SM_SUM + h] = sum + 1e-10f;
    }
    __syncthreads();

    // contraction over y: 256 outputs
    if (t < 256) {
        int n = t, h = n >> 5;
        float a = 0.f;
#pragma unroll 8
        for (int y = 0; y < 128; y++) a += sm[SM_LG + y * 8 + h] * sm[SM_OF + y * OF_LD + n];
        out[(size_t)(b * Ld + x) * HFd + n] = a / sm[SM_SUM + h];
    }
}

// ---------------------------------------------------------------------------
// NormAndLinear for lig/rec: block = 16 rows, thread = output column.
// ---------------------------------------------------------------------------
__global__ void __launch_bounds__(256)
k_normlin(const float* __restrict__ X, const float* __restrict__ W,
          const float* __restrict__ bias, const float* __restrict__ g,
          const float* __restrict__ be, float* __restrict__ out)
{
    __shared__ float sX[16 * 260];
    __shared__ float sH[16 * 260];
    const int t = threadIdx.x;
    const int row0 = blockIdx.x * 16;

#pragma unroll
    for (int s = 0; s < 4; s++) {
        int m = t + s * 256;                 // float4 id, 1024 total
        int r = m >> 6, c = (m & 63) * 4;
        float4 v = *(const float4*)(X + (size_t)(row0 + r) * Fd + c);
        sX[r * 260 + c + 0] = lrelu(v.x);
        sX[r * 260 + c + 1] = lrelu(v.y);
        sX[r * 260 + c + 2] = lrelu(v.z);
        sX[r * 260 + c + 3] = lrelu(v.w);
    }
    __syncthreads();

    float acc[16];
#pragma unroll
    for (int r = 0; r < 16; r++) acc[r] = 0.f;
    const int n = t;
    for (int k0 = 0; k0 < 256; k0 += 8) {
        float w[8];
        *(float4*)&w[0] = *(const float4*)(W + (size_t)n * Fd + k0);
        *(float4*)&w[4] = *(const float4*)(W + (size_t)n * Fd + k0 + 4);
#pragma unroll
        for (int r = 0; r < 16; r++) {
            float a[8];
            *(float4*)&a[0] = *(const float4*)&sX[r * 260 + k0];
            *(float4*)&a[4] = *(const float4*)&sX[r * 260 + k0 + 4];
#pragma unroll
            for (int kk = 0; kk < 8; kk++) acc[r] += a[kk] * w[kk];
        }
    }
    float bv = bias[n];
#pragma unroll
    for (int r = 0; r < 16; r++) sH[r * 260 + n] = acc[r] + bv;
    __syncthreads();

    const int warp = t >> 5, lane = t & 31;
#pragma unroll
    for (int rr = 0; rr < 2; rr++) {
        int r = warp * 2 + rr;
        float vals[8], s = 0.f;
#pragma unroll
        for (int q = 0; q < 8; q++) { vals[q] = sH[r * 260 + lane + q * 32]; s += vals[q]; }
#pragma unroll
        for (int o = 16; o; o >>= 1) s += __shfl_xor_sync(0xffffffffu, s, o);
        float mu = s * (1.f / 256.f);
        float vs = 0.f;
#pragma unroll
        for (int q = 0; q < 8; q++) { float d = vals[q] - mu; vs += d * d; }
#pragma unroll
        for (int o = 16; o; o >>= 1) vs += __shfl_xor_sync(0xffffffffu, vs, o);
        float rstd = rsqrtf(vs * (1.f / 256.f) + 1e-5f);
#pragma unroll
        for (int q = 0; q < 8; q++) {
            int c = lane + q * 32;
            out[(size_t)(row0 + r) * 256 + c] = g[c] * ((vals[q] - mu) * rstd) + be[c];
        }
    }
}

// ---------------------------------------------------------------------------
// Expand: out[b,x,y,h] = sum_f xf[b,x,h,f]*yf[b,y,h,f]
// grid (xt=8, yt=16, b=16), 16 x-rows and 32 y-rows per block.
// ---------------------------------------------------------------------------
__global__ void __launch_bounds__(256)
k_expand(float* __restrict__ out)
{
    __shared__ float sX[16 * 8 * 36];
    __shared__ float sY[32 * 8 * 36];
    const int t = threadIdx.x;
    const int x0 = blockIdx.x * 16, y0 = blockIdx.y * 32, b = blockIdx.z;

#pragma unroll
    for (int s = 0; s < 4; s++) {                       // sX: 1024 float4
        int m = t + s * 256;
        int xi = m >> 6, c = (m & 63) * 4;
        int h = c >> 5, f = c & 31;
        float4 v = *(const float4*)(g_xf + (size_t)(b * Ld + x0 + xi) * HFd + c);
        float* d = &sX[(xi * 8 + h) * 36 + f];
        d[0] = v.x; d[1] = v.y; d[2] = v.z; d[3] = v.w;
    }
#pragma unroll
    for (int s = 0; s < 8; s++) {                       // sY: 2048 float4
        int m = t + s * 256;
        int yi = m >> 6, c = (m & 63) * 4;
        int h = c >> 5, f = c & 31;
        float4 v = *(const float4*)(g_yf + (size_t)(b * Rd + y0 + yi) * HFd + c);
        float* d = &sY[(yi * 8 + h) * 36 + f];
        d[0] = v.x; d[1] = v.y; d[2] = v.z; d[3] = v.w;
    }
    __syncthreads();

    const int h = t & 7, yy = t >> 3;
    float acc[16];
#pragma unroll
    for (int xi = 0; xi < 16; xi++) acc[xi] = 0.f;
#pragma unroll
    for (int f4 = 0; f4 < 32; f4 += 4) {
        float4 yv = *(const float4*)&sY[(yy * 8 + h) * 36 + f4];
#pragma unroll
        for (int xi = 0; xi < 16; xi++) {
            float4 xv = *(const float4*)&sX[(xi * 8 + h) * 36 + f4];
            acc[xi] += xv.x * yv.x + xv.y * yv.y + xv.z * yv.z + xv.w * yv.w;
        }
    }
#pragma unroll
    for (int xi = 0; xi < 16; xi++)
        out[((size_t)(b * Ld + x0 + xi) * Rd + y0 + yy) * Hd + h] = acc[xi];
}

// ---------------------------------------------------------------------------
// Zero llf region
// ---------------------------------------------------------------------------
__global__ void __launch_bounds__(256)
k_zero(float4* __restrict__ p)   // 4,194,304 float4
{
    size_t base = ((size_t)blockIdx.x * 256 + threadIdx.x) * 4;
#pragma unroll
    for (int i = 0; i < 4; i++) p[base + i] = make_float4(0.f, 0.f, 0.f, 0.f);
}

// ---------------------------------------------------------------------------
// Edge: gather -> linear(2F->FE) -> lrelu -> atomic scatter into llf.
// 128 blocks x 128 edges; We^T staged in smem; 32 edges staged per iter.
// ---------------------------------------------------------------------------
constexpr int WET_LD = 68;
constexpr int EDGE_SMEM_FLOATS = 512 * WET_LD + 32 * 512;   // 51,200
constexpr int EDGE_SMEM_BYTES  = EDGE_SMEM_FLOATS * 4;      // 204,800

__global__ void __launch_bounds__(256, 1)
k_edge(const float* __restrict__ lig, const int* __restrict__ eb,
       const int* __restrict__ es, const int* __restrict__ ed,
       const float* __restrict__ We, const float* __restrict__ be,
       float* __restrict__ llf)
{
    extern __shared__ float sm[];
    float* sWeT = sm;                 // [512][68]
    float* sEF  = sm + 512 * WET_LD;  // [32][512]
    const int t = threadIdx.x;

    // stage We transposed: sWeT[k][o] = We[o][k]
#pragma unroll 8
    for (int s = 0; s < 128; s++) {
        int m = t + s * 256;
        int k = m & 511, o = m >> 9;
        sWeT[k * WET_LD + o] = We[o * 512 + k];
    }

    const int to = t & 7;        // output group: o = to*8 .. to*8+7
    const int te = t >> 3;       // edge within the 32-edge stage
    float bev[8];
#pragma unroll
    for (int c = 0; c < 8; c++) bev[c] = be[to * 8 + c];

    for (int iter = 0; iter < 4; iter++) {
        __syncthreads();
        // stage 32 edges' concatenated features (4096 float4)
#pragma unroll
        for (int s = 0; s < 16; s++) {
            int m = t + s * 256;
            int eg = m >> 7, kq = m & 127;
            int k = kq * 4;
            int e = blockIdx.x * 128 + iter * 32 + eg;
            int bb = eb[e];
            int row = (k < 256) ? es[e] : ed[e];
            int col = (k < 256) ? k : (k - 256);
            float4 v = *(const float4*)(lig + (size_t)(bb * Ld + row) * Fd + col);
            float* d = &sEF[eg * 512 + k];
            d[0] = v.x; d[1] = v.y; d[2] = v.z; d[3] = v.w;
        }
        __syncthreads();

        float acc[8];
#pragma unroll
        for (int c = 0; c < 8; c++) acc[c] = 0.f;
#pragma unroll 4
        for (int k = 0; k < 512; k++) {
            float a = sEF[te * 512 + k];
            float4 w0 = *(const float4*)&sWeT[k * WET_LD + to * 8];
            float4 w1 = *(const float4*)&sWeT[k * WET_LD + to * 8 + 4];
            acc[0] += a * w0.x; acc[1] += a * w0.y; acc[2] += a * w0.z; acc[3] += a * w0.w;
            acc[4] += a * w1.x; acc[5] += a * w1.y; acc[6] += a * w1.z; acc[7] += a * w1.w;
        }
        int e = blockIdx.x * 128 + iter * 32 + te;
        int bb = eb[e], ss = es[e], dd = ed[e];
        float* dst = llf + ((size_t)(bb * Ld + ss) * Ld + dd) * FEd + to * 8;
#pragma unroll
        for (int c = 0; c < 8; c++) atomicAdd(dst + c, lrelu(acc[c] + bev[c]));
    }
}

// ---------------------------------------------------------------------------
// Launch
// ---------------------------------------------------------------------------
extern "C" void kernel_launch(void* const* d_in, const int* in_sizes, int n_in,
                              void* d_out, int out_size)
{
    const float*    ll   = (const float*)d_in[0];
    const float*    lig  = (const float*)d_in[1];
    const float*    rec  = (const float*)d_in[2];
    const unsigned* mask = (const unsigned*)d_in[3];
    const int*      eb   = (const int*)d_in[4];
    const int*      es   = (const int*)d_in[5];
    const int*      ed   = (const int*)d_in[6];
    const float*    Wc   = (const float*)d_in[7];
    const float*    bc   = (const float*)d_in[8];
    const float*    gcc  = (const float*)d_in[9];
    const float*    bec  = (const float*)d_in[10];
    const float*    Wca  = (const float*)d_in[11];
    const float*    bca  = (const float*)d_in[12];
    const float*    Wex  = (const float*)d_in[13];
    const float*    bex  = (const float*)d_in[14];
    const float*    gex  = (const float*)d_in[15];
    const float*    beex = (const float*)d_in[16];
    const float*    Wey  = (const float*)d_in[17];
    const float*    bey  = (const float*)d_in[18];
    const float*    gey  = (const float*)d_in[19];
    const float*    beey = (const float*)d_in[20];
    const float*    We   = (const float*)d_in[21];
    const float*    be   = (const float*)d_in[22];

    float* out = (float*)d_out;
    float* oC = out;
    float* oE = out + (size_t)Bd * Ld * HFd;
    float* oL = oE + (size_t)Bd * Ld * Rd * Hd;

    cudaFuncSetAttribute(k_contract, cudaFuncAttributeMaxDynamicSharedMemorySize, SM_CONTRACT_BYTES);
    cudaFuncSetAttribute(k_edge, cudaFuncAttributeMaxDynamicSharedMemorySize, EDGE_SMEM_BYTES);

    void* pxf = nullptr; void* pyf = nullptr;
    cudaGetSymbolAddress(&pxf, g_xf);
    cudaGetSymbolAddress(&pyf, g_yf);

    // expand branch
    k_normlin<<<128, 256>>>(lig, Wex, bex, gex, beex, (float*)pxf);
    k_normlin<<<512, 256>>>(rec, Wey, bey, gey, beey, (float*)pyf);
    k_expand<<<dim3(8, 16, 16), 256>>>(oE);

    // edge branch
    k_zero<<<4096, 256>>>((float4*)oL);
    k_edge<<<128, 256, EDGE_SMEM_BYTES>>>(lig, eb, es, ed, We, be, oL);

    // contract branch (the long pole)
    k_contract<<<dim3(128, 16), 512, SM_CONTRACT_BYTES>>>(ll, mask, Wc, bc, gcc, bec, Wca, bca, oC);
}

// round 4
// speedup vs baseline: 1.7740x; 1.7740x over previous
#include <cuda_runtime.h>
#include <cstdint>
#include <cstddef>

// ---------------------------------------------------------------------------
// Problem dims
// ---------------------------------------------------------------------------
constexpr int Bd = 16, Ld = 128, Rd = 512, Fd = 256, Hd = 8, FHd = 32, FEd = 64, Ed = 16384;
constexpr int HFd = 256;

__device__ __forceinline__ float lrelu(float x) { return x > 0.f ? x : 0.01f * x; }
__device__ __forceinline__ float tf32_rna(float x) {
    float r; asm("cvt.rna.tf32.f32 %0, %1;" : "=f"(r) : "f"(x)); return r;
}

// Scratch for expand branch (device globals: allocation-free)
__device__ float g_xf[Bd * Ld * HFd];   // 2 MB
__device__ float g_yf[Bd * Rd * HFd];   // 8 MB

// m16n8k8 tf32 mma (legacy tensor-core PTX; assembles for sm_103 target)
__device__ __forceinline__ void mma_tf32(float* c, const uint32_t* a, const uint32_t* b)
{
    asm volatile(
        "mma.sync.aligned.m16n8k8.row.col.f32.tf32.tf32.f32 "
        "{%0,%1,%2,%3}, {%4,%5,%6,%7}, {%8,%9}, {%0,%1,%2,%3};"
        : "+f"(c[0]), "+f"(c[1]), "+f"(c[2]), "+f"(c[3])
        : "r"(a[0]), "r"(a[1]), "r"(a[2]), "r"(a[3]), "r"(b[0]), "r"(b[1]));
}

// ---------------------------------------------------------------------------
// Contract kernel SMEM layout (float offsets)
// ---------------------------------------------------------------------------
constexpr int SA_LD = 268;                       // conflict-free for frag loads
constexpr int SB_LD = 265;                       // conflict-free staging writes
constexpr int SA_F   = 0;                        // 128 x 268
constexpr int SB0_F  = SA_F + 128 * SA_LD;       // 34304
constexpr int SB1_F  = SB0_F + 32 * SB_LD;       // 42784
constexpr int WCA_F  = SB1_F + 32 * SB_LD;       // 51264 (8 x 256)
constexpr int LG_F   = WCA_F + 2048;             // 53312 (128 x 8)
constexpr int G_F    = LG_F + 1024;              // 54336
constexpr int BE_F   = G_F + 256;                // 54592
constexpr int BC_F   = BE_F + 256;               // 54848
constexpr int BCA_F  = BC_F + 256;               // 55104
constexpr int SUM_F  = BCA_F + 8;                // 55112
constexpr int SM_CONTRACT_FLOATS = SUM_F + 8;    // 55120
constexpr int SM_CONTRACT_BYTES  = SM_CONTRACT_FLOATS * 4;   // 220,480 B

__global__ void __launch_bounds__(512, 1)
k_contract(const float* __restrict__ ll, const unsigned* __restrict__ mask,
           const float* __restrict__ Wc, const float* __restrict__ bc,
           const float* __restrict__ gc, const float* __restrict__ bec,
           const float* __restrict__ Wca, const float* __restrict__ bca,
           float* __restrict__ out)
{
    extern __shared__ float sm[];
    const int t = threadIdx.x;
    const int x = blockIdx.x, b = blockIdx.y;
    const int w = t >> 5, lane = t & 31;
    const int warp_m = w >> 2, warp_n = w & 3;   // 4x4 warp grid
    const int qrow = lane >> 2, qcol = lane & 3;

    // constants
    if (t < 256) { sm[G_F + t] = gc[t]; sm[BE_F + t] = bec[t]; sm[BC_F + t] = bc[t]; }
    if (t < 8)   { sm[BCA_F + t] = bca[t]; }
#pragma unroll
    for (int s = 0; s < 4; s++) { int m = t + s * 512; sm[WCA_F + m] = Wca[m]; }

    // stage A (lrelu + tf32 round): 128 x 256, stride SA_LD
    const float* Arow = ll + (size_t)(b * Ld + x) * Ld * Fd;
#pragma unroll
    for (int s = 0; s < 16; s++) {
        int m = t + s * 512;                     // float4 id, 8192 total
        int y = m >> 6, col = (m & 63) << 2;
        float4 v = *(const float4*)(Arow + y * 256 + col);
        float4 o;
        o.x = tf32_rna(lrelu(v.x)); o.y = tf32_rna(lrelu(v.y));
        o.z = tf32_rna(lrelu(v.z)); o.w = tf32_rna(lrelu(v.w));
        *(float4*)&sm[SA_F + y * SA_LD + col] = o;
    }
    __syncthreads();

    // attention logits from staged A (vectorized); write to LG
    {
        int y = t & 127, h0 = t >> 7;            // h0 in 0..3; also h0+4
        float lg0 = 0.f, lg1 = 0.f;
#pragma unroll 8
        for (int k4 = 0; k4 < 64; k4++) {
            float4 av = *(const float4*)&sm[SA_F + y * SA_LD + k4 * 4];
            float4 w0 = *(const float4*)&sm[WCA_F + h0 * 256 + k4 * 4];
            float4 w1 = *(const float4*)&sm[WCA_F + (h0 + 4) * 256 + k4 * 4];
            lg0 += av.x * w0.x + av.y * w0.y + av.z * w0.z + av.w * w0.w;
            lg1 += av.x * w1.x + av.y * w1.y + av.z * w1.z + av.w * w1.w;
        }
        sm[LG_F + y * 8 + h0]     = lg0 + sm[BCA_F + h0];
        sm[LG_F + y * 8 + h0 + 4] = lg1 + sm[BCA_F + h0 + 4];
    }

    // ---- pipelined B staging + mma main loop ----
    // B chunk c covers k = c*32 .. c*32+31; sB[kk][n] = tf32(Wc[n][c*32+kk])
    // thread's 4 float4 per chunk: m = t + j*512 -> n = m>>3, kq = m&7
    float4 vb[4];
    {
        const int k0 = 0;
#pragma unroll
        for (int j = 0; j < 4; j++) {
            int m = t + j * 512;
            int n = m >> 3, kq = m & 7;
            vb[j] = *(const float4*)(Wc + (size_t)n * 256 + k0 + kq * 4);
        }
#pragma unroll
        for (int j = 0; j < 4; j++) {
            int m = t + j * 512;
            int n = m >> 3, kq = m & 7;
            float* dst = &sm[SB0_F + (kq * 4) * SB_LD + n];
            dst[0]          = tf32_rna(vb[j].x);
            dst[SB_LD]      = tf32_rna(vb[j].y);
            dst[2 * SB_LD]  = tf32_rna(vb[j].z);
            dst[3 * SB_LD]  = tf32_rna(vb[j].w);
        }
    }

    float acc[2][8][4];
#pragma unroll
    for (int mt = 0; mt < 2; mt++)
#pragma unroll
        for (int nt = 0; nt < 8; nt++)
#pragma unroll
            for (int q = 0; q < 4; q++) acc[mt][nt][q] = 0.f;

    const int arow0 = warp_m * 32 + qrow;
    const int bcol0 = warp_n * 64 + qrow;

    for (int c = 0; c < 8; c++) {
        __syncthreads();
        // prefetch next chunk's global data (hidden under mma)
        if (c < 7) {
            const int k0 = (c + 1) * 32;
#pragma unroll
            for (int j = 0; j < 4; j++) {
                int m = t + j * 512;
                int n = m >> 3, kq = m & 7;
                vb[j] = *(const float4*)(Wc + (size_t)n * 256 + k0 + kq * 4);
            }
        }
        const float* Bc = &sm[(c & 1) ? SB1_F : SB0_F];
#pragma unroll
        for (int kk = 0; kk < 4; kk++) {
            const int kb = kk * 8;
            const int kcol = c * 32 + kb + qcol;
            uint32_t a[2][4];
#pragma unroll
            for (int mt = 0; mt < 2; mt++) {
                int r = arow0 + mt * 16;
                a[mt][0] = __float_as_uint(sm[SA_F + r * SA_LD + kcol]);
                a[mt][1] = __float_as_uint(sm[SA_F + (r + 8) * SA_LD + kcol]);
                a[mt][2] = __float_as_uint(sm[SA_F + r * SA_LD + kcol + 4]);
                a[mt][3] = __float_as_uint(sm[SA_F + (r + 8) * SA_LD + kcol + 4]);
            }
            uint32_t bfr[8][2];
#pragma unroll
            for (int nt = 0; nt < 8; nt++) {
                int n = bcol0 + nt * 8;
                bfr[nt][0] = __float_as_uint(Bc[(kb + qcol) * SB_LD + n]);
                bfr[nt][1] = __float_as_uint(Bc[(kb + 4 + qcol) * SB_LD + n]);
            }
#pragma unroll
            for (int mt = 0; mt < 2; mt++)
#pragma unroll
                for (int nt = 0; nt < 8; nt++)
                    mma_tf32(acc[mt][nt], a[mt], bfr[nt]);
        }
        // store prefetched chunk into the other buffer
        if (c < 7) {
            float* Bn = &sm[((c + 1) & 1) ? SB1_F : SB0_F];
#pragma unroll
            for (int j = 0; j < 4; j++) {
                int m = t + j * 512;
                int n = m >> 3, kq = m & 7;
                float* dst = &Bn[(kq * 4) * SB_LD + n];
                dst[0]         = tf32_rna(vb[j].x);
                dst[SB_LD]     = tf32_rna(vb[j].y);
                dst[2 * SB_LD] = tf32_rna(vb[j].z);
                dst[3 * SB_LD] = tf32_rna(vb[j].w);
            }
        }
    }
    __syncthreads();   // all frag reads of sA done; safe to overwrite with OF

    // write OF = acc + bc into sA region (stride SA_LD)
    {
        const int col0 = warp_n * 64 + 2 * qcol;
#pragma unroll
        for (int mt = 0; mt < 2; mt++) {
            int r = arow0 + mt * 16;
#pragma unroll
            for (int nt = 0; nt < 8; nt++) {
                int cc = col0 + nt * 8;
                sm[SA_F + r * SA_LD + cc]           = acc[mt][nt][0] + sm[BC_F + cc];
                sm[SA_F + r * SA_LD + cc + 1]       = acc[mt][nt][1] + sm[BC_F + cc + 1];
                sm[SA_F + (r + 8) * SA_LD + cc]     = acc[mt][nt][2] + sm[BC_F + cc];
                sm[SA_F + (r + 8) * SA_LD + cc + 1] = acc[mt][nt][3] + sm[BC_F + cc + 1];
            }
        }
    }
    __syncthreads();

    // layernorm: 16 warps x 8 rows
#pragma unroll
    for (int rr = 0; rr < 8; rr++) {
        int y = w * 8 + rr;
        float vals[8], s = 0.f;
#pragma unroll
        for (int q = 0; q < 8; q++) { vals[q] = sm[SA_F + y * SA_LD + lane + q * 32]; s += vals[q]; }
#pragma unroll
        for (int o = 16; o; o >>= 1) s += __shfl_xor_sync(0xffffffffu, s, o);
        float mu = s * (1.f / 256.f);
        float vs = 0.f;
#pragma unroll
        for (int q = 0; q < 8; q++) { float d = vals[q] - mu; vs += d * d; }
#pragma unroll
        for (int o = 16; o; o >>= 1) vs += __shfl_xor_sync(0xffffffffu, vs, o);
        float rs = rsqrtf(vs * (1.f / 256.f) + 1e-5f);
#pragma unroll
        for (int q = 0; q < 8; q++) {
            int c = lane + q * 32;
            sm[SA_F + y * SA_LD + c] = sm[G_F + c] * ((vals[q] - mu) * rs) + sm[BE_F + c];
        }
    }

    // masked softmax over y per head (warps 0..7); ref semantics:
    // max over ALL y, masked entries zeroed in sum, denom = sum + 1e-10
    if (w < 8) {
        int h = w;
        float lv[4];
#pragma unroll
        for (int q = 0; q < 4; q++) lv[q] = sm[LG_F + (lane + q * 32) * 8 + h];
        float mx = fmaxf(fmaxf(lv[0], lv[1]), fmaxf(lv[2], lv[3]));
#pragma unroll
        for (int o = 16; o; o >>= 1) mx = fmaxf(mx, __shfl_xor_sync(0xffffffffu, mx, o));
        const unsigned* mrow = mask + (size_t)(b * Ld + x) * Ld;
        float e[4], sum = 0.f;
#pragma unroll
        for (int q = 0; q < 4; q++) {
            int y = lane + q * 32;
            float ee = (mrow[y] != 0u) ? expf(lv[q] - mx) : 0.f;
            e[q] = ee; sum += ee;
        }
#pragma unroll
        for (int o = 16; o; o >>= 1) sum += __shfl_xor_sync(0xffffffffu, sum, o);
#pragma unroll
        for (int q = 0; q < 4; q++) sm[LG_F + (lane + q * 32) * 8 + h] = e[q];
        if (lane == 0) sm[SUM_F + h] = sum + 1e-10f;
    }
    __syncthreads();

    // contraction over y: 256 outputs
    if (t < 256) {
        int n = t, h = n >> 5;
        float a = 0.f;
#pragma unroll 8
        for (int y = 0; y < 128; y++) a += sm[LG_F + y * 8 + h] * sm[SA_F + y * SA_LD + n];
        out[(size_t)(b * Ld + x) * HFd + n] = a / sm[SUM_F + h];
    }
}

// ---------------------------------------------------------------------------
// NormAndLinear for lig/rec: block = 16 rows, thread = output column.
// ---------------------------------------------------------------------------
__global__ void __launch_bounds__(256)
k_normlin(const float* __restrict__ X, const float* __restrict__ W,
          const float* __restrict__ bias, const float* __restrict__ g,
          const float* __restrict__ be, float* __restrict__ out)
{
    __shared__ float sX[16 * 260];
    __shared__ float sH[16 * 260];
    const int t = threadIdx.x;
    const int row0 = blockIdx.x * 16;

#pragma unroll
    for (int s = 0; s < 4; s++) {
        int m = t + s * 256;
        int r = m >> 6, c = (m & 63) * 4;
        float4 v = *(const float4*)(X + (size_t)(row0 + r) * Fd + c);
        sX[r * 260 + c + 0] = lrelu(v.x);
        sX[r * 260 + c + 1] = lrelu(v.y);
        sX[r * 260 + c + 2] = lrelu(v.z);
        sX[r * 260 + c + 3] = lrelu(v.w);
    }
    __syncthreads();

    float acc[16];
#pragma unroll
    for (int r = 0; r < 16; r++) acc[r] = 0.f;
    const int n = t;
    for (int k0 = 0; k0 < 256; k0 += 8) {
        float wv[8];
        *(float4*)&wv[0] = *(const float4*)(W + (size_t)n * Fd + k0);
        *(float4*)&wv[4] = *(const float4*)(W + (size_t)n * Fd + k0 + 4);
#pragma unroll
        for (int r = 0; r < 16; r++) {
            float a[8];
            *(float4*)&a[0] = *(const float4*)&sX[r * 260 + k0];
            *(float4*)&a[4] = *(const float4*)&sX[r * 260 + k0 + 4];
#pragma unroll
            for (int kk = 0; kk < 8; kk++) acc[r] += a[kk] * wv[kk];
        }
    }
    float bv = bias[n];
#pragma unroll
    for (int r = 0; r < 16; r++) sH[r * 260 + n] = acc[r] + bv;
    __syncthreads();

    const int warp = t >> 5, lane = t & 31;
#pragma unroll
    for (int rr = 0; rr < 2; rr++) {
        int r = warp * 2 + rr;
        float vals[8], s = 0.f;
#pragma unroll
        for (int q = 0; q < 8; q++) { vals[q] = sH[r * 260 + lane + q * 32]; s += vals[q]; }
#pragma unroll
        for (int o = 16; o; o >>= 1) s += __shfl_xor_sync(0xffffffffu, s, o);
        float mu = s * (1.f / 256.f);
        float vs = 0.f;
#pragma unroll
        for (int q = 0; q < 8; q++) { float d = vals[q] - mu; vs += d * d; }
#pragma unroll
        for (int o = 16; o; o >>= 1) vs += __shfl_xor_sync(0xffffffffu, vs, o);
        float rstd = rsqrtf(vs * (1.f / 256.f) + 1e-5f);
#pragma unroll
        for (int q = 0; q < 8; q++) {
            int c = lane + q * 32;
            out[(size_t)(row0 + r) * 256 + c] = g[c] * ((vals[q] - mu) * rstd) + be[c];
        }
    }
}

// ---------------------------------------------------------------------------
// Expand: out[b,x,y,h] = sum_f xf[b,x,h,f]*yf[b,y,h,f]
// ---------------------------------------------------------------------------
__global__ void __launch_bounds__(256)
k_expand(float* __restrict__ out)
{
    __shared__ float sX[16 * 8 * 36];
    __shared__ float sY[32 * 8 * 36];
    const int t = threadIdx.x;
    const int x0 = blockIdx.x * 16, y0 = blockIdx.y * 32, b = blockIdx.z;

#pragma unroll
    for (int s = 0; s < 4; s++) {
        int m = t + s * 256;
        int xi = m >> 6, c = (m & 63) * 4;
        int h = c >> 5, f = c & 31;
        float4 v = *(const float4*)(g_xf + (size_t)(b * Ld + x0 + xi) * HFd + c);
        float* d = &sX[(xi * 8 + h) * 36 + f];
        d[0] = v.x; d[1] = v.y; d[2] = v.z; d[3] = v.w;
    }
#pragma unroll
    for (int s = 0; s < 8; s++) {
        int m = t + s * 256;
        int yi = m >> 6, c = (m & 63) * 4;
        int h = c >> 5, f = c & 31;
        float4 v = *(const float4*)(g_yf + (size_t)(b * Rd + y0 + yi) * HFd + c);
        float* d = &sY[(yi * 8 + h) * 36 + f];
        d[0] = v.x; d[1] = v.y; d[2] = v.z; d[3] = v.w;
    }
    __syncthreads();

    const int h = t & 7, yy = t >> 3;
    float acc[16];
#pragma unroll
    for (int xi = 0; xi < 16; xi++) acc[xi] = 0.f;
#pragma unroll
    for (int f4 = 0; f4 < 32; f4 += 4) {
        float4 yv = *(const float4*)&sY[(yy * 8 + h) * 36 + f4];
#pragma unroll
        for (int xi = 0; xi < 16; xi++) {
            float4 xv = *(const float4*)&sX[(xi * 8 + h) * 36 + f4];
            acc[xi] += xv.x * yv.x + xv.y * yv.y + xv.z * yv.z + xv.w * yv.w;
        }
    }
#pragma unroll
    for (int xi = 0; xi < 16; xi++)
        out[((size_t)(b * Ld + x0 + xi) * Rd + y0 + yy) * Hd + h] = acc[xi];
}

// ---------------------------------------------------------------------------
// Zero llf region
// ---------------------------------------------------------------------------
__global__ void __launch_bounds__(256)
k_zero(float4* __restrict__ p)
{
    size_t base = ((size_t)blockIdx.x * 256 + threadIdx.x) * 4;
#pragma unroll
    for (int i = 0; i < 4; i++) p[base + i] = make_float4(0.f, 0.f, 0.f, 0.f);
}

// ---------------------------------------------------------------------------
// Edge: gather -> linear(2F->FE) -> lrelu -> atomic scatter into llf.
// ---------------------------------------------------------------------------
constexpr int WET_LD = 68;
constexpr int EDGE_SMEM_FLOATS = 512 * WET_LD + 32 * 512;
constexpr int EDGE_SMEM_BYTES  = EDGE_SMEM_FLOATS * 4;

__global__ void __launch_bounds__(256, 1)
k_edge(const float* __restrict__ lig, const int* __restrict__ eb,
       const int* __restrict__ es, const int* __restrict__ ed,
       const float* __restrict__ We, const float* __restrict__ be,
       float* __restrict__ llf)
{
    extern __shared__ float sm[];
    float* sWeT = sm;
    float* sEF  = sm + 512 * WET_LD;
    const int t = threadIdx.x;

#pragma unroll 8
    for (int s = 0; s < 128; s++) {
        int m = t + s * 256;
        int k = m & 511, o = m >> 9;
        sWeT[k * WET_LD + o] = We[o * 512 + k];
    }

    const int to = t & 7;
    const int te = t >> 3;
    float bev[8];
#pragma unroll
    for (int c = 0; c < 8; c++) bev[c] = be[to * 8 + c];

    for (int iter = 0; iter < 4; iter++) {
        __syncthreads();
#pragma unroll
        for (int s = 0; s < 16; s++) {
            int m = t + s * 256;
            int eg = m >> 7, kq = m & 127;
            int k = kq * 4;
            int e = blockIdx.x * 128 + iter * 32 + eg;
            int bb = eb[e];
            int row = (k < 256) ? es[e] : ed[e];
            int col = (k < 256) ? k : (k - 256);
            float4 v = *(const float4*)(lig + (size_t)(bb * Ld + row) * Fd + col);
            float* d = &sEF[eg * 512 + k];
            d[0] = v.x; d[1] = v.y; d[2] = v.z; d[3] = v.w;
        }
        __syncthreads();

        float acc[8];
#pragma unroll
        for (int c = 0; c < 8; c++) acc[c] = 0.f;
#pragma unroll 4
        for (int k = 0; k < 512; k++) {
            float a = sEF[te * 512 + k];
            float4 w0 = *(const float4*)&sWeT[k * WET_LD + to * 8];
            float4 w1 = *(const float4*)&sWeT[k * WET_LD + to * 8 + 4];
            acc[0] += a * w0.x; acc[1] += a * w0.y; acc[2] += a * w0.z; acc[3] += a * w0.w;
            acc[4] += a * w1.x; acc[5] += a * w1.y; acc[6] += a * w1.z; acc[7] += a * w1.w;
        }
        int e = blockIdx.x * 128 + iter * 32 + te;
        int bb = eb[e], ss = es[e], dd = ed[e];
        float* dst = llf + ((size_t)(bb * Ld + ss) * Ld + dd) * FEd + to * 8;
#pragma unroll
        for (int c = 0; c < 8; c++) atomicAdd(dst + c, lrelu(acc[c] + bev[c]));
    }
}

// ---------------------------------------------------------------------------
// Launch
// ---------------------------------------------------------------------------
extern "C" void kernel_launch(void* const* d_in, const int* in_sizes, int n_in,
                              void* d_out, int out_size)
{
    const float*    ll   = (const float*)d_in[0];
    const float*    lig  = (const float*)d_in[1];
    const float*    rec  = (const float*)d_in[2];
    const unsigned* mask = (const unsigned*)d_in[3];
    const int*      eb   = (const int*)d_in[4];
    const int*      es   = (const int*)d_in[5];
    const int*      ed   = (const int*)d_in[6];
    const float*    Wc   = (const float*)d_in[7];
    const float*    bc   = (const float*)d_in[8];
    const float*    gcc  = (const float*)d_in[9];
    const float*    bec  = (const float*)d_in[10];
    const float*    Wca  = (const float*)d_in[11];
    const float*    bca  = (const float*)d_in[12];
    const float*    Wex  = (const float*)d_in[13];
    const float*    bex  = (const float*)d_in[14];
    const float*    gex  = (const float*)d_in[15];
    const float*    beex = (const float*)d_in[16];
    const float*    Wey  = (const float*)d_in[17];
    const float*    bey  = (const float*)d_in[18];
    const float*    gey  = (const float*)d_in[19];
    const float*    beey = (const float*)d_in[20];
    const float*    We   = (const float*)d_in[21];
    const float*    be   = (const float*)d_in[22];

    float* out = (float*)d_out;
    float* oC = out;
    float* oE = out + (size_t)Bd * Ld * HFd;
    float* oL = oE + (size_t)Bd * Ld * Rd * Hd;

    cudaFuncSetAttribute(k_contract, cudaFuncAttributeMaxDynamicSharedMemorySize, SM_CONTRACT_BYTES);
    cudaFuncSetAttribute(k_edge, cudaFuncAttributeMaxDynamicSharedMemorySize, EDGE_SMEM_BYTES);

    void* pxf = nullptr; void* pyf = nullptr;
    cudaGetSymbolAddress(&pxf, g_xf);
    cudaGetSymbolAddress(&pyf, g_yf);

    // contract branch (tf32 mma.sync tensor cores)
    k_contract<<<dim3(128, 16), 512, SM_CONTRACT_BYTES>>>(ll, mask, Wc, bc, gcc, bec, Wca, bca, oC);

    // expand branch
    k_normlin<<<128, 256>>>(lig, Wex, bex, gex, beex, (float*)pxf);
    k_normlin<<<512, 256>>>(rec, Wey, bey, gey, beey, (float*)pyf);
    k_expand<<<dim3(8, 16, 16), 256>>>(oE);

    // edge branch
    k_zero<<<4096, 256>>>((float4*)oL);
    k_edge<<<128, 256, EDGE_SMEM_BYTES>>>(lig, eb, es, ed, We, be, oL);
}

// round 5
// speedup vs baseline: 1.8993x; 1.0706x over previous
#include <cuda_runtime.h>
#include <cstdint>
#include <cstddef>

// ---------------------------------------------------------------------------
// Problem dims
// ---------------------------------------------------------------------------
constexpr int Bd = 16, Ld = 128, Rd = 512, Fd = 256, Hd = 8, FHd = 32, FEd = 64, Ed = 16384;
constexpr int HFd = 256;

__device__ __forceinline__ float lrelu(float x) { return x > 0.f ? x : 0.01f * x; }
__device__ __forceinline__ float tf32_rna(float x) {
    float r; asm("cvt.rna.tf32.f32 %0, %1;" : "=f"(r) : "f"(x)); return r;
}

// Scratch for expand branch (device globals: allocation-free)
__device__ float g_xf[Bd * Ld * HFd];   // 2 MB
__device__ float g_yf[Bd * Rd * HFd];   // 8 MB

// m16n8k8 tf32 mma (legacy tensor-core PTX; assembles for sm_103 target)
__device__ __forceinline__ void mma_tf32(float* c, const uint32_t* a, const uint32_t* b)
{
    asm volatile(
        "mma.sync.aligned.m16n8k8.row.col.f32.tf32.tf32.f32 "
        "{%0,%1,%2,%3}, {%4,%5,%6,%7}, {%8,%9}, {%0,%1,%2,%3};"
        : "+f"(c[0]), "+f"(c[1]), "+f"(c[2]), "+f"(c[3])
        : "r"(a[0]), "r"(a[1]), "r"(a[2]), "r"(a[3]), "r"(b[0]), "r"(b[1]));
}

// ---------------------------------------------------------------------------
// Contract kernel SMEM layout (float offsets)
// ---------------------------------------------------------------------------
constexpr int SA_LD = 268;                       // conflict-free for frag loads
constexpr int SB_LD = 265;                       // conflict-free staging writes
constexpr int SA_F   = 0;                        // 128 x 268
constexpr int SB0_F  = SA_F + 128 * SA_LD;       // 34304
constexpr int SB1_F  = SB0_F + 32 * SB_LD;       // 42784
constexpr int WCA_F  = SB1_F + 32 * SB_LD;       // 51264 (8 x 256)
constexpr int LG_F   = WCA_F + 2048;             // 53312 (128 x 8)
constexpr int G_F    = LG_F + 1024;              // 54336
constexpr int BE_F   = G_F + 256;                // 54592
constexpr int BC_F   = BE_F + 256;               // 54848
constexpr int BCA_F  = BC_F + 256;               // 55104
constexpr int SUM_F  = BCA_F + 8;                // 55112
constexpr int SM_CONTRACT_FLOATS = SUM_F + 8;    // 55120
constexpr int SM_CONTRACT_BYTES  = SM_CONTRACT_FLOATS * 4;   // 220,480 B

__global__ void __launch_bounds__(256, 1)
k_contract(const float* __restrict__ ll, const unsigned* __restrict__ mask,
           const float* __restrict__ Wc, const float* __restrict__ bc,
           const float* __restrict__ gc, const float* __restrict__ bec,
           const float* __restrict__ Wca, const float* __restrict__ bca,
           float* __restrict__ out)
{
    extern __shared__ float sm[];
    const int t = threadIdx.x;
    const int x = blockIdx.x, b = blockIdx.y;
    const int w = t >> 5, lane = t & 31;
    const int warp_m = w >> 2, warp_n = w & 3;   // 2x4 warp grid, warp tile 64x64
    const int qrow = lane >> 2, qcol = lane & 3;

    // constants
    if (t < 8) sm[BCA_F + t] = bca[t];
    { int c = t; sm[G_F + c] = gc[c]; sm[BE_F + c] = bec[c]; sm[BC_F + c] = bc[c]; }
#pragma unroll
    for (int s = 0; s < 8; s++) { int m = t + s * 256; sm[WCA_F + m] = Wca[m]; }

    // stage A (lrelu + tf32 round): 128 x 256, stride SA_LD
    const float* Arow = ll + (size_t)(b * Ld + x) * Ld * Fd;
#pragma unroll
    for (int s = 0; s < 32; s++) {
        int m = t + s * 256;                     // float4 id, 8192 total
        int y = m >> 6, col = (m & 63) << 2;
        float4 v = *(const float4*)(Arow + y * 256 + col);
        float4 o;
        o.x = tf32_rna(lrelu(v.x)); o.y = tf32_rna(lrelu(v.y));
        o.z = tf32_rna(lrelu(v.z)); o.w = tf32_rna(lrelu(v.w));
        *(float4*)&sm[SA_F + y * SA_LD + col] = o;
    }
    __syncthreads();

    // attention logits from staged A: thread handles (y, 4 heads)
    {
        int y = t & 127, half = t >> 7;
        float lg[4] = {0.f, 0.f, 0.f, 0.f};
#pragma unroll 8
        for (int k4 = 0; k4 < 64; k4++) {
            float4 av = *(const float4*)&sm[SA_F + y * SA_LD + k4 * 4];
#pragma unroll
            for (int i = 0; i < 4; i++) {
                float4 wv = *(const float4*)&sm[WCA_F + (half * 4 + i) * 256 + k4 * 4];
                lg[i] += av.x * wv.x + av.y * wv.y + av.z * wv.z + av.w * wv.w;
            }
        }
#pragma unroll
        for (int i = 0; i < 4; i++)
            sm[LG_F + y * 8 + half * 4 + i] = lg[i] + sm[BCA_F + half * 4 + i];
    }

    // ---- pipelined B staging + mma main loop ----
    // B chunk c covers k = c*32 .. c*32+31; sB[kk][n] = tf32(Wc[n][c*32+kk])
    float4 vb[8];
    {
#pragma unroll
        for (int j = 0; j < 8; j++) {
            int m = t + j * 256;
            int n = m >> 3, kq = m & 7;
            vb[j] = *(const float4*)(Wc + (size_t)n * 256 + kq * 4);
        }
#pragma unroll
        for (int j = 0; j < 8; j++) {
            int m = t + j * 256;
            int n = m >> 3, kq = m & 7;
            float* dst = &sm[SB0_F + (kq * 4) * SB_LD + n];
            dst[0]          = tf32_rna(vb[j].x);
            dst[SB_LD]      = tf32_rna(vb[j].y);
            dst[2 * SB_LD]  = tf32_rna(vb[j].z);
            dst[3 * SB_LD]  = tf32_rna(vb[j].w);
        }
    }

    float acc[4][8][4];
#pragma unroll
    for (int mt = 0; mt < 4; mt++)
#pragma unroll
        for (int nt = 0; nt < 8; nt++)
#pragma unroll
            for (int q = 0; q < 4; q++) acc[mt][nt][q] = 0.f;

    const int arow0 = warp_m * 64 + qrow;
    const int bcol0 = warp_n * 64 + qrow;

    for (int c = 0; c < 8; c++) {
        __syncthreads();
        // prefetch next chunk's global data (hidden under mma)
        if (c < 7) {
            const int k0 = (c + 1) * 32;
#pragma unroll
            for (int j = 0; j < 8; j++) {
                int m = t + j * 256;
                int n = m >> 3, kq = m & 7;
                vb[j] = *(const float4*)(Wc + (size_t)n * 256 + k0 + kq * 4);
            }
        }
        const float* Bc = &sm[(c & 1) ? SB1_F : SB0_F];
#pragma unroll
        for (int kk = 0; kk < 4; kk++) {
            const int kb = kk * 8;
            const int kcol = c * 32 + kb + qcol;
            uint32_t a[4][4];
#pragma unroll
            for (int mt = 0; mt < 4; mt++) {
                int r = arow0 + mt * 16;
                a[mt][0] = __float_as_uint(sm[SA_F + r * SA_LD + kcol]);
                a[mt][1] = __float_as_uint(sm[SA_F + (r + 8) * SA_LD + kcol]);
                a[mt][2] = __float_as_uint(sm[SA_F + r * SA_LD + kcol + 4]);
                a[mt][3] = __float_as_uint(sm[SA_F + (r + 8) * SA_LD + kcol + 4]);
            }
            uint32_t bfr[8][2];
#pragma unroll
            for (int nt = 0; nt < 8; nt++) {
                int n = bcol0 + nt * 8;
                bfr[nt][0] = __float_as_uint(Bc[(kb + qcol) * SB_LD + n]);
                bfr[nt][1] = __float_as_uint(Bc[(kb + 4 + qcol) * SB_LD + n]);
            }
#pragma unroll
            for (int mt = 0; mt < 4; mt++)
#pragma unroll
                for (int nt = 0; nt < 8; nt++)
                    mma_tf32(acc[mt][nt], a[mt], bfr[nt]);
        }
        // store prefetched chunk into the other buffer
        if (c < 7) {
            float* Bn = &sm[((c + 1) & 1) ? SB1_F : SB0_F];
#pragma unroll
            for (int j = 0; j < 8; j++) {
                int m = t + j * 256;
                int n = m >> 3, kq = m & 7;
                float* dst = &Bn[(kq * 4) * SB_LD + n];
                dst[0]         = tf32_rna(vb[j].x);
                dst[SB_LD]     = tf32_rna(vb[j].y);
                dst[2 * SB_LD] = tf32_rna(vb[j].z);
                dst[3 * SB_LD] = tf32_rna(vb[j].w);
            }
        }
    }
    __syncthreads();   // all frag reads of sA done; safe to overwrite with OF

    // write OF = acc + bc into sA region (stride SA_LD)
    {
        const int col0 = warp_n * 64 + 2 * qcol;
#pragma unroll
        for (int mt = 0; mt < 4; mt++) {
            int r = arow0 + mt * 16;
#pragma unroll
            for (int nt = 0; nt < 8; nt++) {
                int cc = col0 + nt * 8;
                sm[SA_F + r * SA_LD + cc]           = acc[mt][nt][0] + sm[BC_F + cc];
                sm[SA_F + r * SA_LD + cc + 1]       = acc[mt][nt][1] + sm[BC_F + cc + 1];
                sm[SA_F + (r + 8) * SA_LD + cc]     = acc[mt][nt][2] + sm[BC_F + cc];
                sm[SA_F + (r + 8) * SA_LD + cc + 1] = acc[mt][nt][3] + sm[BC_F + cc + 1];
            }
        }
    }
    __syncthreads();

    // layernorm: 8 warps x 16 rows
#pragma unroll
    for (int rr = 0; rr < 16; rr++) {
        int y = w * 16 + rr;
        float vals[8], s = 0.f;
#pragma unroll
        for (int q = 0; q < 8; q++) { vals[q] = sm[SA_F + y * SA_LD + lane + q * 32]; s += vals[q]; }
#pragma unroll
        for (int o = 16; o; o >>= 1) s += __shfl_xor_sync(0xffffffffu, s, o);
        float mu = s * (1.f / 256.f);
        float vs = 0.f;
#pragma unroll
        for (int q = 0; q < 8; q++) { float d = vals[q] - mu; vs += d * d; }
#pragma unroll
        for (int o = 16; o; o >>= 1) vs += __shfl_xor_sync(0xffffffffu, vs, o);
        float rs = rsqrtf(vs * (1.f / 256.f) + 1e-5f);
#pragma unroll
        for (int q = 0; q < 8; q++) {
            int c = lane + q * 32;
            sm[SA_F + y * SA_LD + c] = sm[G_F + c] * ((vals[q] - mu) * rs) + sm[BE_F + c];
        }
    }

    // masked softmax over y per head (warp w = head w); ref semantics:
    // max over ALL y, masked entries zeroed in sum, denom = sum + 1e-10
    {
        int h = w;
        float lv[4];
#pragma unroll
        for (int q = 0; q < 4; q++) lv[q] = sm[LG_F + (lane + q * 32) * 8 + h];
        float mx = fmaxf(fmaxf(lv[0], lv[1]), fmaxf(lv[2], lv[3]));
#pragma unroll
        for (int o = 16; o; o >>= 1) mx = fmaxf(mx, __shfl_xor_sync(0xffffffffu, mx, o));
        const unsigned* mrow = mask + (size_t)(b * Ld + x) * Ld;
        float e[4], sum = 0.f;
#pragma unroll
        for (int q = 0; q < 4; q++) {
            int y = lane + q * 32;
            float ee = (mrow[y] != 0u) ? expf(lv[q] - mx) : 0.f;
            e[q] = ee; sum += ee;
        }
#pragma unroll
        for (int o = 16; o; o >>= 1) sum += __shfl_xor_sync(0xffffffffu, sum, o);
#pragma unroll
        for (int q = 0; q < 4; q++) sm[LG_F + (lane + q * 32) * 8 + h] = e[q];
        if (lane == 0) sm[SUM_F + h] = sum + 1e-10f;
    }
    __syncthreads();

    // contraction over y: 256 outputs
    {
        int n = t, h = n >> 5;
        float a = 0.f;
#pragma unroll 8
        for (int y = 0; y < 128; y++) a += sm[LG_F + y * 8 + h] * sm[SA_F + y * SA_LD + n];
        out[(size_t)(b * Ld + x) * HFd + n] = a / sm[SUM_F + h];
    }
}

// ---------------------------------------------------------------------------
// NormAndLinear for lig/rec: block = 16 rows, thread = output column.
// ---------------------------------------------------------------------------
__global__ void __launch_bounds__(256)
k_normlin(const float* __restrict__ X, const float* __restrict__ W,
          const float* __restrict__ bias, const float* __restrict__ g,
          const float* __restrict__ be, float* __restrict__ out)
{
    __shared__ float sX[16 * 260];
    __shared__ float sH[16 * 260];
    const int t = threadIdx.x;
    const int row0 = blockIdx.x * 16;

#pragma unroll
    for (int s = 0; s < 4; s++) {
        int m = t + s * 256;
        int r = m >> 6, c = (m & 63) * 4;
        float4 v = *(const float4*)(X + (size_t)(row0 + r) * Fd + c);
        sX[r * 260 + c + 0] = lrelu(v.x);
        sX[r * 260 + c + 1] = lrelu(v.y);
        sX[r * 260 + c + 2] = lrelu(v.z);
        sX[r * 260 + c + 3] = lrelu(v.w);
    }
    __syncthreads();

    float acc[16];
#pragma unroll
    for (int r = 0; r < 16; r++) acc[r] = 0.f;
    const int n = t;
    for (int k0 = 0; k0 < 256; k0 += 8) {
        float wv[8];
        *(float4*)&wv[0] = *(const float4*)(W + (size_t)n * Fd + k0);
        *(float4*)&wv[4] = *(const float4*)(W + (size_t)n * Fd + k0 + 4);
#pragma unroll
        for (int r = 0; r < 16; r++) {
            float a[8];
            *(float4*)&a[0] = *(const float4*)&sX[r * 260 + k0];
            *(float4*)&a[4] = *(const float4*)&sX[r * 260 + k0 + 4];
#pragma unroll
            for (int kk = 0; kk < 8; kk++) acc[r] += a[kk] * wv[kk];
        }
    }
    float bv = bias[n];
#pragma unroll
    for (int r = 0; r < 16; r++) sH[r * 260 + n] = acc[r] + bv;
    __syncthreads();

    const int warp = t >> 5, lane = t & 31;
#pragma unroll
    for (int rr = 0; rr < 2; rr++) {
        int r = warp * 2 + rr;
        float vals[8], s = 0.f;
#pragma unroll
        for (int q = 0; q < 8; q++) { vals[q] = sH[r * 260 + lane + q * 32]; s += vals[q]; }
#pragma unroll
        for (int o = 16; o; o >>= 1) s += __shfl_xor_sync(0xffffffffu, s, o);
        float mu = s * (1.f / 256.f);
        float vs = 0.f;
#pragma unroll
        for (int q = 0; q < 8; q++) { float d = vals[q] - mu; vs += d * d; }
#pragma unroll
        for (int o = 16; o; o >>= 1) vs += __shfl_xor_sync(0xffffffffu, vs, o);
        float rstd = rsqrtf(vs * (1.f / 256.f) + 1e-5f);
#pragma unroll
        for (int q = 0; q < 8; q++) {
            int c = lane + q * 32;
            out[(size_t)(row0 + r) * 256 + c] = g[c] * ((vals[q] - mu) * rstd) + be[c];
        }
    }
}

// ---------------------------------------------------------------------------
// Expand: out[b,x,y,h] = sum_f xf[b,x,h,f]*yf[b,y,h,f]
// Block tile: 16 x-rows, 64 y-rows; each thread 2 y (register blocking).
// ---------------------------------------------------------------------------
constexpr int EXP_SMEM_FLOATS = 16 * 8 * 36 + 64 * 8 * 36;   // 23040
constexpr int EXP_SMEM_BYTES  = EXP_SMEM_FLOATS * 4;          // 92160

__global__ void __launch_bounds__(256)
k_expand(float* __restrict__ out)
{
    extern __shared__ float es[];
    float* sX = es;                 // 16*8*36
    float* sY = es + 16 * 8 * 36;   // 64*8*36
    const int t = threadIdx.x;
    const int x0 = blockIdx.x * 16, y0 = blockIdx.y * 64, b = blockIdx.z;

#pragma unroll
    for (int s = 0; s < 4; s++) {                       // sX: 1024 float4
        int m = t + s * 256;
        int xi = m >> 6, c = (m & 63) * 4;
        int h = c >> 5, f = c & 31;
        float4 v = *(const float4*)(g_xf + (size_t)(b * Ld + x0 + xi) * HFd + c);
        float* d = &sX[(xi * 8 + h) * 36 + f];
        d[0] = v.x; d[1] = v.y; d[2] = v.z; d[3] = v.w;
    }
#pragma unroll
    for (int s = 0; s < 16; s++) {                      // sY: 4096 float4
        int m = t + s * 256;
        int yi = m >> 6, c = (m & 63) * 4;
        int h = c >> 5, f = c & 31;
        float4 v = *(const float4*)(g_yf + (size_t)(b * Rd + y0 + yi) * HFd + c);
        float* d = &sY[(yi * 8 + h) * 36 + f];
        d[0] = v.x; d[1] = v.y; d[2] = v.z; d[3] = v.w;
    }
    __syncthreads();

    const int h = t & 7, yy = t >> 3;   // yy in 0..31; handles yy and yy+32
    float acc[2][16];
#pragma unroll
    for (int p = 0; p < 2; p++)
#pragma unroll
        for (int xi = 0; xi < 16; xi++) acc[p][xi] = 0.f;
#pragma unroll
    for (int f4 = 0; f4 < 32; f4 += 4) {
        float4 yv0 = *(const float4*)&sY[(yy * 8 + h) * 36 + f4];
        float4 yv1 = *(const float4*)&sY[((yy + 32) * 8 + h) * 36 + f4];
#pragma unroll
        for (int xi = 0; xi < 16; xi++) {
            float4 xv = *(const float4*)&sX[(xi * 8 + h) * 36 + f4];
            acc[0][xi] += xv.x * yv0.x + xv.y * yv0.y + xv.z * yv0.z + xv.w * yv0.w;
            acc[1][xi] += xv.x * yv1.x + xv.y * yv1.y + xv.z * yv1.z + xv.w * yv1.w;
        }
    }
#pragma unroll
    for (int xi = 0; xi < 16; xi++) {
        out[((size_t)(b * Ld + x0 + xi) * Rd + y0 + yy) * Hd + h]      = acc[0][xi];
        out[((size_t)(b * Ld + x0 + xi) * Rd + y0 + yy + 32) * Hd + h] = acc[1][xi];
    }
}

// ---------------------------------------------------------------------------
// Zero llf region
// ---------------------------------------------------------------------------
__global__ void __launch_bounds__(256)
k_zero(float4* __restrict__ p)
{
    size_t base = ((size_t)blockIdx.x * 256 + threadIdx.x) * 4;
#pragma unroll
    for (int i = 0; i < 4; i++) p[base + i] = make_float4(0.f, 0.f, 0.f, 0.f);
}

// ---------------------------------------------------------------------------
// Edge: gather -> linear(2F->FE) -> lrelu -> atomic scatter into llf.
// ---------------------------------------------------------------------------
constexpr int WET_LD = 68;
constexpr int EDGE_SMEM_FLOATS = 512 * WET_LD + 32 * 512;
constexpr int EDGE_SMEM_BYTES  = EDGE_SMEM_FLOATS * 4;

__global__ void __launch_bounds__(256, 1)
k_edge(const float* __restrict__ lig, const int* __restrict__ eb,
       const int* __restrict__ es, const int* __restrict__ ed,
       const float* __restrict__ We, const float* __restrict__ be,
       float* __restrict__ llf)
{
    extern __shared__ float sm[];
    float* sWeT = sm;
    float* sEF  = sm + 512 * WET_LD;
    const int t = threadIdx.x;

#pragma unroll 8
    for (int s = 0; s < 128; s++) {
        int m = t + s * 256;
        int k = m & 511, o = m >> 9;
        sWeT[k * WET_LD + o] = We[o * 512 + k];
    }

    const int to = t & 7;
    const int te = t >> 3;
    float bev[8];
#pragma unroll
    for (int c = 0; c < 8; c++) bev[c] = be[to * 8 + c];

    for (int iter = 0; iter < 4; iter++) {
        __syncthreads();
#pragma unroll
        for (int s = 0; s < 16; s++) {
            int m = t + s * 256;
            int eg = m >> 7, kq = m & 127;
            int k = kq * 4;
            int e = blockIdx.x * 128 + iter * 32 + eg;
            int bb = eb[e];
            int row = (k < 256) ? es[e] : ed[e];
            int col = (k < 256) ? k : (k - 256);
            float4 v = *(const float4*)(lig + (size_t)(bb * Ld + row) * Fd + col);
            float* d = &sEF[eg * 512 + k];
            d[0] = v.x; d[1] = v.y; d[2] = v.z; d[3] = v.w;
        }
        __syncthreads();

        float acc[8];
#pragma unroll
        for (int c = 0; c < 8; c++) acc[c] = 0.f;
#pragma unroll 4
        for (int k = 0; k < 512; k++) {
            float a = sEF[te * 512 + k];
            float4 w0 = *(const float4*)&sWeT[k * WET_LD + to * 8];
            float4 w1 = *(const float4*)&sWeT[k * WET_LD + to * 8 + 4];
            acc[0] += a * w0.x; acc[1] += a * w0.y; acc[2] += a * w0.z; acc[3] += a * w0.w;
            acc[4] += a * w1.x; acc[5] += a * w1.y; acc[6] += a * w1.z; acc[7] += a * w1.w;
        }
        int e = blockIdx.x * 128 + iter * 32 + te;
        int bb = eb[e], ss = es[e], dd = ed[e];
        float* dst = llf + ((size_t)(bb * Ld + ss) * Ld + dd) * FEd + to * 8;
#pragma unroll
        for (int c = 0; c < 8; c++) atomicAdd(dst + c, lrelu(acc[c] + bev[c]));
    }
}

// ---------------------------------------------------------------------------
// Launch
// ---------------------------------------------------------------------------
extern "C" void kernel_launch(void* const* d_in, const int* in_sizes, int n_in,
                              void* d_out, int out_size)
{
    const float*    ll   = (const float*)d_in[0];
    const float*    lig  = (const float*)d_in[1];
    const float*    rec  = (const float*)d_in[2];
    const unsigned* mask = (const unsigned*)d_in[3];
    const int*      eb   = (const int*)d_in[4];
    const int*      es   = (const int*)d_in[5];
    const int*      ed   = (const int*)d_in[6];
    const float*    Wc   = (const float*)d_in[7];
    const float*    bc   = (const float*)d_in[8];
    const float*    gcc  = (const float*)d_in[9];
    const float*    bec  = (const float*)d_in[10];
    const float*    Wca  = (const float*)d_in[11];
    const float*    bca  = (const float*)d_in[12];
    const float*    Wex  = (const float*)d_in[13];
    const float*    bex  = (const float*)d_in[14];
    const float*    gex  = (const float*)d_in[15];
    const float*    beex = (const float*)d_in[16];
    const float*    Wey  = (const float*)d_in[17];
    const float*    bey  = (const float*)d_in[18];
    const float*    gey  = (const float*)d_in[19];
    const float*    beey = (const float*)d_in[20];
    const float*    We   = (const float*)d_in[21];
    const float*    be   = (const float*)d_in[22];

    float* out = (float*)d_out;
    float* oC = out;
    float* oE = out + (size_t)Bd * Ld * HFd;
    float* oL = oE + (size_t)Bd * Ld * Rd * Hd;

    cudaFuncSetAttribute(k_contract, cudaFuncAttributeMaxDynamicSharedMemorySize, SM_CONTRACT_BYTES);
    cudaFuncSetAttribute(k_edge, cudaFuncAttributeMaxDynamicSharedMemorySize, EDGE_SMEM_BYTES);
    cudaFuncSetAttribute(k_expand, cudaFuncAttributeMaxDynamicSharedMemorySize, EXP_SMEM_BYTES);

    void* pxf = nullptr; void* pyf = nullptr;
    cudaGetSymbolAddress(&pxf, g_xf);
    cudaGetSymbolAddress(&pyf, g_yf);

    // contract branch (tf32 mma.sync tensor cores)
    k_contract<<<dim3(128, 16), 256, SM_CONTRACT_BYTES>>>(ll, mask, Wc, bc, gcc, bec, Wca, bca, oC);

    // expand branch
    k_normlin<<<128, 256>>>(lig, Wex, bex, gex, beex, (float*)pxf);
    k_normlin<<<512, 256>>>(rec, Wey, bey, gey, beey, (float*)pyf);
    k_expand<<<dim3(8, 8, 16), 256, EXP_SMEM_BYTES>>>(oE);

    // edge branch
    k_zero<<<4096, 256>>>((float4*)oL);
    k_edge<<<128, 256, EDGE_SMEM_BYTES>>>(lig, eb, es, ed, We, be, oL);
}

// round 6
// speedup vs baseline: 2.5963x; 1.3670x over previous
#include <cuda_runtime.h>
#include <cuda_fp16.h>
#include <cstdint>
#include <cstddef>

// ---------------------------------------------------------------------------
// Problem dims
// ---------------------------------------------------------------------------
constexpr int Bd = 16, Ld = 128, Rd = 512, Fd = 256, Hd = 8, FHd = 32, FEd = 64, Ed = 16384;
constexpr int HFd = 256;

__device__ __forceinline__ float lrelu(float x) { return x > 0.f ? x : 0.01f * x; }

// Scratch (device globals: allocation-free)
__device__ float  g_xf[Bd * Ld * HFd];     // 2 MB
__device__ float  g_yf[Bd * Rd * HFd];     // 8 MB
__device__ __half g_Wh[8 * 264 * 32];      // Wc||Wca in half, chunked [c][n][32]

// fp16 m16n8k16 mma, f32 accum
__device__ __forceinline__ void mma_f16(float* c, uint32_t a0, uint32_t a1, uint32_t a2, uint32_t a3,
                                        uint32_t b0, uint32_t b1)
{
    asm volatile(
        "mma.sync.aligned.m16n8k16.row.col.f32.f16.f16.f32 "
        "{%0,%1,%2,%3}, {%4,%5,%6,%7}, {%8,%9}, {%0,%1,%2,%3};"
        : "+f"(c[0]), "+f"(c[1]), "+f"(c[2]), "+f"(c[3])
        : "r"(a0), "r"(a1), "r"(a2), "r"(a3), "r"(b0), "r"(b1));
}

__device__ __forceinline__ uint32_t smem_u32(const void* p) {
    uint32_t a;
    asm("{ .reg .u64 t; cvta.to.shared.u64 t, %1; cvt.u32.u64 %0, t; }" : "=r"(a) : "l"(p));
    return a;
}

// ---------------------------------------------------------------------------
// Prep kernel: Wc (256x256) || Wca (8x256) -> half, chunked [c][n][32]
// ---------------------------------------------------------------------------
__global__ void __launch_bounds__(256)
k_prep(const float* __restrict__ Wc, const float* __restrict__ Wca)
{
    int n = blockIdx.x;          // 0..263
    int k = threadIdx.x;         // 0..255
    float v = (n < 256) ? Wc[(size_t)n * 256 + k] : Wca[(size_t)(n - 256) * 256 + k];
    g_Wh[((size_t)(k >> 5) * 264 + n) * 32 + (k & 31)] = __float2half_rn(v);
}

// ---------------------------------------------------------------------------
// Contract kernel. 512 threads, 16 warps (wm = w>>2, wn = w&3).
// Warp tile: rows wm*32 (2 m16 tiles), cols wn*64 (8 n8 tiles) + logits tile
// (cols 256..263) on wn==3. A in smem half (full K), B cp.async double-buffered.
// Epilogue entirely on registers + small smem tables.
// ---------------------------------------------------------------------------
// byte offsets in dynamic smem
constexpr uint32_t SA_B  = 0;             // half [128][264], row stride 528 B
constexpr uint32_t SB_B  = 67584;         // 2 bufs x [264][40] half (80 B rows)
constexpr uint32_t SBSZ  = 21120;
constexpr uint32_t LG_B  = 109824;        // f32 [128][8]
constexpr uint32_t MU_B  = 113920;        // f32 [128]
constexpr uint32_t RS_B  = 114432;        // f32 [128]
constexpr uint32_t SP_B  = 114944;        // f32 [128][4]
constexpr uint32_t SQ_B  = 116992;        // f32 [128][4]
constexpr uint32_t CP_B  = 119040;        // f32 [4][256]
constexpr uint32_t G_B   = 123136;        // f32 [256]
constexpr uint32_t BE_B  = 124160;        // f32 [256]
constexpr uint32_t BC_B  = 125184;        // f32 [256]
constexpr uint32_t BCA_B = 126208;        // f32 [8]
constexpr uint32_t SUM_B = 126240;        // f32 [8]
constexpr int SM_CONTRACT_BYTES = 126272;

__global__ void __launch_bounds__(512, 1)
k_contract(const float* __restrict__ ll, const unsigned* __restrict__ mask,
           const float* __restrict__ bc, const float* __restrict__ gc,
           const float* __restrict__ bec, const float* __restrict__ bca,
           float* __restrict__ out)
{
    extern __shared__ char smc[];
    float* smf = (float*)smc;
    const uint32_t smb = smem_u32(smc);
    const int t = threadIdx.x;
    const int x = blockIdx.x, b = blockIdx.y;
    const int w = t >> 5, lane = t & 31;
    const int wm = w >> 2, wn = w & 3;
    const int qrow = lane >> 2, qcol = lane & 3;
    const int ntmax = (wn == 3) ? 9 : 8;

    // constants
    if (t < 256) {
        smf[(G_B >> 2) + t]  = gc[t];
        smf[(BE_B >> 2) + t] = bec[t];
        smf[(BC_B >> 2) + t] = bc[t];
    }
    if (t < 8) smf[(BCA_B >> 2) + t] = bca[t];

    // kick off B chunks 0 and 1 via cp.async
#pragma unroll
    for (int pc = 0; pc < 2; pc++) {
        uint32_t dbase = smb + SB_B + pc * SBSZ;
        for (int m = t; m < 1056; m += 512) {
            int n = m >> 2, k8 = m & 3;
            const __half* src = g_Wh + ((size_t)(pc * 264 + n) << 5) + k8 * 8;
            uint32_t dst = dbase + n * 80 + k8 * 16;
            asm volatile("cp.async.cg.shared.global [%0], [%1], 16;" :: "r"(dst), "l"(src));
        }
        asm volatile("cp.async.commit_group;");
    }

    // stage A (lrelu -> half): 128 x 256, row stride 528 B
    const float* Arow = ll + (size_t)(b * Ld + x) * Ld * Fd;
#pragma unroll
    for (int s = 0; s < 16; s++) {
        int m = t + s * 512;                 // float4 id, 8192 total
        int y = m >> 6, c4 = m & 63;
        float4 v = *(const float4*)(Arow + y * 256 + c4 * 4);
        __half2 h01 = __floats2half2_rn(lrelu(v.x), lrelu(v.y));
        __half2 h23 = __floats2half2_rn(lrelu(v.z), lrelu(v.w));
        uint2 u;
        u.x = *(uint32_t*)&h01; u.y = *(uint32_t*)&h23;
        *(uint2*)(smc + SA_B + y * 528 + c4 * 8) = u;
    }

    float acc[2][9][4];
#pragma unroll
    for (int mt = 0; mt < 2; mt++)
#pragma unroll
        for (int nt = 0; nt < 9; nt++)
#pragma unroll
            for (int q = 0; q < 4; q++) acc[mt][nt][q] = 0.f;

    const char* saB = smc + SA_B;
    const int r0base = wm * 32 + qrow;

    // main loop: 8 chunks of K=32 (2 k-steps each)
    for (int c = 0; c < 8; c++) {
        asm volatile("cp.async.wait_group 1;");
        __syncthreads();
        const char* sbB = smc + SB_B + (c & 1) * SBSZ;
#pragma unroll
        for (int sub = 0; sub < 2; sub++) {
            const int khw = ((c * 2 + sub) * 8 + qcol) * 4;   // byte offset of half2 in A row
            uint32_t af[2][4];
#pragma unroll
            for (int mt = 0; mt < 2; mt++) {
                const char* base = saB + (r0base + mt * 16) * 528 + khw;
                af[mt][0] = *(const uint32_t*)(base);
                af[mt][1] = *(const uint32_t*)(base + 8 * 528);
                af[mt][2] = *(const uint32_t*)(base + 16);
                af[mt][3] = *(const uint32_t*)(base + 8 * 528 + 16);
            }
            const int kbw = (sub * 8 + qcol) * 4;             // byte offset in B row
            for (int nt = 0; nt < ntmax; nt++) {
                int nbase = (nt < 8) ? (wn * 64 + nt * 8) : 256;
                const char* brow = sbB + (nbase + qrow) * 80 + kbw;
                uint32_t b0 = *(const uint32_t*)(brow);
                uint32_t b1 = *(const uint32_t*)(brow + 16);
                mma_f16(acc[0][nt], af[0][0], af[0][1], af[0][2], af[0][3], b0, b1);
                mma_f16(acc[1][nt], af[1][0], af[1][1], af[1][2], af[1][3], b0, b1);
            }
        }
        __syncthreads();
        if (c + 2 < 8) {
            uint32_t dbase = smb + SB_B + (c & 1) * SBSZ;
            int cc = c + 2;
            for (int m = t; m < 1056; m += 512) {
                int n = m >> 2, k8 = m & 3;
                const __half* src = g_Wh + ((size_t)(cc * 264 + n) << 5) + k8 * 8;
                uint32_t dst = dbase + n * 80 + k8 * 16;
                asm volatile("cp.async.cg.shared.global [%0], [%1], 16;" :: "r"(dst), "l"(src));
            }
        }
        asm volatile("cp.async.commit_group;");
    }

    // ---- epilogue phase 1: bias add, logits out, LN partial sums ----
#pragma unroll
    for (int mt = 0; mt < 2; mt++)
#pragma unroll
        for (int nt = 0; nt < 8; nt++) {
            int col = wn * 64 + nt * 8 + 2 * qcol;
            float b0 = smf[(BC_B >> 2) + col], b1 = smf[(BC_B >> 2) + col + 1];
            acc[mt][nt][0] += b0; acc[mt][nt][1] += b1;
            acc[mt][nt][2] += b0; acc[mt][nt][3] += b1;
        }
    if (wn == 3) {
        float ba0 = smf[(BCA_B >> 2) + 2 * qcol], ba1 = smf[(BCA_B >> 2) + 2 * qcol + 1];
#pragma unroll
        for (int mt = 0; mt < 2; mt++) {
            int r = r0base + mt * 16;
            smf[(LG_B >> 2) + r * 8 + 2 * qcol]           = acc[mt][8][0] + ba0;
            smf[(LG_B >> 2) + r * 8 + 2 * qcol + 1]       = acc[mt][8][1] + ba1;
            smf[(LG_B >> 2) + (r + 8) * 8 + 2 * qcol]     = acc[mt][8][2] + ba0;
            smf[(LG_B >> 2) + (r + 8) * 8 + 2 * qcol + 1] = acc[mt][8][3] + ba1;
        }
    }
    // LN partials over this warp's 64-col slice for its 4 rows
#pragma unroll
    for (int mt = 0; mt < 2; mt++)
#pragma unroll
        for (int e = 0; e < 2; e++) {
            int r = r0base + mt * 16 + e * 8;
            int qb = e * 2;
            float s = 0.f, sq = 0.f;
#pragma unroll
            for (int nt = 0; nt < 8; nt++) {
                float v0 = acc[mt][nt][qb], v1 = acc[mt][nt][qb + 1];
                s += v0 + v1; sq += v0 * v0 + v1 * v1;
            }
            s  += __shfl_xor_sync(0xffffffffu, s, 1);  s  += __shfl_xor_sync(0xffffffffu, s, 2);
            sq += __shfl_xor_sync(0xffffffffu, sq, 1); sq += __shfl_xor_sync(0xffffffffu, sq, 2);
            if (qcol == 0) {
                smf[(SP_B >> 2) + r * 4 + wn] = s;
                smf[(SQ_B >> 2) + r * 4 + wn] = sq;
            }
        }
    __syncthreads();

    // ---- phase 2: row stats (warps 0-3) + masked softmax (warps 8-15) ----
    if (t < 128) {
        int r = t;
        float s  = smf[(SP_B >> 2) + r * 4] + smf[(SP_B >> 2) + r * 4 + 1]
                 + smf[(SP_B >> 2) + r * 4 + 2] + smf[(SP_B >> 2) + r * 4 + 3];
        float sq = smf[(SQ_B >> 2) + r * 4] + smf[(SQ_B >> 2) + r * 4 + 1]
                 + smf[(SQ_B >> 2) + r * 4 + 2] + smf[(SQ_B >> 2) + r * 4 + 3];
        float mu = s * (1.f / 256.f);
        float var = sq * (1.f / 256.f) - mu * mu;
        smf[(MU_B >> 2) + r] = mu;
        smf[(RS_B >> 2) + r] = rsqrtf(var + 1e-5f);
    }
    if (w >= 8) {
        int h = w - 8;
        float lv[4];
#pragma unroll
        for (int q = 0; q < 4; q++) lv[q] = smf[(LG_B >> 2) + (lane + q * 32) * 8 + h];
        float mx = fmaxf(fmaxf(lv[0], lv[1]), fmaxf(lv[2], lv[3]));
#pragma unroll
        for (int o = 16; o; o >>= 1) mx = fmaxf(mx, __shfl_xor_sync(0xffffffffu, mx, o));
        const unsigned* mrow = mask + (size_t)(b * Ld + x) * Ld;
        float e[4], sum = 0.f;
#pragma unroll
        for (int q = 0; q < 4; q++) {
            int y = lane + q * 32;
            float ee = (mrow[y] != 0u) ? expf(lv[q] - mx) : 0.f;
            e[q] = ee; sum += ee;
        }
#pragma unroll
        for (int o = 16; o; o >>= 1) sum += __shfl_xor_sync(0xffffffffu, sum, o);
#pragma unroll
        for (int q = 0; q < 4; q++) smf[(LG_B >> 2) + (lane + q * 32) * 8 + h] = e[q];
        if (lane == 0) smf[(SUM_B >> 2) + h] = sum + 1e-10f;
    }
    __syncthreads();

    // ---- phase 3: LN apply + weighted contraction over this warp's rows ----
    {
        float psum[16];
#pragma unroll
        for (int i = 0; i < 16; i++) psum[i] = 0.f;
#pragma unroll
        for (int mt = 0; mt < 2; mt++)
#pragma unroll
            for (int e = 0; e < 2; e++) {
                int r = r0base + mt * 16 + e * 8;
                int qb = e * 2;
                float mu = smf[(MU_B >> 2) + r];
                float rs = smf[(RS_B >> 2) + r];
                float a0 = smf[(LG_B >> 2) + r * 8 + wn * 2];
                float a1 = smf[(LG_B >> 2) + r * 8 + wn * 2 + 1];
#pragma unroll
                for (int nt = 0; nt < 8; nt++) {
                    int col = wn * 64 + nt * 8 + 2 * qcol;
                    float g0 = smf[(G_B >> 2) + col],  g1 = smf[(G_B >> 2) + col + 1];
                    float e0 = smf[(BE_B >> 2) + col], e1 = smf[(BE_B >> 2) + col + 1];
                    float of0 = g0 * ((acc[mt][nt][qb] - mu) * rs) + e0;
                    float of1 = g1 * ((acc[mt][nt][qb + 1] - mu) * rs) + e1;
                    float a = (nt < 4) ? a0 : a1;
                    psum[nt * 2]     += a * of0;
                    psum[nt * 2 + 1] += a * of1;
                }
            }
        // reduce over qrow lanes (bits 2..4 of lane)
#pragma unroll
        for (int i = 0; i < 16; i++) {
            psum[i] += __shfl_xor_sync(0xffffffffu, psum[i], 4);
            psum[i] += __shfl_xor_sync(0xffffffffu, psum[i], 8);
            psum[i] += __shfl_xor_sync(0xffffffffu, psum[i], 16);
        }
        if (qrow == 0) {
#pragma unroll
            for (int nt = 0; nt < 8; nt++) {
                int col = wn * 64 + nt * 8 + 2 * qcol;
                smf[(CP_B >> 2) + wm * 256 + col]     = psum[nt * 2];
                smf[(CP_B >> 2) + wm * 256 + col + 1] = psum[nt * 2 + 1];
            }
        }
    }
    __syncthreads();

    if (t < 256) {
        int col = t, h = col >> 5;
        float v = smf[(CP_B >> 2) + col] + smf[(CP_B >> 2) + 256 + col]
                + smf[(CP_B >> 2) + 512 + col] + smf[(CP_B >> 2) + 768 + col];
        out[(size_t)(b * Ld + x) * HFd + col] = v / smf[(SUM_B >> 2) + h];
    }
}

// ---------------------------------------------------------------------------
// NormAndLinear for lig/rec: block = 16 rows, thread = output column.
// ---------------------------------------------------------------------------
__global__ void __launch_bounds__(256)
k_normlin(const float* __restrict__ X, const float* __restrict__ W,
          const float* __restrict__ bias, const float* __restrict__ g,
          const float* __restrict__ be, float* __restrict__ out)
{
    __shared__ float sX[16 * 260];
    __shared__ float sH[16 * 260];
    const int t = threadIdx.x;
    const int row0 = blockIdx.x * 16;

#pragma unroll
    for (int s = 0; s < 4; s++) {
        int m = t + s * 256;
        int r = m >> 6, c = (m & 63) * 4;
        float4 v = *(const float4*)(X + (size_t)(row0 + r) * Fd + c);
        sX[r * 260 + c + 0] = lrelu(v.x);
        sX[r * 260 + c + 1] = lrelu(v.y);
        sX[r * 260 + c + 2] = lrelu(v.z);
        sX[r * 260 + c + 3] = lrelu(v.w);
    }
    __syncthreads();

    float acc[16];
#pragma unroll
    for (int r = 0; r < 16; r++) acc[r] = 0.f;
    const int n = t;
    for (int k0 = 0; k0 < 256; k0 += 8) {
        float wv[8];
        *(float4*)&wv[0] = *(const float4*)(W + (size_t)n * Fd + k0);
        *(float4*)&wv[4] = *(const float4*)(W + (size_t)n * Fd + k0 + 4);
#pragma unroll
        for (int r = 0; r < 16; r++) {
            float a[8];
            *(float4*)&a[0] = *(const float4*)&sX[r * 260 + k0];
            *(float4*)&a[4] = *(const float4*)&sX[r * 260 + k0 + 4];
#pragma unroll
            for (int kk = 0; kk < 8; kk++) acc[r] += a[kk] * wv[kk];
        }
    }
    float bv = bias[n];
#pragma unroll
    for (int r = 0; r < 16; r++) sH[r * 260 + n] = acc[r] + bv;
    __syncthreads();

    const int warp = t >> 5, lane = t & 31;
#pragma unroll
    for (int rr = 0; rr < 2; rr++) {
        int r = warp * 2 + rr;
        float vals[8], s = 0.f;
#pragma unroll
        for (int q = 0; q < 8; q++) { vals[q] = sH[r * 260 + lane + q * 32]; s += vals[q]; }
#pragma unroll
        for (int o = 16; o; o >>= 1) s += __shfl_xor_sync(0xffffffffu, s, o);
        float mu = s * (1.f / 256.f);
        float vs = 0.f;
#pragma unroll
        for (int q = 0; q < 8; q++) { float d = vals[q] - mu; vs += d * d; }
#pragma unroll
        for (int o = 16; o; o >>= 1) vs += __shfl_xor_sync(0xffffffffu, vs, o);
        float rstd = rsqrtf(vs * (1.f / 256.f) + 1e-5f);
#pragma unroll
        for (int q = 0; q < 8; q++) {
            int c = lane + q * 32;
            out[(size_t)(row0 + r) * 256 + c] = g[c] * ((vals[q] - mu) * rstd) + be[c];
        }
    }
}

// ---------------------------------------------------------------------------
// Expand: out[b,x,y,h] = sum_f xf[b,x,h,f]*yf[b,y,h,f]
// Block tile: 16 x-rows, 64 y-rows; each thread 2 y.
// ---------------------------------------------------------------------------
constexpr int EXP_SMEM_FLOATS = 16 * 8 * 36 + 64 * 8 * 36;
constexpr int EXP_SMEM_BYTES  = EXP_SMEM_FLOATS * 4;

__global__ void __launch_bounds__(256)
k_expand(float* __restrict__ out)
{
    extern __shared__ float es[];
    float* sX = es;
    float* sY = es + 16 * 8 * 36;
    const int t = threadIdx.x;
    const int x0 = blockIdx.x * 16, y0 = blockIdx.y * 64, b = blockIdx.z;

#pragma unroll
    for (int s = 0; s < 4; s++) {
        int m = t + s * 256;
        int xi = m >> 6, c = (m & 63) * 4;
        int h = c >> 5, f = c & 31;
        float4 v = *(const float4*)(g_xf + (size_t)(b * Ld + x0 + xi) * HFd + c);
        float* d = &sX[(xi * 8 + h) * 36 + f];
        d[0] = v.x; d[1] = v.y; d[2] = v.z; d[3] = v.w;
    }
#pragma unroll
    for (int s = 0; s < 16; s++) {
        int m = t + s * 256;
        int yi = m >> 6, c = (m & 63) * 4;
        int h = c >> 5, f = c & 31;
        float4 v = *(const float4*)(g_yf + (size_t)(b * Rd + y0 + yi) * HFd + c);
        float* d = &sY[(yi * 8 + h) * 36 + f];
        d[0] = v.x; d[1] = v.y; d[2] = v.z; d[3] = v.w;
    }
    __syncthreads();

    const int h = t & 7, yy = t >> 3;
    float acc[2][16];
#pragma unroll
    for (int p = 0; p < 2; p++)
#pragma unroll
        for (int xi = 0; xi < 16; xi++) acc[p][xi] = 0.f;
#pragma unroll
    for (int f4 = 0; f4 < 32; f4 += 4) {
        float4 yv0 = *(const float4*)&sY[(yy * 8 + h) * 36 + f4];
        float4 yv1 = *(const float4*)&sY[((yy + 32) * 8 + h) * 36 + f4];
#pragma unroll
        for (int xi = 0; xi < 16; xi++) {
            float4 xv = *(const float4*)&sX[(xi * 8 + h) * 36 + f4];
            acc[0][xi] += xv.x * yv0.x + xv.y * yv0.y + xv.z * yv0.z + xv.w * yv0.w;
            acc[1][xi] += xv.x * yv1.x + xv.y * yv1.y + xv.z * yv1.z + xv.w * yv1.w;
        }
    }
#pragma unroll
    for (int xi = 0; xi < 16; xi++) {
        out[((size_t)(b * Ld + x0 + xi) * Rd + y0 + yy) * Hd + h]      = acc[0][xi];
        out[((size_t)(b * Ld + x0 + xi) * Rd + y0 + yy + 32) * Hd + h] = acc[1][xi];
    }
}

// ---------------------------------------------------------------------------
// Zero llf region
// ---------------------------------------------------------------------------
__global__ void __launch_bounds__(256)
k_zero(float4* __restrict__ p)
{
    size_t base = ((size_t)blockIdx.x * 256 + threadIdx.x) * 4;
#pragma unroll
    for (int i = 0; i < 4; i++) p[base + i] = make_float4(0.f, 0.f, 0.f, 0.f);
}

// ---------------------------------------------------------------------------
// Edge: gather -> linear(2F->FE) -> lrelu -> atomic scatter into llf.
// ---------------------------------------------------------------------------
constexpr int WET_LD = 68;
constexpr int EDGE_SMEM_FLOATS = 512 * WET_LD + 32 * 512;
constexpr int EDGE_SMEM_BYTES  = EDGE_SMEM_FLOATS * 4;

__global__ void __launch_bounds__(256, 1)
k_edge(const float* __restrict__ lig, const int* __restrict__ eb,
       const int* __restrict__ es, const int* __restrict__ ed,
       const float* __restrict__ We, const float* __restrict__ be,
       float* __restrict__ llf)
{
    extern __shared__ float sm[];
    float* sWeT = sm;
    float* sEF  = sm + 512 * WET_LD;
    const int t = threadIdx.x;

#pragma unroll 8
    for (int s = 0; s < 128; s++) {
        int m = t + s * 256;
        int k = m & 511, o = m >> 9;
        sWeT[k * WET_LD + o] = We[o * 512 + k];
    }

    const int to = t & 7;
    const int te = t >> 3;
    float bev[8];
#pragma unroll
    for (int c = 0; c < 8; c++) bev[c] = be[to * 8 + c];

    for (int iter = 0; iter < 4; iter++) {
        __syncthreads();
#pragma unroll
        for (int s = 0; s < 16; s++) {
            int m = t + s * 256;
            int eg = m >> 7, kq = m & 127;
            int k = kq * 4;
            int e = blockIdx.x * 128 + iter * 32 + eg;
            int bb = eb[e];
            int row = (k < 256) ? es[e] : ed[e];
            int col = (k < 256) ? k : (k - 256);
            float4 v = *(const float4*)(lig + (size_t)(bb * Ld + row) * Fd + col);
            float* d = &sEF[eg * 512 + k];
            d[0] = v.x; d[1] = v.y; d[2] = v.z; d[3] = v.w;
        }
        __syncthreads();

        float acc[8];
#pragma unroll
        for (int c = 0; c < 8; c++) acc[c] = 0.f;
#pragma unroll 4
        for (int k = 0; k < 512; k++) {
            float a = sEF[te * 512 + k];
            float4 w0 = *(const float4*)&sWeT[k * WET_LD + to * 8];
            float4 w1 = *(const float4*)&sWeT[k * WET_LD + to * 8 + 4];
            acc[0] += a * w0.x; acc[1] += a * w0.y; acc[2] += a * w0.z; acc[3] += a * w0.w;
            acc[4] += a * w1.x; acc[5] += a * w1.y; acc[6] += a * w1.z; acc[7] += a * w1.w;
        }
        int e = blockIdx.x * 128 + iter * 32 + te;
        int bb = eb[e], ss = es[e], dd = ed[e];
        float* dst = llf + ((size_t)(bb * Ld + ss) * Ld + dd) * FEd + to * 8;
#pragma unroll
        for (int c = 0; c < 8; c++) atomicAdd(dst + c, lrelu(acc[c] + bev[c]));
    }
}

// ---------------------------------------------------------------------------
// Launch
// ---------------------------------------------------------------------------
extern "C" void kernel_launch(void* const* d_in, const int* in_sizes, int n_in,
                              void* d_out, int out_size)
{
    const float*    ll   = (const float*)d_in[0];
    const float*    lig  = (const float*)d_in[1];
    const float*    rec  = (const float*)d_in[2];
    const unsigned* mask = (const unsigned*)d_in[3];
    const int*      eb   = (const int*)d_in[4];
    const int*      es   = (const int*)d_in[5];
    const int*      ed   = (const int*)d_in[6];
    const float*    Wc   = (const float*)d_in[7];
    const float*    bc   = (const float*)d_in[8];
    const float*    gcc  = (const float*)d_in[9];
    const float*    bec  = (const float*)d_in[10];
    const float*    Wca  = (const float*)d_in[11];
    const float*    bca  = (const float*)d_in[12];
    const float*    Wex  = (const float*)d_in[13];
    const float*    bex  = (const float*)d_in[14];
    const float*    gex  = (const float*)d_in[15];
    const float*    beex = (const float*)d_in[16];
    const float*    Wey  = (const float*)d_in[17];
    const float*    bey  = (const float*)d_in[18];
    const float*    gey  = (const float*)d_in[19];
    const float*    beey = (const float*)d_in[20];
    const float*    We   = (const float*)d_in[21];
    const float*    be   = (const float*)d_in[22];

    float* out = (float*)d_out;
    float* oC = out;
    float* oE = out + (size_t)Bd * Ld * HFd;
    float* oL = oE + (size_t)Bd * Ld * Rd * Hd;

    cudaFuncSetAttribute(k_contract, cudaFuncAttributeMaxDynamicSharedMemorySize, SM_CONTRACT_BYTES);
    cudaFuncSetAttribute(k_edge, cudaFuncAttributeMaxDynamicSharedMemorySize, EDGE_SMEM_BYTES);
    cudaFuncSetAttribute(k_expand, cudaFuncAttributeMaxDynamicSharedMemorySize, EXP_SMEM_BYTES);

    void* pxf = nullptr; void* pyf = nullptr;
    cudaGetSymbolAddress(&pxf, g_xf);
    cudaGetSymbolAddress(&pyf, g_yf);

    // prep half weights, then contract (fp16 mma tensor cores)
    k_prep<<<264, 256>>>(Wc, Wca);
    k_contract<<<dim3(128, 16), 512, SM_CONTRACT_BYTES>>>(ll, mask, bc, gcc, bec, bca, oC);

    // expand branch
    k_normlin<<<128, 256>>>(lig, Wex, bex, gex, beex, (float*)pxf);
    k_normlin<<<512, 256>>>(rec, Wey, bey, gey, beey, (float*)pyf);
    k_expand<<<dim3(8, 8, 16), 256, EXP_SMEM_BYTES>>>(oE);

    // edge branch
    k_zero<<<4096, 256>>>((float4*)oL);
    k_edge<<<128, 256, EDGE_SMEM_BYTES>>>(lig, eb, es, ed, We, be, oL);
}

// round 7
// speedup vs baseline: 2.6037x; 1.0028x over previous
#include <cuda_runtime.h>
#include <cuda_fp16.h>
#include <cstdint>
#include <cstddef>

// ---------------------------------------------------------------------------
// Problem dims
// ---------------------------------------------------------------------------
constexpr int Bd = 16, Ld = 128, Rd = 512, Fd = 256, Hd = 8, FHd = 32, FEd = 64, Ed = 16384;
constexpr int HFd = 256;

__device__ __forceinline__ float lrelu(float x) { return x > 0.f ? x : 0.01f * x; }

// Scratch (device globals: allocation-free)
__device__ float  g_xf[Bd * Ld * HFd];     // 2 MB
__device__ float  g_yf[Bd * Rd * HFd];     // 8 MB
__device__ __half g_Wh[8 * 264 * 32];      // Wc||Wca in half, chunked [c][n][32]

// fp16 m16n8k16 mma, f32 accum
__device__ __forceinline__ void mma_f16(float* c, uint32_t a0, uint32_t a1, uint32_t a2, uint32_t a3,
                                        uint32_t b0, uint32_t b1)
{
    asm volatile(
        "mma.sync.aligned.m16n8k16.row.col.f32.f16.f16.f32 "
        "{%0,%1,%2,%3}, {%4,%5,%6,%7}, {%8,%9}, {%0,%1,%2,%3};"
        : "+f"(c[0]), "+f"(c[1]), "+f"(c[2]), "+f"(c[3])
        : "r"(a0), "r"(a1), "r"(a2), "r"(a3), "r"(b0), "r"(b1));
}

__device__ __forceinline__ uint32_t smem_u32(const void* p) {
    uint32_t a;
    asm("{ .reg .u64 t; cvta.to.shared.u64 t, %1; cvt.u32.u64 %0, t; }" : "=r"(a) : "l"(p));
    return a;
}

// ---------------------------------------------------------------------------
// Prep kernel: Wc (256x256) || Wca (8x256) -> half, chunked [c][n][32]
// ---------------------------------------------------------------------------
__global__ void __launch_bounds__(256)
k_prep(const float* __restrict__ Wc, const float* __restrict__ Wca)
{
    int n = blockIdx.x;          // 0..263
    int k = threadIdx.x;         // 0..255
    float v = (n < 256) ? Wc[(size_t)n * 256 + k] : Wca[(size_t)(n - 256) * 256 + k];
    g_Wh[((size_t)(k >> 5) * 264 + n) * 32 + (k & 31)] = __float2half_rn(v);
}

// ---------------------------------------------------------------------------
// Contract kernel. 512 threads, 16 warps (wm = w>>2, wn = w&3).
// Warp tile: rows wm*32 (2 m16 tiles), cols wn*64 (8 n8 tiles) + logits tile
// (cols 256..263) on wn==3. A in smem half (full K), B cp.async double-buffered.
// Epilogue entirely on registers + small smem tables.
// ---------------------------------------------------------------------------
// byte offsets in dynamic smem
constexpr uint32_t SA_B  = 0;             // half [128][264], row stride 528 B
constexpr uint32_t SB_B  = 67584;         // 2 bufs x [264][40] half (80 B rows)
constexpr uint32_t SBSZ  = 21120;
constexpr uint32_t LG_B  = 109824;        // f32 [128][8]
constexpr uint32_t MU_B  = 113920;        // f32 [128]
constexpr uint32_t RS_B  = 114432;        // f32 [128]
constexpr uint32_t SP_B  = 114944;        // f32 [128][4]
constexpr uint32_t SQ_B  = 116992;        // f32 [128][4]
constexpr uint32_t CP_B  = 119040;        // f32 [4][256]
constexpr uint32_t G_B   = 123136;        // f32 [256]
constexpr uint32_t BE_B  = 124160;        // f32 [256]
constexpr uint32_t BC_B  = 125184;        // f32 [256]
constexpr uint32_t BCA_B = 126208;        // f32 [8]
constexpr uint32_t SUM_B = 126240;        // f32 [8]
constexpr int SM_CONTRACT_BYTES = 126272;

__global__ void __launch_bounds__(512, 1)
k_contract(const float* __restrict__ ll, const unsigned* __restrict__ mask,
           const float* __restrict__ bc, const float* __restrict__ gc,
           const float* __restrict__ bec, const float* __restrict__ bca,
           float* __restrict__ out)
{
    extern __shared__ char smc[];
    float* smf = (float*)smc;
    const uint32_t smb = smem_u32(smc);
    const int t = threadIdx.x;
    const int x = blockIdx.x, b = blockIdx.y;
    const int w = t >> 5, lane = t & 31;
    const int wm = w >> 2, wn = w & 3;
    const int qrow = lane >> 2, qcol = lane & 3;
    const int ntmax = (wn == 3) ? 9 : 8;

    // constants
    if (t < 256) {
        smf[(G_B >> 2) + t]  = gc[t];
        smf[(BE_B >> 2) + t] = bec[t];
        smf[(BC_B >> 2) + t] = bc[t];
    }
    if (t < 8) smf[(BCA_B >> 2) + t] = bca[t];

    // kick off B chunks 0 and 1 via cp.async
#pragma unroll
    for (int pc = 0; pc < 2; pc++) {
        uint32_t dbase = smb + SB_B + pc * SBSZ;
        for (int m = t; m < 1056; m += 512) {
            int n = m >> 2, k8 = m & 3;
            const __half* src = g_Wh + ((size_t)(pc * 264 + n) << 5) + k8 * 8;
            uint32_t dst = dbase + n * 80 + k8 * 16;
            asm volatile("cp.async.cg.shared.global [%0], [%1], 16;" :: "r"(dst), "l"(src));
        }
        asm volatile("cp.async.commit_group;");
    }

    // stage A (lrelu -> half): 128 x 256, row stride 528 B
    const float* Arow = ll + (size_t)(b * Ld + x) * Ld * Fd;
#pragma unroll
    for (int s = 0; s < 16; s++) {
        int m = t + s * 512;                 // float4 id, 8192 total
        int y = m >> 6, c4 = m & 63;
        float4 v = *(const float4*)(Arow + y * 256 + c4 * 4);
        __half2 h01 = __floats2half2_rn(lrelu(v.x), lrelu(v.y));
        __half2 h23 = __floats2half2_rn(lrelu(v.z), lrelu(v.w));
        uint2 u;
        u.x = *(uint32_t*)&h01; u.y = *(uint32_t*)&h23;
        *(uint2*)(smc + SA_B + y * 528 + c4 * 8) = u;
    }

    float acc[2][9][4];
#pragma unroll
    for (int mt = 0; mt < 2; mt++)
#pragma unroll
        for (int nt = 0; nt < 9; nt++)
#pragma unroll
            for (int q = 0; q < 4; q++) acc[mt][nt][q] = 0.f;

    const char* saB = smc + SA_B;
    const int r0base = wm * 32 + qrow;

    // main loop: 8 chunks of K=32 (2 k-steps each)
    for (int c = 0; c < 8; c++) {
        asm volatile("cp.async.wait_group 1;");
        __syncthreads();
        const char* sbB = smc + SB_B + (c & 1) * SBSZ;
#pragma unroll
        for (int sub = 0; sub < 2; sub++) {
            const int khw = ((c * 2 + sub) * 8 + qcol) * 4;   // byte offset of half2 in A row
            uint32_t af[2][4];
#pragma unroll
            for (int mt = 0; mt < 2; mt++) {
                const char* base = saB + (r0base + mt * 16) * 528 + khw;
                af[mt][0] = *(const uint32_t*)(base);
                af[mt][1] = *(const uint32_t*)(base + 8 * 528);
                af[mt][2] = *(const uint32_t*)(base + 16);
                af[mt][3] = *(const uint32_t*)(base + 8 * 528 + 16);
            }
            const int kbw = (sub * 8 + qcol) * 4;             // byte offset in B row
            for (int nt = 0; nt < ntmax; nt++) {
                int nbase = (nt < 8) ? (wn * 64 + nt * 8) : 256;
                const char* brow = sbB + (nbase + qrow) * 80 + kbw;
                uint32_t b0 = *(const uint32_t*)(brow);
                uint32_t b1 = *(const uint32_t*)(brow + 16);
                mma_f16(acc[0][nt], af[0][0], af[0][1], af[0][2], af[0][3], b0, b1);
                mma_f16(acc[1][nt], af[1][0], af[1][1], af[1][2], af[1][3], b0, b1);
            }
        }
        __syncthreads();
        if (c + 2 < 8) {
            uint32_t dbase = smb + SB_B + (c & 1) * SBSZ;
            int cc = c + 2;
            for (int m = t; m < 1056; m += 512) {
                int n = m >> 2, k8 = m & 3;
                const __half* src = g_Wh + ((size_t)(cc * 264 + n) << 5) + k8 * 8;
                uint32_t dst = dbase + n * 80 + k8 * 16;
                asm volatile("cp.async.cg.shared.global [%0], [%1], 16;" :: "r"(dst), "l"(src));
            }
        }
        asm volatile("cp.async.commit_group;");
    }

    // ---- epilogue phase 1: bias add, logits out, LN partial sums ----
#pragma unroll
    for (int mt = 0; mt < 2; mt++)
#pragma unroll
        for (int nt = 0; nt < 8; nt++) {
            int col = wn * 64 + nt * 8 + 2 * qcol;
            float b0 = smf[(BC_B >> 2) + col], b1 = smf[(BC_B >> 2) + col + 1];
            acc[mt][nt][0] += b0; acc[mt][nt][1] += b1;
            acc[mt][nt][2] += b0; acc[mt][nt][3] += b1;
        }
    if (wn == 3) {
        float ba0 = smf[(BCA_B >> 2) + 2 * qcol], ba1 = smf[(BCA_B >> 2) + 2 * qcol + 1];
#pragma unroll
        for (int mt = 0; mt < 2; mt++) {
            int r = r0base + mt * 16;
            smf[(LG_B >> 2) + r * 8 + 2 * qcol]           = acc[mt][8][0] + ba0;
            smf[(LG_B >> 2) + r * 8 + 2 * qcol + 1]       = acc[mt][8][1] + ba1;
            smf[(LG_B >> 2) + (r + 8) * 8 + 2 * qcol]     = acc[mt][8][2] + ba0;
            smf[(LG_B >> 2) + (r + 8) * 8 + 2 * qcol + 1] = acc[mt][8][3] + ba1;
        }
    }
    // LN partials over this warp's 64-col slice for its 4 rows
#pragma unroll
    for (int mt = 0; mt < 2; mt++)
#pragma unroll
        for (int e = 0; e < 2; e++) {
            int r = r0base + mt * 16 + e * 8;
            int qb = e * 2;
            float s = 0.f, sq = 0.f;
#pragma unroll
            for (int nt = 0; nt < 8; nt++) {
                float v0 = acc[mt][nt][qb], v1 = acc[mt][nt][qb + 1];
                s += v0 + v1; sq += v0 * v0 + v1 * v1;
            }
            s  += __shfl_xor_sync(0xffffffffu, s, 1);  s  += __shfl_xor_sync(0xffffffffu, s, 2);
            sq += __shfl_xor_sync(0xffffffffu, sq, 1); sq += __shfl_xor_sync(0xffffffffu, sq, 2);
            if (qcol == 0) {
                smf[(SP_B >> 2) + r * 4 + wn] = s;
                smf[(SQ_B >> 2) + r * 4 + wn] = sq;
            }
        }
    __syncthreads();

    // ---- phase 2: row stats (warps 0-3) + masked softmax (warps 8-15) ----
    if (t < 128) {
        int r = t;
        float s  = smf[(SP_B >> 2) + r * 4] + smf[(SP_B >> 2) + r * 4 + 1]
                 + smf[(SP_B >> 2) + r * 4 + 2] + smf[(SP_B >> 2) + r * 4 + 3];
        float sq = smf[(SQ_B >> 2) + r * 4] + smf[(SQ_B >> 2) + r * 4 + 1]
                 + smf[(SQ_B >> 2) + r * 4 + 2] + smf[(SQ_B >> 2) + r * 4 + 3];
        float mu = s * (1.f / 256.f);
        float var = sq * (1.f / 256.f) - mu * mu;
        smf[(MU_B >> 2) + r] = mu;
        smf[(RS_B >> 2) + r] = rsqrtf(var + 1e-5f);
    }
    if (w >= 8) {
        int h = w - 8;
        float lv[4];
#pragma unroll
        for (int q = 0; q < 4; q++) lv[q] = smf[(LG_B >> 2) + (lane + q * 32) * 8 + h];
        float mx = fmaxf(fmaxf(lv[0], lv[1]), fmaxf(lv[2], lv[3]));
#pragma unroll
        for (int o = 16; o; o >>= 1) mx = fmaxf(mx, __shfl_xor_sync(0xffffffffu, mx, o));
        const unsigned* mrow = mask + (size_t)(b * Ld + x) * Ld;
        float e[4], sum = 0.f;
#pragma unroll
        for (int q = 0; q < 4; q++) {
            int y = lane + q * 32;
            float ee = (mrow[y] != 0u) ? expf(lv[q] - mx) : 0.f;
            e[q] = ee; sum += ee;
        }
#pragma unroll
        for (int o = 16; o; o >>= 1) sum += __shfl_xor_sync(0xffffffffu, sum, o);
#pragma unroll
        for (int q = 0; q < 4; q++) smf[(LG_B >> 2) + (lane + q * 32) * 8 + h] = e[q];
        if (lane == 0) smf[(SUM_B >> 2) + h] = sum + 1e-10f;
    }
    __syncthreads();

    // ---- phase 3: LN apply + weighted contraction over this warp's rows ----
    {
        float psum[16];
#pragma unroll
        for (int i = 0; i < 16; i++) psum[i] = 0.f;
#pragma unroll
        for (int mt = 0; mt < 2; mt++)
#pragma unroll
            for (int e = 0; e < 2; e++) {
                int r = r0base + mt * 16 + e * 8;
                int qb = e * 2;
                float mu = smf[(MU_B >> 2) + r];
                float rs = smf[(RS_B >> 2) + r];
                float a0 = smf[(LG_B >> 2) + r * 8 + wn * 2];
                float a1 = smf[(LG_B >> 2) + r * 8 + wn * 2 + 1];
#pragma unroll
                for (int nt = 0; nt < 8; nt++) {
                    int col = wn * 64 + nt * 8 + 2 * qcol;
                    float g0 = smf[(G_B >> 2) + col],  g1 = smf[(G_B >> 2) + col + 1];
                    float e0 = smf[(BE_B >> 2) + col], e1 = smf[(BE_B >> 2) + col + 1];
                    float of0 = g0 * ((acc[mt][nt][qb] - mu) * rs) + e0;
                    float of1 = g1 * ((acc[mt][nt][qb + 1] - mu) * rs) + e1;
                    float a = (nt < 4) ? a0 : a1;
                    psum[nt * 2]     += a * of0;
                    psum[nt * 2 + 1] += a * of1;
                }
            }
        // reduce over qrow lanes (bits 2..4 of lane)
#pragma unroll
        for (int i = 0; i < 16; i++) {
            psum[i] += __shfl_xor_sync(0xffffffffu, psum[i], 4);
            psum[i] += __shfl_xor_sync(0xffffffffu, psum[i], 8);
            psum[i] += __shfl_xor_sync(0xffffffffu, psum[i], 16);
        }
        if (qrow == 0) {
#pragma unroll
            for (int nt = 0; nt < 8; nt++) {
                int col = wn * 64 + nt * 8 + 2 * qcol;
                smf[(CP_B >> 2) + wm * 256 + col]     = psum[nt * 2];
                smf[(CP_B >> 2) + wm * 256 + col + 1] = psum[nt * 2 + 1];
            }
        }
    }
    __syncthreads();

    if (t < 256) {
        int col = t, h = col >> 5;
        float v = smf[(CP_B >> 2) + col] + smf[(CP_B >> 2) + 256 + col]
                + smf[(CP_B >> 2) + 512 + col] + smf[(CP_B >> 2) + 768 + col];
        out[(size_t)(b * Ld + x) * HFd + col] = v / smf[(SUM_B >> 2) + h];
    }
}

// ---------------------------------------------------------------------------
// NormAndLinear for lig/rec: block = 16 rows, thread = output column.
// ---------------------------------------------------------------------------
__global__ void __launch_bounds__(256)
k_normlin(const float* __restrict__ X, const float* __restrict__ W,
          const float* __restrict__ bias, const float* __restrict__ g,
          const float* __restrict__ be, float* __restrict__ out)
{
    __shared__ float sX[16 * 260];
    __shared__ float sH[16 * 260];
    const int t = threadIdx.x;
    const int row0 = blockIdx.x * 16;

#pragma unroll
    for (int s = 0; s < 4; s++) {
        int m = t + s * 256;
        int r = m >> 6, c = (m & 63) * 4;
        float4 v = *(const float4*)(X + (size_t)(row0 + r) * Fd + c);
        sX[r * 260 + c + 0] = lrelu(v.x);
        sX[r * 260 + c + 1] = lrelu(v.y);
        sX[r * 260 + c + 2] = lrelu(v.z);
        sX[r * 260 + c + 3] = lrelu(v.w);
    }
    __syncthreads();

    float acc[16];
#pragma unroll
    for (int r = 0; r < 16; r++) acc[r] = 0.f;
    const int n = t;
    for (int k0 = 0; k0 < 256; k0 += 8) {
        float wv[8];
        *(float4*)&wv[0] = *(const float4*)(W + (size_t)n * Fd + k0);
        *(float4*)&wv[4] = *(const float4*)(W + (size_t)n * Fd + k0 + 4);
#pragma unroll
        for (int r = 0; r < 16; r++) {
            float a[8];
            *(float4*)&a[0] = *(const float4*)&sX[r * 260 + k0];
            *(float4*)&a[4] = *(const float4*)&sX[r * 260 + k0 + 4];
#pragma unroll
            for (int kk = 0; kk < 8; kk++) acc[r] += a[kk] * wv[kk];
        }
    }
    float bv = bias[n];
#pragma unroll
    for (int r = 0; r < 16; r++) sH[r * 260 + n] = acc[r] + bv;
    __syncthreads();

    const int warp = t >> 5, lane = t & 31;
#pragma unroll
    for (int rr = 0; rr < 2; rr++) {
        int r = warp * 2 + rr;
        float vals[8], s = 0.f;
#pragma unroll
        for (int q = 0; q < 8; q++) { vals[q] = sH[r * 260 + lane + q * 32]; s += vals[q]; }
#pragma unroll
        for (int o = 16; o; o >>= 1) s += __shfl_xor_sync(0xffffffffu, s, o);
        float mu = s * (1.f / 256.f);
        float vs = 0.f;
#pragma unroll
        for (int q = 0; q < 8; q++) { float d = vals[q] - mu; vs += d * d; }
#pragma unroll
        for (int o = 16; o; o >>= 1) vs += __shfl_xor_sync(0xffffffffu, vs, o);
        float rstd = rsqrtf(vs * (1.f / 256.f) + 1e-5f);
#pragma unroll
        for (int q = 0; q < 8; q++) {
            int c = lane + q * 32;
            out[(size_t)(row0 + r) * 256 + c] = g[c] * ((vals[q] - mu) * rstd) + be[c];
        }
    }
}

// ---------------------------------------------------------------------------
// Expand: out[b,x,y,h] = sum_f xf[b,x,h,f]*yf[b,y,h,f]
// Block tile: 16 x-rows, 64 y-rows; each thread 2 y.
// ---------------------------------------------------------------------------
constexpr int EXP_SMEM_FLOATS = 16 * 8 * 36 + 64 * 8 * 36;
constexpr int EXP_SMEM_BYTES  = EXP_SMEM_FLOATS * 4;

__global__ void __launch_bounds__(256)
k_expand(float* __restrict__ out)
{
    extern __shared__ float es[];
    float* sX = es;
    float* sY = es + 16 * 8 * 36;
    const int t = threadIdx.x;
    const int x0 = blockIdx.x * 16, y0 = blockIdx.y * 64, b = blockIdx.z;

#pragma unroll
    for (int s = 0; s < 4; s++) {
        int m = t + s * 256;
        int xi = m >> 6, c = (m & 63) * 4;
        int h = c >> 5, f = c & 31;
        float4 v = *(const float4*)(g_xf + (size_t)(b * Ld + x0 + xi) * HFd + c);
        float* d = &sX[(xi * 8 + h) * 36 + f];
        d[0] = v.x; d[1] = v.y; d[2] = v.z; d[3] = v.w;
    }
#pragma unroll
    for (int s = 0; s < 16; s++) {
        int m = t + s * 256;
        int yi = m >> 6, c = (m & 63) * 4;
        int h = c >> 5, f = c & 31;
        float4 v = *(const float4*)(g_yf + (size_t)(b * Rd + y0 + yi) * HFd + c);
        float* d = &sY[(yi * 8 + h) * 36 + f];
        d[0] = v.x; d[1] = v.y; d[2] = v.z; d[3] = v.w;
    }
    __syncthreads();

    const int h = t & 7, yy = t >> 3;
    float acc[2][16];
#pragma unroll
    for (int p = 0; p < 2; p++)
#pragma unroll
        for (int xi = 0; xi < 16; xi++) acc[p][xi] = 0.f;
#pragma unroll
    for (int f4 = 0; f4 < 32; f4 += 4) {
        float4 yv0 = *(const float4*)&sY[(yy * 8 + h) * 36 + f4];
        float4 yv1 = *(const float4*)&sY[((yy + 32) * 8 + h) * 36 + f4];
#pragma unroll
        for (int xi = 0; xi < 16; xi++) {
            float4 xv = *(const float4*)&sX[(xi * 8 + h) * 36 + f4];
            acc[0][xi] += xv.x * yv0.x + xv.y * yv0.y + xv.z * yv0.z + xv.w * yv0.w;
            acc[1][xi] += xv.x * yv1.x + xv.y * yv1.y + xv.z * yv1.z + xv.w * yv1.w;
        }
    }
#pragma unroll
    for (int xi = 0; xi < 16; xi++) {
        out[((size_t)(b * Ld + x0 + xi) * Rd + y0 + yy) * Hd + h]      = acc[0][xi];
        out[((size_t)(b * Ld + x0 + xi) * Rd + y0 + yy + 32) * Hd + h] = acc[1][xi];
    }
}

// ---------------------------------------------------------------------------
// Zero llf region
// ---------------------------------------------------------------------------
__global__ void __launch_bounds__(256)
k_zero(float4* __restrict__ p)
{
    size_t base = ((size_t)blockIdx.x * 256 + threadIdx.x) * 4;
#pragma unroll
    for (int i = 0; i < 4; i++) p[base + i] = make_float4(0.f, 0.f, 0.f, 0.f);
}

// ---------------------------------------------------------------------------
// Edge: gather -> linear(2F->FE) -> lrelu -> atomic scatter into llf.
// ---------------------------------------------------------------------------
constexpr int WET_LD = 68;
constexpr int EDGE_SMEM_FLOATS = 512 * WET_LD + 32 * 512;
constexpr int EDGE_SMEM_BYTES  = EDGE_SMEM_FLOATS * 4;

__global__ void __launch_bounds__(256, 1)
k_edge(const float* __restrict__ lig, const int* __restrict__ eb,
       const int* __restrict__ es, const int* __restrict__ ed,
       const float* __restrict__ We, const float* __restrict__ be,
       float* __restrict__ llf)
{
    extern __shared__ float sm[];
    float* sWeT = sm;
    float* sEF  = sm + 512 * WET_LD;
    const int t = threadIdx.x;

#pragma unroll 8
    for (int s = 0; s < 128; s++) {
        int m = t + s * 256;
        int k = m & 511, o = m >> 9;
        sWeT[k * WET_LD + o] = We[o * 512 + k];
    }

    const int to = t & 7;
    const int te = t >> 3;
    float bev[8];
#pragma unroll
    for (int c = 0; c < 8; c++) bev[c] = be[to * 8 + c];

    for (int iter = 0; iter < 4; iter++) {
        __syncthreads();
#pragma unroll
        for (int s = 0; s < 16; s++) {
            int m = t + s * 256;
            int eg = m >> 7, kq = m & 127;
            int k = kq * 4;
            int e = blockIdx.x * 128 + iter * 32 + eg;
            int bb = eb[e];
            int row = (k < 256) ? es[e] : ed[e];
            int col = (k < 256) ? k : (k - 256);
            float4 v = *(const float4*)(lig + (size_t)(bb * Ld + row) * Fd + col);
            float* d = &sEF[eg * 512 + k];
            d[0] = v.x; d[1] = v.y; d[2] = v.z; d[3] = v.w;
        }
        __syncthreads();

        float acc[8];
#pragma unroll
        for (int c = 0; c < 8; c++) acc[c] = 0.f;
#pragma unroll 4
        for (int k = 0; k < 512; k++) {
            float a = sEF[te * 512 + k];
            float4 w0 = *(const float4*)&sWeT[k * WET_LD + to * 8];
            float4 w1 = *(const float4*)&sWeT[k * WET_LD + to * 8 + 4];
            acc[0] += a * w0.x; acc[1] += a * w0.y; acc[2] += a * w0.z; acc[3] += a * w0.w;
            acc[4] += a * w1.x; acc[5] += a * w1.y; acc[6] += a * w1.z; acc[7] += a * w1.w;
        }
        int e = blockIdx.x * 128 + iter * 32 + te;
        int bb = eb[e], ss = es[e], dd = ed[e];
        float* dst = llf + ((size_t)(bb * Ld + ss) * Ld + dd) * FEd + to * 8;
#pragma unroll
        for (int c = 0; c < 8; c++) atomicAdd(dst + c, lrelu(acc[c] + bev[c]));
    }
}

// ---------------------------------------------------------------------------
// Launch
// ---------------------------------------------------------------------------
extern "C" void kernel_launch(void* const* d_in, const int* in_sizes, int n_in,
                              void* d_out, int out_size)
{
    const float*    ll   = (const float*)d_in[0];
    const float*    lig  = (const float*)d_in[1];
    const float*    rec  = (const float*)d_in[2];
    const unsigned* mask = (const unsigned*)d_in[3];
    const int*      eb   = (const int*)d_in[4];
    const int*      es   = (const int*)d_in[5];
    const int*      ed   = (const int*)d_in[6];
    const float*    Wc   = (const float*)d_in[7];
    const float*    bc   = (const float*)d_in[8];
    const float*    gcc  = (const float*)d_in[9];
    const float*    bec  = (const float*)d_in[10];
    const float*    Wca  = (const float*)d_in[11];
    const float*    bca  = (const float*)d_in[12];
    const float*    Wex  = (const float*)d_in[13];
    const float*    bex  = (const float*)d_in[14];
    const float*    gex  = (const float*)d_in[15];
    const float*    beex = (const float*)d_in[16];
    const float*    Wey  = (const float*)d_in[17];
    const float*    bey  = (const float*)d_in[18];
    const float*    gey  = (const float*)d_in[19];
    const float*    beey = (const float*)d_in[20];
    const float*    We   = (const float*)d_in[21];
    const float*    be   = (const float*)d_in[22];

    float* out = (float*)d_out;
    float* oC = out;
    float* oE = out + (size_t)Bd * Ld * HFd;
    float* oL = oE + (size_t)Bd * Ld * Rd * Hd;

    cudaFuncSetAttribute(k_contract, cudaFuncAttributeMaxDynamicSharedMemorySize, SM_CONTRACT_BYTES);
    cudaFuncSetAttribute(k_edge, cudaFuncAttributeMaxDynamicSharedMemorySize, EDGE_SMEM_BYTES);
    cudaFuncSetAttribute(k_expand, cudaFuncAttributeMaxDynamicSharedMemorySize, EXP_SMEM_BYTES);

    void* pxf = nullptr; void* pyf = nullptr;
    cudaGetSymbolAddress(&pxf, g_xf);
    cudaGetSymbolAddress(&pyf, g_yf);

    // prep half weights, then contract (fp16 mma tensor cores)
    k_prep<<<264, 256>>>(Wc, Wca);
    k_contract<<<dim3(128, 16), 512, SM_CONTRACT_BYTES>>>(ll, mask, bc, gcc, bec, bca, oC);

    // expand branch
    k_normlin<<<128, 256>>>(lig, Wex, bex, gex, beex, (float*)pxf);
    k_normlin<<<512, 256>>>(rec, Wey, bey, gey, beey, (float*)pyf);
    k_expand<<<dim3(8, 8, 16), 256, EXP_SMEM_BYTES>>>(oE);

    // edge branch
    k_zero<<<4096, 256>>>((float4*)oL);
    k_edge<<<128, 256, EDGE_SMEM_BYTES>>>(lig, eb, es, ed, We, be, oL);
}

// round 8
// speedup vs baseline: 2.9025x; 1.1148x over previous
#include <cuda_runtime.h>
#include <cuda_fp16.h>
#include <cstdint>
#include <cstddef>

// ---------------------------------------------------------------------------
// Problem dims
// ---------------------------------------------------------------------------
constexpr int Bd = 16, Ld = 128, Rd = 512, Fd = 256, Hd = 8, FHd = 32, FEd = 64, Ed = 16384;
constexpr int HFd = 256;

__device__ __forceinline__ float lrelu(float x) { return x > 0.f ? x : 0.01f * x; }

// Scratch (device globals: allocation-free)
__device__ float  g_xf[Bd * Ld * HFd];     // 2 MB
__device__ float  g_yf[Bd * Rd * HFd];     // 8 MB
__device__ __half g_Whc[264 * 256];        // Wc||Wca in half, [n][k]
__device__ __half g_Whx[256 * 256];        // Wex half
__device__ __half g_Why[256 * 256];        // Wey half

// fp16 m16n8k16 mma, f32 accum
__device__ __forceinline__ void mma_f16(float* c, uint32_t a0, uint32_t a1, uint32_t a2, uint32_t a3,
                                        uint32_t b0, uint32_t b1)
{
    asm volatile(
        "mma.sync.aligned.m16n8k16.row.col.f32.f16.f16.f32 "
        "{%0,%1,%2,%3}, {%4,%5,%6,%7}, {%8,%9}, {%0,%1,%2,%3};"
        : "+f"(c[0]), "+f"(c[1]), "+f"(c[2]), "+f"(c[3])
        : "r"(a0), "r"(a1), "r"(a2), "r"(a3), "r"(b0), "r"(b1));
}

__device__ __forceinline__ uint32_t smem_u32(const void* p) {
    uint32_t a;
    asm("{ .reg .u64 t; cvta.to.shared.u64 t, %1; cvt.u32.u64 %0, t; }" : "=r"(a) : "l"(p));
    return a;
}

// ---------------------------------------------------------------------------
// Prep: float weights -> half [n][256]
// ---------------------------------------------------------------------------
__global__ void __launch_bounds__(256)
k_prep(const float* __restrict__ W, __half* __restrict__ dst)
{
    int n = blockIdx.x, k = threadIdx.x;
    dst[(size_t)n * 256 + k] = __float2half_rn(W[(size_t)n * 256 + k]);
}

// ---------------------------------------------------------------------------
// Contract kernel. 512 threads, 16 warps (wm = w>>2, wn = w&3).
// A (lrelu->half) and B (Wc||Wca half) BOTH smem-resident; mainloop sync-free.
// Epilogue on registers + small smem tables.
// ---------------------------------------------------------------------------
constexpr uint32_t CSA_B  = 0;          // half [128][264]  row stride 528 B
constexpr uint32_t CSB_B  = 67584;      // half [264][264]  row stride 528 B (256 data)
constexpr uint32_t CLG_B  = 206976;     // f32 [128][8]
constexpr uint32_t CMU_B  = 211072;     // f32 [128]
constexpr uint32_t CRS_B  = 211584;     // f32 [128]
constexpr uint32_t CSP_B  = 212096;     // f32 [128][4]
constexpr uint32_t CSQ_B  = 214144;     // f32 [128][4]
constexpr uint32_t CCP_B  = 216192;     // f32 [4][256]
constexpr uint32_t CG_B   = 220288;     // f32 [256]
constexpr uint32_t CBE_B  = 221312;     // f32 [256]
constexpr uint32_t CBC_B  = 222336;     // f32 [256]
constexpr uint32_t CBCA_B = 223360;     // f32 [8]
constexpr uint32_t CSUM_B = 223392;     // f32 [8]
constexpr int SM_CONTRACT_BYTES = 223424;

__global__ void __launch_bounds__(512, 1)
k_contract(const float* __restrict__ ll, const unsigned* __restrict__ mask,
           const float* __restrict__ bc, const float* __restrict__ gc,
           const float* __restrict__ bec, const float* __restrict__ bca,
           float* __restrict__ out)
{
    extern __shared__ char smc[];
    float* smf = (float*)smc;
    const uint32_t smb = smem_u32(smc);
    const int t = threadIdx.x;
    const int x = blockIdx.x, b = blockIdx.y;
    const int w = t >> 5, lane = t & 31;
    const int wm = w >> 2, wn = w & 3;
    const int qrow = lane >> 2, qcol = lane & 3;
    const int ntmax = (wn == 3) ? 9 : 8;

    // B: 264 rows x 512 data bytes via cp.async (16B granules, 8448 total)
    for (int m = t; m < 8448; m += 512) {
        int n = m >> 5, k16 = m & 31;
        const __half* src = g_Whc + (size_t)n * 256 + k16 * 8;
        uint32_t dst = smb + CSB_B + n * 528 + k16 * 16;
        asm volatile("cp.async.cg.shared.global [%0], [%1], 16;" :: "r"(dst), "l"(src));
    }
    asm volatile("cp.async.commit_group;");

    // constants
    if (t < 256) {
        smf[(CG_B >> 2) + t]  = gc[t];
        smf[(CBE_B >> 2) + t] = bec[t];
        smf[(CBC_B >> 2) + t] = bc[t];
    }
    if (t < 8) smf[(CBCA_B >> 2) + t] = bca[t];

    // stage A (lrelu -> half): 128 x 256, row stride 528 B
    const float* Arow = ll + (size_t)(b * Ld + x) * Ld * Fd;
#pragma unroll
    for (int s = 0; s < 16; s++) {
        int m = t + s * 512;                 // float4 id, 8192 total
        int y = m >> 6, c4 = m & 63;
        float4 v = *(const float4*)(Arow + y * 256 + c4 * 4);
        __half2 h01 = __floats2half2_rn(lrelu(v.x), lrelu(v.y));
        __half2 h23 = __floats2half2_rn(lrelu(v.z), lrelu(v.w));
        uint2 u;
        u.x = *(uint32_t*)&h01; u.y = *(uint32_t*)&h23;
        *(uint2*)(smc + CSA_B + y * 528 + c4 * 8) = u;
    }

    float acc[2][9][4];
#pragma unroll
    for (int mt = 0; mt < 2; mt++)
#pragma unroll
        for (int nt = 0; nt < 9; nt++)
#pragma unroll
            for (int q = 0; q < 4; q++) acc[mt][nt][q] = 0.f;

    asm volatile("cp.async.wait_group 0;");
    __syncthreads();

    const char* saB = smc + CSA_B;
    const char* sbB = smc + CSB_B;
    const int r0base = wm * 32 + qrow;

    // sync-free mainloop: 16 k-steps of 16
#pragma unroll 4
    for (int ks = 0; ks < 16; ks++) {
        const int khw = (ks * 8 + qcol) * 4;     // byte offset of half2 within row
        uint32_t af[2][4];
#pragma unroll
        for (int mt = 0; mt < 2; mt++) {
            const char* base = saB + (r0base + mt * 16) * 528 + khw;
            af[mt][0] = *(const uint32_t*)(base);
            af[mt][1] = *(const uint32_t*)(base + 8 * 528);
            af[mt][2] = *(const uint32_t*)(base + 16);
            af[mt][3] = *(const uint32_t*)(base + 8 * 528 + 16);
        }
        for (int nt = 0; nt < ntmax; nt++) {
            int nbase = (nt < 8) ? (wn * 64 + nt * 8) : 256;
            const char* brow = sbB + (nbase + qrow) * 528 + khw;
            uint32_t b0 = *(const uint32_t*)(brow);
            uint32_t b1 = *(const uint32_t*)(brow + 16);
            mma_f16(acc[0][nt], af[0][0], af[0][1], af[0][2], af[0][3], b0, b1);
            mma_f16(acc[1][nt], af[1][0], af[1][1], af[1][2], af[1][3], b0, b1);
        }
    }

    // ---- epilogue phase 1: bias add, logits out, LN partial sums ----
#pragma unroll
    for (int mt = 0; mt < 2; mt++)
#pragma unroll
        for (int nt = 0; nt < 8; nt++) {
            int col = wn * 64 + nt * 8 + 2 * qcol;
            float b0 = smf[(CBC_B >> 2) + col], b1 = smf[(CBC_B >> 2) + col + 1];
            acc[mt][nt][0] += b0; acc[mt][nt][1] += b1;
            acc[mt][nt][2] += b0; acc[mt][nt][3] += b1;
        }
    if (wn == 3) {
        float ba0 = smf[(CBCA_B >> 2) + 2 * qcol], ba1 = smf[(CBCA_B >> 2) + 2 * qcol + 1];
#pragma unroll
        for (int mt = 0; mt < 2; mt++) {
            int r = r0base + mt * 16;
            smf[(CLG_B >> 2) + r * 8 + 2 * qcol]           = acc[mt][8][0] + ba0;
            smf[(CLG_B >> 2) + r * 8 + 2 * qcol + 1]       = acc[mt][8][1] + ba1;
            smf[(CLG_B >> 2) + (r + 8) * 8 + 2 * qcol]     = acc[mt][8][2] + ba0;
            smf[(CLG_B >> 2) + (r + 8) * 8 + 2 * qcol + 1] = acc[mt][8][3] + ba1;
        }
    }
#pragma unroll
    for (int mt = 0; mt < 2; mt++)
#pragma unroll
        for (int e = 0; e < 2; e++) {
            int r = r0base + mt * 16 + e * 8;
            int qb = e * 2;
            float s = 0.f, sq = 0.f;
#pragma unroll
            for (int nt = 0; nt < 8; nt++) {
                float v0 = acc[mt][nt][qb], v1 = acc[mt][nt][qb + 1];
                s += v0 + v1; sq += v0 * v0 + v1 * v1;
            }
            s  += __shfl_xor_sync(0xffffffffu, s, 1);  s  += __shfl_xor_sync(0xffffffffu, s, 2);
            sq += __shfl_xor_sync(0xffffffffu, sq, 1); sq += __shfl_xor_sync(0xffffffffu, sq, 2);
            if (qcol == 0) {
                smf[(CSP_B >> 2) + r * 4 + wn] = s;
                smf[(CSQ_B >> 2) + r * 4 + wn] = sq;
            }
        }
    __syncthreads();

    // ---- phase 2: row stats + masked softmax ----
    if (t < 128) {
        int r = t;
        float s  = smf[(CSP_B >> 2) + r * 4] + smf[(CSP_B >> 2) + r * 4 + 1]
                 + smf[(CSP_B >> 2) + r * 4 + 2] + smf[(CSP_B >> 2) + r * 4 + 3];
        float sq = smf[(CSQ_B >> 2) + r * 4] + smf[(CSQ_B >> 2) + r * 4 + 1]
                 + smf[(CSQ_B >> 2) + r * 4 + 2] + smf[(CSQ_B >> 2) + r * 4 + 3];
        float mu = s * (1.f / 256.f);
        float var = sq * (1.f / 256.f) - mu * mu;
        smf[(CMU_B >> 2) + r] = mu;
        smf[(CRS_B >> 2) + r] = rsqrtf(var + 1e-5f);
    }
    if (w >= 8) {
        int h = w - 8;
        float lv[4];
#pragma unroll
        for (int q = 0; q < 4; q++) lv[q] = smf[(CLG_B >> 2) + (lane + q * 32) * 8 + h];
        float mx = fmaxf(fmaxf(lv[0], lv[1]), fmaxf(lv[2], lv[3]));
#pragma unroll
        for (int o = 16; o; o >>= 1) mx = fmaxf(mx, __shfl_xor_sync(0xffffffffu, mx, o));
        const unsigned* mrow = mask + (size_t)(b * Ld + x) * Ld;
        float e[4], sum = 0.f;
#pragma unroll
        for (int q = 0; q < 4; q++) {
            int y = lane + q * 32;
            float ee = (mrow[y] != 0u) ? expf(lv[q] - mx) : 0.f;
            e[q] = ee; sum += ee;
        }
#pragma unroll
        for (int o = 16; o; o >>= 1) sum += __shfl_xor_sync(0xffffffffu, sum, o);
#pragma unroll
        for (int q = 0; q < 4; q++) smf[(CLG_B >> 2) + (lane + q * 32) * 8 + h] = e[q];
        if (lane == 0) smf[(CSUM_B >> 2) + h] = sum + 1e-10f;
    }
    __syncthreads();

    // ---- phase 3: LN apply + weighted contraction ----
    {
        float psum[16];
#pragma unroll
        for (int i = 0; i < 16; i++) psum[i] = 0.f;
#pragma unroll
        for (int mt = 0; mt < 2; mt++)
#pragma unroll
            for (int e = 0; e < 2; e++) {
                int r = r0base + mt * 16 + e * 8;
                int qb = e * 2;
                float mu = smf[(CMU_B >> 2) + r];
                float rs = smf[(CRS_B >> 2) + r];
                float a0 = smf[(CLG_B >> 2) + r * 8 + wn * 2];
                float a1 = smf[(CLG_B >> 2) + r * 8 + wn * 2 + 1];
#pragma unroll
                for (int nt = 0; nt < 8; nt++) {
                    int col = wn * 64 + nt * 8 + 2 * qcol;
                    float g0 = smf[(CG_B >> 2) + col],  g1 = smf[(CG_B >> 2) + col + 1];
                    float e0 = smf[(CBE_B >> 2) + col], e1 = smf[(CBE_B >> 2) + col + 1];
                    float of0 = g0 * ((acc[mt][nt][qb] - mu) * rs) + e0;
                    float of1 = g1 * ((acc[mt][nt][qb + 1] - mu) * rs) + e1;
                    float a = (nt < 4) ? a0 : a1;
                    psum[nt * 2]     += a * of0;
                    psum[nt * 2 + 1] += a * of1;
                }
            }
#pragma unroll
        for (int i = 0; i < 16; i++) {
            psum[i] += __shfl_xor_sync(0xffffffffu, psum[i], 4);
            psum[i] += __shfl_xor_sync(0xffffffffu, psum[i], 8);
            psum[i] += __shfl_xor_sync(0xffffffffu, psum[i], 16);
        }
        if (qrow == 0) {
#pragma unroll
            for (int nt = 0; nt < 8; nt++) {
                int col = wn * 64 + nt * 8 + 2 * qcol;
                smf[(CCP_B >> 2) + wm * 256 + col]     = psum[nt * 2];
                smf[(CCP_B >> 2) + wm * 256 + col + 1] = psum[nt * 2 + 1];
            }
        }
    }
    __syncthreads();

    if (t < 256) {
        int col = t, h = col >> 5;
        float v = smf[(CCP_B >> 2) + col] + smf[(CCP_B >> 2) + 256 + col]
                + smf[(CCP_B >> 2) + 512 + col] + smf[(CCP_B >> 2) + 768 + col];
        out[(size_t)(b * Ld + x) * HFd + col] = v / smf[(CSUM_B >> 2) + h];
    }
}

// ---------------------------------------------------------------------------
// NormAndLinear via fp16 mma: 128 rows per CTA, N=256, K=256, W resident.
// ---------------------------------------------------------------------------
constexpr uint32_t NSA_B = 0;          // half [128][264]
constexpr uint32_t NSB_B = 67584;      // half [256][264]
constexpr uint32_t NMU_B = 202752;     // f32 [128]
constexpr uint32_t NRS_B = 203264;     // f32 [128]
constexpr uint32_t NSP_B = 203776;     // f32 [128][4]
constexpr uint32_t NSQ_B = 205824;     // f32 [128][4]
constexpr uint32_t NG_B  = 207872;     // f32 [256]
constexpr uint32_t NBE_B = 208896;     // f32 [256]
constexpr uint32_t NBC_B = 209920;     // f32 [256]
constexpr int SM_NORMLIN_BYTES = 210944;

__global__ void __launch_bounds__(512, 1)
k_normlin_h(const float* __restrict__ X, const __half* __restrict__ Wh,
            const float* __restrict__ bias, const float* __restrict__ g,
            const float* __restrict__ be, float* __restrict__ out)
{
    extern __shared__ char smc[];
    float* smf = (float*)smc;
    const uint32_t smb = smem_u32(smc);
    const int t = threadIdx.x;
    const int row0 = blockIdx.x * 128;
    const int w = t >> 5, lane = t & 31;
    const int wm = w >> 2, wn = w & 3;
    const int qrow = lane >> 2, qcol = lane & 3;

    // W resident: 256 rows x 512B
    for (int m = t; m < 8192; m += 512) {
        int n = m >> 5, k16 = m & 31;
        const __half* src = Wh + (size_t)n * 256 + k16 * 8;
        uint32_t dst = smb + NSB_B + n * 528 + k16 * 16;
        asm volatile("cp.async.cg.shared.global [%0], [%1], 16;" :: "r"(dst), "l"(src));
    }
    asm volatile("cp.async.commit_group;");

    if (t < 256) {
        smf[(NG_B >> 2) + t]  = g[t];
        smf[(NBE_B >> 2) + t] = be[t];
        smf[(NBC_B >> 2) + t] = bias[t];
    }

    // stage X rows (lrelu -> half)
#pragma unroll
    for (int s = 0; s < 16; s++) {
        int m = t + s * 512;
        int y = m >> 6, c4 = m & 63;
        float4 v = *(const float4*)(X + (size_t)(row0 + y) * Fd + c4 * 4);
        __half2 h01 = __floats2half2_rn(lrelu(v.x), lrelu(v.y));
        __half2 h23 = __floats2half2_rn(lrelu(v.z), lrelu(v.w));
        uint2 u;
        u.x = *(uint32_t*)&h01; u.y = *(uint32_t*)&h23;
        *(uint2*)(smc + NSA_B + y * 528 + c4 * 8) = u;
    }

    float acc[2][8][4];
#pragma unroll
    for (int mt = 0; mt < 2; mt++)
#pragma unroll
        for (int nt = 0; nt < 8; nt++)
#pragma unroll
            for (int q = 0; q < 4; q++) acc[mt][nt][q] = 0.f;

    asm volatile("cp.async.wait_group 0;");
    __syncthreads();

    const char* saB = smc + NSA_B;
    const char* sbB = smc + NSB_B;
    const int r0base = wm * 32 + qrow;

#pragma unroll 4
    for (int ks = 0; ks < 16; ks++) {
        const int khw = (ks * 8 + qcol) * 4;
        uint32_t af[2][4];
#pragma unroll
        for (int mt = 0; mt < 2; mt++) {
            const char* base = saB + (r0base + mt * 16) * 528 + khw;
            af[mt][0] = *(const uint32_t*)(base);
            af[mt][1] = *(const uint32_t*)(base + 8 * 528);
            af[mt][2] = *(const uint32_t*)(base + 16);
            af[mt][3] = *(const uint32_t*)(base + 8 * 528 + 16);
        }
#pragma unroll
        for (int nt = 0; nt < 8; nt++) {
            int nbase = wn * 64 + nt * 8;
            const char* brow = sbB + (nbase + qrow) * 528 + khw;
            uint32_t b0 = *(const uint32_t*)(brow);
            uint32_t b1 = *(const uint32_t*)(brow + 16);
            mma_f16(acc[0][nt], af[0][0], af[0][1], af[0][2], af[0][3], b0, b1);
            mma_f16(acc[1][nt], af[1][0], af[1][1], af[1][2], af[1][3], b0, b1);
        }
    }

    // bias + LN partials
#pragma unroll
    for (int mt = 0; mt < 2; mt++)
#pragma unroll
        for (int nt = 0; nt < 8; nt++) {
            int col = wn * 64 + nt * 8 + 2 * qcol;
            float b0 = smf[(NBC_B >> 2) + col], b1 = smf[(NBC_B >> 2) + col + 1];
            acc[mt][nt][0] += b0; acc[mt][nt][1] += b1;
            acc[mt][nt][2] += b0; acc[mt][nt][3] += b1;
        }
#pragma unroll
    for (int mt = 0; mt < 2; mt++)
#pragma unroll
        for (int e = 0; e < 2; e++) {
            int r = r0base + mt * 16 + e * 8;
            int qb = e * 2;
            float s = 0.f, sq = 0.f;
#pragma unroll
            for (int nt = 0; nt < 8; nt++) {
                float v0 = acc[mt][nt][qb], v1 = acc[mt][nt][qb + 1];
                s += v0 + v1; sq += v0 * v0 + v1 * v1;
            }
            s  += __shfl_xor_sync(0xffffffffu, s, 1);  s  += __shfl_xor_sync(0xffffffffu, s, 2);
            sq += __shfl_xor_sync(0xffffffffu, sq, 1); sq += __shfl_xor_sync(0xffffffffu, sq, 2);
            if (qcol == 0) {
                smf[(NSP_B >> 2) + r * 4 + wn] = s;
                smf[(NSQ_B >> 2) + r * 4 + wn] = sq;
            }
        }
    __syncthreads();

    if (t < 128) {
        int r = t;
        float s  = smf[(NSP_B >> 2) + r * 4] + smf[(NSP_B >> 2) + r * 4 + 1]
                 + smf[(NSP_B >> 2) + r * 4 + 2] + smf[(NSP_B >> 2) + r * 4 + 3];
        float sq = smf[(NSQ_B >> 2) + r * 4] + smf[(NSQ_B >> 2) + r * 4 + 1]
                 + smf[(NSQ_B >> 2) + r * 4 + 2] + smf[(NSQ_B >> 2) + r * 4 + 3];
        float mu = s * (1.f / 256.f);
        float var = sq * (1.f / 256.f) - mu * mu;
        smf[(NMU_B >> 2) + r] = mu;
        smf[(NRS_B >> 2) + r] = rsqrtf(var + 1e-5f);
    }
    __syncthreads();

    // LN apply + write out
#pragma unroll
    for (int mt = 0; mt < 2; mt++)
#pragma unroll
        for (int e = 0; e < 2; e++) {
            int r = r0base + mt * 16 + e * 8;
            int qb = e * 2;
            float mu = smf[(NMU_B >> 2) + r];
            float rs = smf[(NRS_B >> 2) + r];
            float* orow = out + (size_t)(row0 + r) * 256;
#pragma unroll
            for (int nt = 0; nt < 8; nt++) {
                int col = wn * 64 + nt * 8 + 2 * qcol;
                float g0 = smf[(NG_B >> 2) + col],  g1 = smf[(NG_B >> 2) + col + 1];
                float e0 = smf[(NBE_B >> 2) + col], e1 = smf[(NBE_B >> 2) + col + 1];
                float2 o;
                o.x = g0 * ((acc[mt][nt][qb] - mu) * rs) + e0;
                o.y = g1 * ((acc[mt][nt][qb + 1] - mu) * rs) + e1;
                *(float2*)(orow + col) = o;
            }
        }
}

// ---------------------------------------------------------------------------
// Expand: out[b,x,y,h] = sum_f xf[b,x,h,f]*yf[b,y,h,f]
// ---------------------------------------------------------------------------
constexpr int EXP_SMEM_FLOATS = 16 * 8 * 36 + 64 * 8 * 36;
constexpr int EXP_SMEM_BYTES  = EXP_SMEM_FLOATS * 4;

__global__ void __launch_bounds__(256)
k_expand(float* __restrict__ out)
{
    extern __shared__ float es[];
    float* sX = es;
    float* sY = es + 16 * 8 * 36;
    const int t = threadIdx.x;
    const int x0 = blockIdx.x * 16, y0 = blockIdx.y * 64, b = blockIdx.z;

#pragma unroll
    for (int s = 0; s < 4; s++) {
        int m = t + s * 256;
        int xi = m >> 6, c = (m & 63) * 4;
        int h = c >> 5, f = c & 31;
        float4 v = *(const float4*)(g_xf + (size_t)(b * Ld + x0 + xi) * HFd + c);
        float* d = &sX[(xi * 8 + h) * 36 + f];
        d[0] = v.x; d[1] = v.y; d[2] = v.z; d[3] = v.w;
    }
#pragma unroll
    for (int s = 0; s < 16; s++) {
        int m = t + s * 256;
        int yi = m >> 6, c = (m & 63) * 4;
        int h = c >> 5, f = c & 31;
        float4 v = *(const float4*)(g_yf + (size_t)(b * Rd + y0 + yi) * HFd + c);
        float* d = &sY[(yi * 8 + h) * 36 + f];
        d[0] = v.x; d[1] = v.y; d[2] = v.z; d[3] = v.w;
    }
    __syncthreads();

    const int h = t & 7, yy = t >> 3;
    float acc[2][16];
#pragma unroll
    for (int p = 0; p < 2; p++)
#pragma unroll
        for (int xi = 0; xi < 16; xi++) acc[p][xi] = 0.f;
#pragma unroll
    for (int f4 = 0; f4 < 32; f4 += 4) {
        float4 yv0 = *(const float4*)&sY[(yy * 8 + h) * 36 + f4];
        float4 yv1 = *(const float4*)&sY[((yy + 32) * 8 + h) * 36 + f4];
#pragma unroll
        for (int xi = 0; xi < 16; xi++) {
            float4 xv = *(const float4*)&sX[(xi * 8 + h) * 36 + f4];
            acc[0][xi] += xv.x * yv0.x + xv.y * yv0.y + xv.z * yv0.z + xv.w * yv0.w;
            acc[1][xi] += xv.x * yv1.x + xv.y * yv1.y + xv.z * yv1.z + xv.w * yv1.w;
        }
    }
#pragma unroll
    for (int xi = 0; xi < 16; xi++) {
        out[((size_t)(b * Ld + x0 + xi) * Rd + y0 + yy) * Hd + h]      = acc[0][xi];
        out[((size_t)(b * Ld + x0 + xi) * Rd + y0 + yy + 32) * Hd + h] = acc[1][xi];
    }
}

// ---------------------------------------------------------------------------
// Zero llf region
// ---------------------------------------------------------------------------
__global__ void __launch_bounds__(256)
k_zero(float4* __restrict__ p)
{
    size_t base = ((size_t)blockIdx.x * 256 + threadIdx.x) * 4;
#pragma unroll
    for (int i = 0; i < 4; i++) p[base + i] = make_float4(0.f, 0.f, 0.f, 0.f);
}

// ---------------------------------------------------------------------------
// Edge: gather -> linear(2F->FE) -> lrelu -> atomic scatter into llf.
// ---------------------------------------------------------------------------
constexpr int WET_LD = 68;
constexpr int EDGE_SMEM_FLOATS = 512 * WET_LD + 32 * 512;
constexpr int EDGE_SMEM_BYTES  = EDGE_SMEM_FLOATS * 4;

__global__ void __launch_bounds__(256, 1)
k_edge(const float* __restrict__ lig, const int* __restrict__ eb,
       const int* __restrict__ es, const int* __restrict__ ed,
       const float* __restrict__ We, const float* __restrict__ be,
       float* __restrict__ llf)
{
    extern __shared__ float sm[];
    float* sWeT = sm;
    float* sEF  = sm + 512 * WET_LD;
    const int t = threadIdx.x;

#pragma unroll 8
    for (int s = 0; s < 128; s++) {
        int m = t + s * 256;
        int k = m & 511, o = m >> 9;
        sWeT[k * WET_LD + o] = We[o * 512 + k];
    }

    const int to = t & 7;
    const int te = t >> 3;
    float bev[8];
#pragma unroll
    for (int c = 0; c < 8; c++) bev[c] = be[to * 8 + c];

    for (int iter = 0; iter < 4; iter++) {
        __syncthreads();
#pragma unroll
        for (int s = 0; s < 16; s++) {
            int m = t + s * 256;
            int eg = m >> 7, kq = m & 127;
            int k = kq * 4;
            int e = blockIdx.x * 128 + iter * 32 + eg;
            int bb = eb[e];
            int row = (k < 256) ? es[e] : ed[e];
            int col = (k < 256) ? k : (k - 256);
            float4 v = *(const float4*)(lig + (size_t)(bb * Ld + row) * Fd + col);
            float* d = &sEF[eg * 512 + k];
            d[0] = v.x; d[1] = v.y; d[2] = v.z; d[3] = v.w;
        }
        __syncthreads();

        float acc[8];
#pragma unroll
        for (int c = 0; c < 8; c++) acc[c] = 0.f;
#pragma unroll 4
        for (int k = 0; k < 512; k++) {
            float a = sEF[te * 512 + k];
            float4 w0 = *(const float4*)&sWeT[k * WET_LD + to * 8];
            float4 w1 = *(const float4*)&sWeT[k * WET_LD + to * 8 + 4];
            acc[0] += a * w0.x; acc[1] += a * w0.y; acc[2] += a * w0.z; acc[3] += a * w0.w;
            acc[4] += a * w1.x; acc[5] += a * w1.y; acc[6] += a * w1.z; acc[7] += a * w1.w;
        }
        int e = blockIdx.x * 128 + iter * 32 + te;
        int bb = eb[e], ss = es[e], dd = ed[e];
        float* dst = llf + ((size_t)(bb * Ld + ss) * Ld + dd) * FEd + to * 8;
#pragma unroll
        for (int c = 0; c < 8; c++) atomicAdd(dst + c, lrelu(acc[c] + bev[c]));
    }
}

// ---------------------------------------------------------------------------
// Launch
// ---------------------------------------------------------------------------
extern "C" void kernel_launch(void* const* d_in, const int* in_sizes, int n_in,
                              void* d_out, int out_size)
{
    const float*    ll   = (const float*)d_in[0];
    const float*    lig  = (const float*)d_in[1];
    const float*    rec  = (const float*)d_in[2];
    const unsigned* mask = (const unsigned*)d_in[3];
    const int*      eb   = (const int*)d_in[4];
    const int*      es   = (const int*)d_in[5];
    const int*      ed   = (const int*)d_in[6];
    const float*    Wc   = (const float*)d_in[7];
    const float*    bc   = (const float*)d_in[8];
    const float*    gcc  = (const float*)d_in[9];
    const float*    bec  = (const float*)d_in[10];
    const float*    Wca  = (const float*)d_in[11];
    const float*    bca  = (const float*)d_in[12];
    const float*    Wex  = (const float*)d_in[13];
    const float*    bex  = (const float*)d_in[14];
    const float*    gex  = (const float*)d_in[15];
    const float*    beex = (const float*)d_in[16];
    const float*    Wey  = (const float*)d_in[17];
    const float*    bey  = (const float*)d_in[18];
    const float*    gey  = (const float*)d_in[19];
    const float*    beey = (const float*)d_in[20];
    const float*    We   = (const float*)d_in[21];
    const float*    be   = (const float*)d_in[22];

    float* out = (float*)d_out;
    float* oC = out;
    float* oE = out + (size_t)Bd * Ld * HFd;
    float* oL = oE + (size_t)Bd * Ld * Rd * Hd;

    cudaFuncSetAttribute(k_contract, cudaFuncAttributeMaxDynamicSharedMemorySize, SM_CONTRACT_BYTES);
    cudaFuncSetAttribute(k_normlin_h, cudaFuncAttributeMaxDynamicSharedMemorySize, SM_NORMLIN_BYTES);
    cudaFuncSetAttribute(k_edge, cudaFuncAttributeMaxDynamicSharedMemorySize, EDGE_SMEM_BYTES);
    cudaFuncSetAttribute(k_expand, cudaFuncAttributeMaxDynamicSharedMemorySize, EXP_SMEM_BYTES);

    void* pxf = nullptr; void* pyf = nullptr; void* pWhc = nullptr; void* pWhx = nullptr; void* pWhy = nullptr;
    cudaGetSymbolAddress(&pxf, g_xf);
    cudaGetSymbolAddress(&pyf, g_yf);
    cudaGetSymbolAddress(&pWhc, g_Whc);
    cudaGetSymbolAddress(&pWhx, g_Whx);
    cudaGetSymbolAddress(&pWhy, g_Why);

    // prep half weights
    k_prep<<<256, 256>>>(Wc, (__half*)pWhc);
    k_prep<<<8, 256>>>(Wca, (__half*)pWhc + 256 * 256);
    k_prep<<<256, 256>>>(Wex, (__half*)pWhx);
    k_prep<<<256, 256>>>(Wey, (__half*)pWhy);

    // contract (fp16 mma, B-resident, sync-free mainloop)
    k_contract<<<dim3(128, 16), 512, SM_CONTRACT_BYTES>>>(ll, mask, bc, gcc, bec, bca, oC);

    // expand branch
    k_normlin_h<<<16, 512, SM_NORMLIN_BYTES>>>(lig, (const __half*)pWhx, bex, gex, beex, (float*)pxf);
    k_normlin_h<<<64, 512, SM_NORMLIN_BYTES>>>(rec, (const __half*)pWhy, bey, gey, beey, (float*)pyf);
    k_expand<<<dim3(8, 8, 16), 256, EXP_SMEM_BYTES>>>(oE);

    // edge branch
    k_zero<<<4096, 256>>>((float4*)oL);
    k_edge<<<128, 256, EDGE_SMEM_BYTES>>>(lig, eb, es, ed, We, be, oL);
}

// round 10
// speedup vs baseline: 3.1515x; 1.0858x over previous
#include <cuda_runtime.h>
#include <cuda_fp16.h>
#include <cstdint>
#include <cstddef>

// ---------------------------------------------------------------------------
// Problem dims
// ---------------------------------------------------------------------------
constexpr int Bd = 16, Ld = 128, Rd = 512, Fd = 256, Hd = 8, FHd = 32, FEd = 64, Ed = 16384;
constexpr int HFd = 256;

__device__ __forceinline__ float lrelu(float x) { return x > 0.f ? x : 0.01f * x; }

// Scratch (device globals: allocation-free)
__device__ float  g_xf[Bd * Ld * HFd];     // 2 MB
__device__ float  g_yf[Bd * Rd * HFd];     // 8 MB
__device__ __half g_Whc[264 * 256];        // Wc||Wca in half, [n][k]
__device__ __half g_Whx[256 * 256];        // Wex half
__device__ __half g_Why[256 * 256];        // Wey half

// fp16 m16n8k16 mma, f32 accum
__device__ __forceinline__ void mma_f16(float* c, uint32_t a0, uint32_t a1, uint32_t a2, uint32_t a3,
                                        uint32_t b0, uint32_t b1)
{
    asm volatile(
        "mma.sync.aligned.m16n8k16.row.col.f32.f16.f16.f32 "
        "{%0,%1,%2,%3}, {%4,%5,%6,%7}, {%8,%9}, {%0,%1,%2,%3};"
        : "+f"(c[0]), "+f"(c[1]), "+f"(c[2]), "+f"(c[3])
        : "r"(a0), "r"(a1), "r"(a2), "r"(a3), "r"(b0), "r"(b1));
}

__device__ __forceinline__ void ldsm_x4(uint32_t* r, uint32_t addr)
{
    asm volatile("ldmatrix.sync.aligned.m8n8.x4.shared.b16 {%0,%1,%2,%3}, [%4];"
                 : "=r"(r[0]), "=r"(r[1]), "=r"(r[2]), "=r"(r[3]) : "r"(addr));
}
__device__ __forceinline__ void ldsm_x2(uint32_t* r, uint32_t addr)
{
    asm volatile("ldmatrix.sync.aligned.m8n8.x2.shared.b16 {%0,%1}, [%2];"
                 : "=r"(r[0]), "=r"(r[1]) : "r"(addr));
}

__device__ __forceinline__ uint32_t smem_u32(const void* p) {
    uint32_t a;
    asm("{ .reg .u64 t; cvta.to.shared.u64 t, %1; cvt.u32.u64 %0, t; }" : "=r"(a) : "l"(p));
    return a;
}

// ---------------------------------------------------------------------------
// Prep: all four weight matrices -> half, one launch.
// rows: [0,264) -> g_Whc (Wc rows 0..255, Wca rows 256..263)
//       [264,520) -> g_Whx ; [520,776) -> g_Why
// ---------------------------------------------------------------------------
__global__ void __launch_bounds__(256)
k_prep_all(const float* __restrict__ Wc, const float* __restrict__ Wca,
           const float* __restrict__ Wex, const float* __restrict__ Wey)
{
    int n = blockIdx.x, k = threadIdx.x;
    const float* src; __half* dst;
    if (n < 264) {
        src = (n < 256) ? (Wc + (size_t)n * 256) : (Wca + (size_t)(n - 256) * 256);
        dst = g_Whc + (size_t)n * 256;
    } else if (n < 520) {
        src = Wex + (size_t)(n - 264) * 256;
        dst = g_Whx + (size_t)(n - 264) * 256;
    } else {
        src = Wey + (size_t)(n - 520) * 256;
        dst = g_Why + (size_t)(n - 520) * 256;
    }
    dst[k] = __float2half_rn(src[k]);
}

// ---------------------------------------------------------------------------
// Contract kernel: PERSISTENT. grid=152 CTAs x 512 thr; B resident once,
// tile loop over 2048 (b,x) tiles. ldmatrix frags, fully-unrolled mainloop.
// ---------------------------------------------------------------------------
constexpr uint32_t CSA_B  = 0;          // half [128][264]  row stride 528 B
constexpr uint32_t CSB_B  = 67584;      // half [264][264]  row stride 528 B (512B data)
constexpr uint32_t CLG_B  = 206976;     // f32 [128][8]
constexpr uint32_t CMU_B  = 211072;     // f32 [128]
constexpr uint32_t CRS_B  = 211584;     // f32 [128]
constexpr uint32_t CSP_B  = 212096;     // f32 [128][4]
constexpr uint32_t CSQ_B  = 214144;     // f32 [128][4]
constexpr uint32_t CCP_B  = 216192;     // f32 [4][256]
constexpr uint32_t CG_B   = 220288;     // f32 [256]
constexpr uint32_t CBE_B  = 221312;     // f32 [256]
constexpr uint32_t CBC_B  = 222336;     // f32 [256]
constexpr uint32_t CBCA_B = 223360;     // f32 [8]
constexpr uint32_t CSUM_B = 223392;     // f32 [8]
constexpr int SM_CONTRACT_BYTES = 223424;
constexpr int N_TILES = Bd * Ld;        // 2048

__global__ void __launch_bounds__(512, 1)
k_contract(const float* __restrict__ ll, const unsigned* __restrict__ mask,
           const float* __restrict__ bc, const float* __restrict__ gc,
           const float* __restrict__ bec, const float* __restrict__ bca,
           float* __restrict__ out)
{
    extern __shared__ char smc[];
    float* smf = (float*)smc;
    const uint32_t smb = smem_u32(smc);
    const int t = threadIdx.x;
    const int w = t >> 5, lane = t & 31;
    const int wm = w >> 2, wn = w & 3;
    const int qrow = lane >> 2, qcol = lane & 3;

    // B resident: 264 rows x 512 data bytes via cp.async
    for (int m = t; m < 8448; m += 512) {
        int n = m >> 5, k16 = m & 31;
        const __half* src = g_Whc + (size_t)n * 256 + k16 * 8;
        uint32_t dst = smb + CSB_B + n * 528 + k16 * 16;
        asm volatile("cp.async.cg.shared.global [%0], [%1], 16;" :: "r"(dst), "l"(src));
    }
    asm volatile("cp.async.commit_group;");

    // constants (once)
    if (t < 256) {
        smf[(CG_B >> 2) + t]  = gc[t];
        smf[(CBE_B >> 2) + t] = bec[t];
        smf[(CBC_B >> 2) + t] = bc[t];
    }
    if (t < 8) smf[(CBCA_B >> 2) + t] = bca[t];

    asm volatile("cp.async.wait_group 0;");
    __syncthreads();

    // ldmatrix source addresses (fixed per thread)
    const uint32_t aAddr0 = smb + CSA_B + (uint32_t)(wm * 32 + (lane & 15)) * 528 + ((lane >> 4) << 4);
    const uint32_t aAddr1 = aAddr0 + 16 * 528;
    const uint32_t bAddrB = smb + CSB_B + (uint32_t)(wn * 64 + (lane & 7)) * 528 + (((lane >> 3) & 1) << 4);
    const uint32_t bAddrL = smb + CSB_B + (uint32_t)(256 + (lane & 7)) * 528 + (((lane >> 3) & 1) << 4);
    const int r0base = wm * 32 + qrow;

    for (int tile = blockIdx.x; tile < N_TILES; tile += gridDim.x) {
        // ---- stage A (lrelu -> half) ----
        const float* Arow = ll + (size_t)tile * (Ld * Fd);
#pragma unroll
        for (int s = 0; s < 16; s++) {
            int m = t + s * 512;
            int y = m >> 6, c4 = m & 63;
            float4 v = *(const float4*)(Arow + y * 256 + c4 * 4);
            __half2 h01 = __floats2half2_rn(lrelu(v.x), lrelu(v.y));
            __half2 h23 = __floats2half2_rn(lrelu(v.z), lrelu(v.w));
            uint2 u;
            u.x = *(uint32_t*)&h01; u.y = *(uint32_t*)&h23;
            *(uint2*)(smc + CSA_B + y * 528 + c4 * 8) = u;
        }
        __syncthreads();

        float acc[2][9][4];
#pragma unroll
        for (int mt = 0; mt < 2; mt++)
#pragma unroll
            for (int nt = 0; nt < 9; nt++)
#pragma unroll
                for (int q = 0; q < 4; q++) acc[mt][nt][q] = 0.f;

        // ---- sync-free mainloop: 16 k-steps, fully unrolled inner tiles ----
#pragma unroll 2
        for (int ks = 0; ks < 16; ks++) {
            const uint32_t ko = (uint32_t)ks * 32;
            uint32_t a0[4], a1[4];
            ldsm_x4(a0, aAddr0 + ko);
            ldsm_x4(a1, aAddr1 + ko);
            uint32_t bb[8][2];
#pragma unroll
            for (int nt = 0; nt < 8; nt++)
                ldsm_x2(bb[nt], bAddrB + (uint32_t)nt * (8 * 528) + ko);
#pragma unroll
            for (int nt = 0; nt < 8; nt++) {
                mma_f16(acc[0][nt], a0[0], a0[1], a0[2], a0[3], bb[nt][0], bb[nt][1]);
                mma_f16(acc[1][nt], a1[0], a1[1], a1[2], a1[3], bb[nt][0], bb[nt][1]);
            }
            if (wn == 3) {
                uint32_t cL[2];
                ldsm_x2(cL, bAddrL + ko);
                mma_f16(acc[0][8], a0[0], a0[1], a0[2], a0[3], cL[0], cL[1]);
                mma_f16(acc[1][8], a1[0], a1[1], a1[2], a1[3], cL[0], cL[1]);
            }
        }

        // ---- epilogue phase 1: bias add, logits out, LN partial sums ----
#pragma unroll
        for (int mt = 0; mt < 2; mt++)
#pragma unroll
            for (int nt = 0; nt < 8; nt++) {
                int col = wn * 64 + nt * 8 + 2 * qcol;
                float b0 = smf[(CBC_B >> 2) + col], b1 = smf[(CBC_B >> 2) + col + 1];
                acc[mt][nt][0] += b0; acc[mt][nt][1] += b1;
                acc[mt][nt][2] += b0; acc[mt][nt][3] += b1;
            }
        if (wn == 3) {
            float ba0 = smf[(CBCA_B >> 2) + 2 * qcol], ba1 = smf[(CBCA_B >> 2) + 2 * qcol + 1];
#pragma unroll
            for (int mt = 0; mt < 2; mt++) {
                int r = r0base + mt * 16;
                smf[(CLG_B >> 2) + r * 8 + 2 * qcol]           = acc[mt][8][0] + ba0;
                smf[(CLG_B >> 2) + r * 8 + 2 * qcol + 1]       = acc[mt][8][1] + ba1;
                smf[(CLG_B >> 2) + (r + 8) * 8 + 2 * qcol]     = acc[mt][8][2] + ba0;
                smf[(CLG_B >> 2) + (r + 8) * 8 + 2 * qcol + 1] = acc[mt][8][3] + ba1;
            }
        }
#pragma unroll
        for (int mt = 0; mt < 2; mt++)
#pragma unroll
            for (int e = 0; e < 2; e++) {
                int r = r0base + mt * 16 + e * 8;
                int qb = e * 2;
                float s = 0.f, sq = 0.f;
#pragma unroll
                for (int nt = 0; nt < 8; nt++) {
                    float v0 = acc[mt][nt][qb], v1 = acc[mt][nt][qb + 1];
                    s += v0 + v1; sq += v0 * v0 + v1 * v1;
                }
                s  += __shfl_xor_sync(0xffffffffu, s, 1);  s  += __shfl_xor_sync(0xffffffffu, s, 2);
                sq += __shfl_xor_sync(0xffffffffu, sq, 1); sq += __shfl_xor_sync(0xffffffffu, sq, 2);
                if (qcol == 0) {
                    smf[(CSP_B >> 2) + r * 4 + wn] = s;
                    smf[(CSQ_B >> 2) + r * 4 + wn] = sq;
                }
            }
        __syncthreads();

        // ---- phase 2: row stats + masked softmax ----
        if (t < 128) {
            int r = t;
            float s  = smf[(CSP_B >> 2) + r * 4] + smf[(CSP_B >> 2) + r * 4 + 1]
                     + smf[(CSP_B >> 2) + r * 4 + 2] + smf[(CSP_B >> 2) + r * 4 + 3];
            float sq = smf[(CSQ_B >> 2) + r * 4] + smf[(CSQ_B >> 2) + r * 4 + 1]
                     + smf[(CSQ_B >> 2) + r * 4 + 2] + smf[(CSQ_B >> 2) + r * 4 + 3];
            float mu = s * (1.f / 256.f);
            float var = sq * (1.f / 256.f) - mu * mu;
            smf[(CMU_B >> 2) + r] = mu;
            smf[(CRS_B >> 2) + r] = rsqrtf(var + 1e-5f);
        }
        if (w >= 8) {
            int h = w - 8;
            float lv[4];
#pragma unroll
            for (int q = 0; q < 4; q++) lv[q] = smf[(CLG_B >> 2) + (lane + q * 32) * 8 + h];
            float mx = fmaxf(fmaxf(lv[0], lv[1]), fmaxf(lv[2], lv[3]));
#pragma unroll
            for (int o = 16; o; o >>= 1) mx = fmaxf(mx, __shfl_xor_sync(0xffffffffu, mx, o));
            const unsigned* mrow = mask + (size_t)tile * Ld;
            float e[4], sum = 0.f;
#pragma unroll
            for (int q = 0; q < 4; q++) {
                int y = lane + q * 32;
                float ee = (mrow[y] != 0u) ? expf(lv[q] - mx) : 0.f;
                e[q] = ee; sum += ee;
            }
#pragma unroll
            for (int o = 16; o; o >>= 1) sum += __shfl_xor_sync(0xffffffffu, sum, o);
#pragma unroll
            for (int q = 0; q < 4; q++) smf[(CLG_B >> 2) + (lane + q * 32) * 8 + h] = e[q];
            if (lane == 0) smf[(CSUM_B >> 2) + h] = sum + 1e-10f;
        }
        __syncthreads();

        // ---- phase 3: LN apply + weighted contraction ----
        {
            float psum[16];
#pragma unroll
            for (int i = 0; i < 16; i++) psum[i] = 0.f;
#pragma unroll
            for (int mt = 0; mt < 2; mt++)
#pragma unroll
                for (int e = 0; e < 2; e++) {
                    int r = r0base + mt * 16 + e * 8;
                    int qb = e * 2;
                    float mu = smf[(CMU_B >> 2) + r];
                    float rs = smf[(CRS_B >> 2) + r];
                    float a0 = smf[(CLG_B >> 2) + r * 8 + wn * 2];
                    float a1 = smf[(CLG_B >> 2) + r * 8 + wn * 2 + 1];
#pragma unroll
                    for (int nt = 0; nt < 8; nt++) {
                        int col = wn * 64 + nt * 8 + 2 * qcol;
                        float g0 = smf[(CG_B >> 2) + col],  g1 = smf[(CG_B >> 2) + col + 1];
                        float e0 = smf[(CBE_B >> 2) + col], e1 = smf[(CBE_B >> 2) + col + 1];
                        float of0 = g0 * ((acc[mt][nt][qb] - mu) * rs) + e0;
                        float of1 = g1 * ((acc[mt][nt][qb + 1] - mu) * rs) + e1;
                        float a = (nt < 4) ? a0 : a1;
                        psum[nt * 2]     += a * of0;
                        psum[nt * 2 + 1] += a * of1;
                    }
                }
#pragma unroll
            for (int i = 0; i < 16; i++) {
                psum[i] += __shfl_xor_sync(0xffffffffu, psum[i], 4);
                psum[i] += __shfl_xor_sync(0xffffffffu, psum[i], 8);
                psum[i] += __shfl_xor_sync(0xffffffffu, psum[i], 16);
            }
            if (qrow == 0) {
#pragma unroll
                for (int nt = 0; nt < 8; nt++) {
                    int col = wn * 64 + nt * 8 + 2 * qcol;
                    smf[(CCP_B >> 2) + wm * 256 + col]     = psum[nt * 2];
                    smf[(CCP_B >> 2) + wm * 256 + col + 1] = psum[nt * 2 + 1];
                }
            }
        }
        __syncthreads();

        if (t < 256) {
            int col = t, h = col >> 5;
            float v = smf[(CCP_B >> 2) + col] + smf[(CCP_B >> 2) + 256 + col]
                    + smf[(CCP_B >> 2) + 512 + col] + smf[(CCP_B >> 2) + 768 + col];
            out[(size_t)tile * HFd + col] = v / smf[(CSUM_B >> 2) + h];
        }
        __syncthreads();
    }
}

// ---------------------------------------------------------------------------
// NormAndLinear via fp16 mma: 128 rows per CTA, N=256, K=256, W resident.
// ---------------------------------------------------------------------------
constexpr uint32_t NSA_B = 0;          // half [128][264]
constexpr uint32_t NSB_B = 67584;      // half [256][264]
constexpr uint32_t NMU_B = 202752;     // f32 [128]
constexpr uint32_t NRS_B = 203264;     // f32 [128]
constexpr uint32_t NSP_B = 203776;     // f32 [128][4]
constexpr uint32_t NSQ_B = 205824;     // f32 [128][4]
constexpr uint32_t NG_B  = 207872;     // f32 [256]
constexpr uint32_t NBE_B = 208896;     // f32 [256]
constexpr uint32_t NBC_B = 209920;     // f32 [256]
constexpr int SM_NORMLIN_BYTES = 210944;

__global__ void __launch_bounds__(512, 1)
k_normlin_h(const float* __restrict__ X, const __half* __restrict__ Wh,
            const float* __restrict__ bias, const float* __restrict__ g,
            const float* __restrict__ be, float* __restrict__ out)
{
    extern __shared__ char smc[];
    float* smf = (float*)smc;
    const uint32_t smb = smem_u32(smc);
    const int t = threadIdx.x;
    const int row0 = blockIdx.x * 128;
    const int w = t >> 5, lane = t & 31;
    const int wm = w >> 2, wn = w & 3;
    const int qrow = lane >> 2, qcol = lane & 3;

    for (int m = t; m < 8192; m += 512) {
        int n = m >> 5, k16 = m & 31;
        const __half* src = Wh + (size_t)n * 256 + k16 * 8;
        uint32_t dst = smb + NSB_B + n * 528 + k16 * 16;
        asm volatile("cp.async.cg.shared.global [%0], [%1], 16;" :: "r"(dst), "l"(src));
    }
    asm volatile("cp.async.commit_group;");

    if (t < 256) {
        smf[(NG_B >> 2) + t]  = g[t];
        smf[(NBE_B >> 2) + t] = be[t];
        smf[(NBC_B >> 2) + t] = bias[t];
    }

#pragma unroll
    for (int s = 0; s < 16; s++) {
        int m = t + s * 512;
        int y = m >> 6, c4 = m & 63;
        float4 v = *(const float4*)(X + (size_t)(row0 + y) * Fd + c4 * 4);
        __half2 h01 = __floats2half2_rn(lrelu(v.x), lrelu(v.y));
        __half2 h23 = __floats2half2_rn(lrelu(v.z), lrelu(v.w));
        uint2 u;
        u.x = *(uint32_t*)&h01; u.y = *(uint32_t*)&h23;
        *(uint2*)(smc + NSA_B + y * 528 + c4 * 8) = u;
    }

    float acc[2][8][4];
#pragma unroll
    for (int mt = 0; mt < 2; mt++)
#pragma unroll
        for (int nt = 0; nt < 8; nt++)
#pragma unroll
            for (int q = 0; q < 4; q++) acc[mt][nt][q] = 0.f;

    asm volatile("cp.async.wait_group 0;");
    __syncthreads();

    const uint32_t aAddr0 = smb + NSA_B + (uint32_t)(wm * 32 + (lane & 15)) * 528 + ((lane >> 4) << 4);
    const uint32_t aAddr1 = aAddr0 + 16 * 528;
    const uint32_t bAddrB = smb + NSB_B + (uint32_t)(wn * 64 + (lane & 7)) * 528 + (((lane >> 3) & 1) << 4);
    const int r0base = wm * 32 + qrow;

#pragma unroll 2
    for (int ks = 0; ks < 16; ks++) {
        const uint32_t ko = (uint32_t)ks * 32;
        uint32_t a0[4], a1[4];
        ldsm_x4(a0, aAddr0 + ko);
        ldsm_x4(a1, aAddr1 + ko);
        uint32_t bb[8][2];
#pragma unroll
        for (int nt = 0; nt < 8; nt++)
            ldsm_x2(bb[nt], bAddrB + (uint32_t)nt * (8 * 528) + ko);
#pragma unroll
        for (int nt = 0; nt < 8; nt++) {
            mma_f16(acc[0][nt], a0[0], a0[1], a0[2], a0[3], bb[nt][0], bb[nt][1]);
            mma_f16(acc[1][nt], a1[0], a1[1], a1[2], a1[3], bb[nt][0], bb[nt][1]);
        }
    }

#pragma unroll
    for (int mt = 0; mt < 2; mt++)
#pragma unroll
        for (int nt = 0; nt < 8; nt++) {
            int col = wn * 64 + nt * 8 + 2 * qcol;
            float b0 = smf[(NBC_B >> 2) + col], b1 = smf[(NBC_B >> 2) + col + 1];
            acc[mt][nt][0] += b0; acc[mt][nt][1] += b1;
            acc[mt][nt][2] += b0; acc[mt][nt][3] += b1;
        }
#pragma unroll
    for (int mt = 0; mt < 2; mt++)
#pragma unroll
        for (int e = 0; e < 2; e++) {
            int r = r0base + mt * 16 + e * 8;
            int qb = e * 2;
            float s = 0.f, sq = 0.f;
#pragma unroll
            for (int nt = 0; nt < 8; nt++) {
                float v0 = acc[mt][nt][qb], v1 = acc[mt][nt][qb + 1];
                s += v0 + v1; sq += v0 * v0 + v1 * v1;
            }
            s  += __shfl_xor_sync(0xffffffffu, s, 1);  s  += __shfl_xor_sync(0xffffffffu, s, 2);
            sq += __shfl_xor_sync(0xffffffffu, sq, 1); sq += __shfl_xor_sync(0xffffffffu, sq, 2);
            if (qcol == 0) {
                smf[(NSP_B >> 2) + r * 4 + wn] = s;
                smf[(NSQ_B >> 2) + r * 4 + wn] = sq;
            }
        }
    __syncthreads();

    if (t < 128) {
        int r = t;
        float s  = smf[(NSP_B >> 2) + r * 4] + smf[(NSP_B >> 2) + r * 4 + 1]
                 + smf[(NSP_B >> 2) + r * 4 + 2] + smf[(NSP_B >> 2) + r * 4 + 3];
        float sq = smf[(NSQ_B >> 2) + r * 4] + smf[(NSQ_B >> 2) + r * 4 + 1]
                 + smf[(NSQ_B >> 2) + r * 4 + 2] + smf[(NSQ_B >> 2) + r * 4 + 3];
        float mu = s * (1.f / 256.f);
        float var = sq * (1.f / 256.f) - mu * mu;
        smf[(NMU_B >> 2) + r] = mu;
        smf[(NRS_B >> 2) + r] = rsqrtf(var + 1e-5f);
    }
    __syncthreads();

#pragma unroll
    for (int mt = 0; mt < 2; mt++)
#pragma unroll
        for (int e = 0; e < 2; e++) {
            int r = r0base + mt * 16 + e * 8;
            int qb = e * 2;
            float mu = smf[(NMU_B >> 2) + r];
            float rs = smf[(NRS_B >> 2) + r];
            float* orow = out + (size_t)(row0 + r) * 256;
#pragma unroll
            for (int nt = 0; nt < 8; nt++) {
                int col = wn * 64 + nt * 8 + 2 * qcol;
                float g0 = smf[(NG_B >> 2) + col],  g1 = smf[(NG_B >> 2) + col + 1];
                float e0 = smf[(NBE_B >> 2) + col], e1 = smf[(NBE_B >> 2) + col + 1];
                float2 o;
                o.x = g0 * ((acc[mt][nt][qb] - mu) * rs) + e0;
                o.y = g1 * ((acc[mt][nt][qb + 1] - mu) * rs) + e1;
                *(float2*)(orow + col) = o;
            }
        }
}

// ---------------------------------------------------------------------------
// Expand: out[b,x,y,h] = sum_f xf[b,x,h,f]*yf[b,y,h,f]
// ---------------------------------------------------------------------------
constexpr int EXP_SMEM_FLOATS = 16 * 8 * 36 + 64 * 8 * 36;
constexpr int EXP_SMEM_BYTES  = EXP_SMEM_FLOATS * 4;

__global__ void __launch_bounds__(256)
k_expand(float* __restrict__ out)
{
    extern __shared__ float es[];
    float* sX = es;
    float* sY = es + 16 * 8 * 36;
    const int t = threadIdx.x;
    const int x0 = blockIdx.x * 16, y0 = blockIdx.y * 64, b = blockIdx.z;

#pragma unroll
    for (int s = 0; s < 4; s++) {
        int m = t + s * 256;
        int xi = m >> 6, c = (m & 63) * 4;
        int h = c >> 5, f = c & 31;
        float4 v = *(const float4*)(g_xf + (size_t)(b * Ld + x0 + xi) * HFd + c);
        float* d = &sX[(xi * 8 + h) * 36 + f];
        d[0] = v.x; d[1] = v.y; d[2] = v.z; d[3] = v.w;
    }
#pragma unroll
    for (int s = 0; s < 16; s++) {
        int m = t + s * 256;
        int yi = m >> 6, c = (m & 63) * 4;
        int h = c >> 5, f = c & 31;
        float4 v = *(const float4*)(g_yf + (size_t)(b * Rd + y0 + yi) * HFd + c);
        float* d = &sY[(yi * 8 + h) * 36 + f];
        d[0] = v.x; d[1] = v.y; d[2] = v.z; d[3] = v.w;
    }
    __syncthreads();

    const int h = t & 7, yy = t >> 3;
    float acc[2][16];
#pragma unroll
    for (int p = 0; p < 2; p++)
#pragma unroll
        for (int xi = 0; xi < 16; xi++) acc[p][xi] = 0.f;
#pragma unroll
    for (int f4 = 0; f4 < 32; f4 += 4) {
        float4 yv0 = *(const float4*)&sY[(yy * 8 + h) * 36 + f4];
        float4 yv1 = *(const float4*)&sY[((yy + 32) * 8 + h) * 36 + f4];
#pragma unroll
        for (int xi = 0; xi < 16; xi++) {
            float4 xv = *(const float4*)&sX[(xi * 8 + h) * 36 + f4];
            acc[0][xi] += xv.x * yv0.x + xv.y * yv0.y + xv.z * yv0.z + xv.w * yv0.w;
            acc[1][xi] += xv.x * yv1.x + xv.y * yv1.y + xv.z * yv1.z + xv.w * yv1.w;
        }
    }
#pragma unroll
    for (int xi = 0; xi < 16; xi++) {
        out[((size_t)(b * Ld + x0 + xi) * Rd + y0 + yy) * Hd + h]      = acc[0][xi];
        out[((size_t)(b * Ld + x0 + xi) * Rd + y0 + yy + 32) * Hd + h] = acc[1][xi];
    }
}

// ---------------------------------------------------------------------------
// Zero llf region
// ---------------------------------------------------------------------------
__global__ void __launch_bounds__(256)
k_zero(float4* __restrict__ p)
{
    size_t base = ((size_t)blockIdx.x * 256 + threadIdx.x) * 4;
#pragma unroll
    for (int i = 0; i < 4; i++) p[base + i] = make_float4(0.f, 0.f, 0.f, 0.f);
}

// ---------------------------------------------------------------------------
// Edge: gather -> linear(2F->FE) -> lrelu -> atomic scatter into llf.
// ---------------------------------------------------------------------------
constexpr int WET_LD = 68;
constexpr int EDGE_SMEM_FLOATS = 512 * WET_LD + 32 * 512;
constexpr int EDGE_SMEM_BYTES  = EDGE_SMEM_FLOATS * 4;

__global__ void __launch_bounds__(256, 1)
k_edge(const float* __restrict__ lig, const int* __restrict__ eb,
       const int* __restrict__ es, const int* __restrict__ ed,
       const float* __restrict__ We, const float* __restrict__ be,
       float* __restrict__ llf)
{
    extern __shared__ float sm[];
    float* sWeT = sm;
    float* sEF  = sm + 512 * WET_LD;
    const int t = threadIdx.x;

#pragma unroll 8
    for (int s = 0; s < 128; s++) {
        int m = t + s * 256;
        int k = m & 511, o = m >> 9;
        sWeT[k * WET_LD + o] = We[o * 512 + k];
    }

    const int to = t & 7;
    const int te = t >> 3;
    float bev[8];
#pragma unroll
    for (int c = 0; c < 8; c++) bev[c] = be[to * 8 + c];

    for (int iter = 0; iter < 4; iter++) {
        __syncthreads();
#pragma unroll
        for (int s = 0; s < 16; s++) {
            int m = t + s * 256;
            int eg = m >> 7, kq = m & 127;
            int k = kq * 4;
            int e = blockIdx.x * 128 + iter * 32 + eg;
            int bb = eb[e];
            int row = (k < 256) ? es[e] : ed[e];
            int col = (k < 256) ? k : (k - 256);
            float4 v = *(const float4*)(lig + (size_t)(bb * Ld + row) * Fd + col);
            float* d = &sEF[eg * 512 + k];
            d[0] = v.x; d[1] = v.y; d[2] = v.z; d[3] = v.w;
        }
        __syncthreads();

        float acc[8];
#pragma unroll
        for (int c = 0; c < 8; c++) acc[c] = 0.f;
#pragma unroll 4
        for (int k = 0; k < 512; k++) {
            float a = sEF[te * 512 + k];
            float4 w0 = *(const float4*)&sWeT[k * WET_LD + to * 8];
            float4 w1 = *(const float4*)&sWeT[k * WET_LD + to * 8 + 4];
            acc[0] += a * w0.x; acc[1] += a * w0.y; acc[2] += a * w0.z; acc[3] += a * w0.w;
            acc[4] += a * w1.x; acc[5] += a * w1.y; acc[6] += a * w1.z; acc[7] += a * w1.w;
        }
        int e = blockIdx.x * 128 + iter * 32 + te;
        int bb = eb[e], ss = es[e], dd = ed[e];
        float* dst = llf + ((size_t)(bb * Ld + ss) * Ld + dd) * FEd + to * 8;
#pragma unroll
        for (int c = 0; c < 8; c++) atomicAdd(dst + c, lrelu(acc[c] + bev[c]));
    }
}

// ---------------------------------------------------------------------------
// Launch
// ---------------------------------------------------------------------------
extern "C" void kernel_launch(void* const* d_in, const int* in_sizes, int n_in,
                              void* d_out, int out_size)
{
    const float*    ll   = (const float*)d_in[0];
    const float*    lig  = (const float*)d_in[1];
    const float*    rec  = (const float*)d_in[2];
    const unsigned* mask = (const unsigned*)d_in[3];
    const int*      eb   = (const int*)d_in[4];
    const int*      es   = (const int*)d_in[5];
    const int*      ed   = (const int*)d_in[6];
    const float*    Wc   = (const float*)d_in[7];
    const float*    bc   = (const float*)d_in[8];
    const float*    gcc  = (const float*)d_in[9];
    const float*    bec  = (const float*)d_in[10];
    const float*    Wca  = (const float*)d_in[11];
    const float*    bca  = (const float*)d_in[12];
    const float*    Wex  = (const float*)d_in[13];
    const float*    bex  = (const float*)d_in[14];
    const float*    gex  = (const float*)d_in[15];
    const float*    beex = (const float*)d_in[16];
    const float*    Wey  = (const float*)d_in[17];
    const float*    bey  = (const float*)d_in[18];
    const float*    gey  = (const float*)d_in[19];
    const float*    beey = (const float*)d_in[20];
    const float*    We   = (const float*)d_in[21];
    const float*    be   = (const float*)d_in[22];

    float* out = (float*)d_out;
    float* oC = out;
    float* oE = out + (size_t)Bd * Ld * HFd;
    float* oL = oE + (size_t)Bd * Ld * Rd * Hd;

    cudaFuncSetAttribute(k_contract, cudaFuncAttributeMaxDynamicSharedMemorySize, SM_CONTRACT_BYTES);
    cudaFuncSetAttribute(k_normlin_h, cudaFuncAttributeMaxDynamicSharedMemorySize, SM_NORMLIN_BYTES);
    cudaFuncSetAttribute(k_edge, cudaFuncAttributeMaxDynamicSharedMemorySize, EDGE_SMEM_BYTES);
    cudaFuncSetAttribute(k_expand, cudaFuncAttributeMaxDynamicSharedMemorySize, EXP_SMEM_BYTES);

    void* pxf = nullptr; void* pyf = nullptr; void* pWhx = nullptr; void* pWhy = nullptr;
    cudaGetSymbolAddress(&pxf, g_xf);
    cudaGetSymbolAddress(&pyf, g_yf);
    cudaGetSymbolAddress(&pWhx, g_Whx);
    cudaGetSymbolAddress(&pWhy, g_Why);

    // prep half weights (single launch)
    k_prep_all<<<776, 256>>>(Wc, Wca, Wex, Wey);

    // contract (persistent, fp16 mma, ldmatrix, B-resident)
    k_contract<<<152, 512, SM_CONTRACT_BYTES>>>(ll, mask, bc, gcc, bec, bca, oC);

    // expand branch
    k_normlin_h<<<16, 512, SM_NORMLIN_BYTES>>>(lig, (const __half*)pWhx, bex, gex, beex, (float*)pxf);
    k_normlin_h<<<64, 512, SM_NORMLIN_BYTES>>>(rec, (const __half*)pWhy, bey, gey, beey, (float*)pyf);
    k_expand<<<dim3(8, 8, 16), 256, EXP_SMEM_BYTES>>>(oE);

    // edge branch
    k_zero<<<4096, 256>>>((float4*)oL);
    k_edge<<<128, 256, EDGE_SMEM_BYTES>>>(lig, eb, es, ed, We, be, oL);
}

// round 11
// speedup vs baseline: 4.6657x; 1.4805x over previous
#include <cuda_runtime.h>
#include <cuda_fp16.h>
#include <cstdint>
#include <cstddef>

// ---------------------------------------------------------------------------
// Problem dims
// ---------------------------------------------------------------------------
constexpr int Bd = 16, Ld = 128, Rd = 512, Fd = 256, Hd = 8, FHd = 32, FEd = 64, Ed = 16384;
constexpr int HFd = 256;

__device__ __forceinline__ float lrelu(float x) { return x > 0.f ? x : 0.01f * x; }

// Scratch (device globals: allocation-free)
__device__ float  g_xf[Bd * Ld * HFd];        // 2 MB
__device__ float  g_yf[Bd * Rd * HFd];        // 8 MB
__device__ __half g_Whc[264 * 256];           // Wc||Wca half
__device__ __half g_Whx[256 * 256];           // Wex half
__device__ __half g_Why[256 * 256];           // Wey half
__device__ __half g_Weh[64 * 512];            // We half
__device__ __half g_llh[67108864];            // lrelu(ll) half, 134 MB

// fp16 m16n8k16 mma, f32 accum
__device__ __forceinline__ void mma_f16(float* c, uint32_t a0, uint32_t a1, uint32_t a2, uint32_t a3,
                                        uint32_t b0, uint32_t b1)
{
    asm volatile(
        "mma.sync.aligned.m16n8k16.row.col.f32.f16.f16.f32 "
        "{%0,%1,%2,%3}, {%4,%5,%6,%7}, {%8,%9}, {%0,%1,%2,%3};"
        : "+f"(c[0]), "+f"(c[1]), "+f"(c[2]), "+f"(c[3])
        : "r"(a0), "r"(a1), "r"(a2), "r"(a3), "r"(b0), "r"(b1));
}
__device__ __forceinline__ void ldsm_x4(uint32_t* r, uint32_t addr)
{
    asm volatile("ldmatrix.sync.aligned.m8n8.x4.shared.b16 {%0,%1,%2,%3}, [%4];"
                 : "=r"(r[0]), "=r"(r[1]), "=r"(r[2]), "=r"(r[3]) : "r"(addr));
}
__device__ __forceinline__ void ldsm_x2(uint32_t* r, uint32_t addr)
{
    asm volatile("ldmatrix.sync.aligned.m8n8.x2.shared.b16 {%0,%1}, [%2];"
                 : "=r"(r[0]), "=r"(r[1]) : "r"(addr));
}
__device__ __forceinline__ uint32_t smem_u32(const void* p) {
    uint32_t a;
    asm("{ .reg .u64 t; cvta.to.shared.u64 t, %1; cvt.u32.u64 %0, t; }" : "=r"(a) : "l"(p));
    return a;
}
#define CP_ASYNC16(dst, src) \
    asm volatile("cp.async.cg.shared.global [%0], [%1], 16;" :: "r"(dst), "l"(src))
#define CP_COMMIT() asm volatile("cp.async.commit_group;")
#define CP_WAIT0()  asm volatile("cp.async.wait_group 0;")

// ---------------------------------------------------------------------------
// Prep kernels
// ---------------------------------------------------------------------------
__global__ void __launch_bounds__(256)
k_prep_all(const float* __restrict__ Wc, const float* __restrict__ Wca,
           const float* __restrict__ Wex, const float* __restrict__ Wey)
{
    int n = blockIdx.x, k = threadIdx.x;
    const float* src; __half* dst;
    if (n < 264) {
        src = (n < 256) ? (Wc + (size_t)n * 256) : (Wca + (size_t)(n - 256) * 256);
        dst = g_Whc + (size_t)n * 256;
    } else if (n < 520) {
        src = Wex + (size_t)(n - 264) * 256;
        dst = g_Whx + (size_t)(n - 264) * 256;
    } else {
        src = Wey + (size_t)(n - 520) * 256;
        dst = g_Why + (size_t)(n - 520) * 256;
    }
    dst[k] = __float2half_rn(src[k]);
}

__global__ void __launch_bounds__(512)
k_prep_we(const float* __restrict__ We)
{
    int i = blockIdx.x * 512 + threadIdx.x;   // 64 blocks -> 32768
    g_Weh[i] = __float2half_rn(We[i]);
}

// lrelu(ll) -> half. 16,777,216 float4 granules; 8192 blocks x 512 thr x 4.
__global__ void __launch_bounds__(512)
k_prep_ll(const float* __restrict__ ll)
{
    size_t base = (size_t)blockIdx.x * 2048 + threadIdx.x;
#pragma unroll
    for (int it = 0; it < 4; it++) {
        size_t g = base + (size_t)it * 512;
        float4 v = *(const float4*)(ll + g * 4);
        __half2 h01 = __floats2half2_rn(lrelu(v.x), lrelu(v.y));
        __half2 h23 = __floats2half2_rn(lrelu(v.z), lrelu(v.w));
        uint2 u;
        u.x = *(uint32_t*)&h01; u.y = *(uint32_t*)&h23;
        *(uint2*)(g_llh + g * 4) = u;
    }
}

// ---------------------------------------------------------------------------
// Contract kernel: PERSISTENT, A staged via cp.async from g_llh (half),
// issued one tile early (overlaps epilogue). B resident. ldmatrix + fp16 mma.
// ---------------------------------------------------------------------------
constexpr uint32_t CSA_B  = 0;          // half [128][264]  row stride 528 B
constexpr uint32_t CSB_B  = 67584;      // half [264][264]  row stride 528 B
constexpr uint32_t CLG_B  = 206976;     // f32 [128][8]
constexpr uint32_t CMU_B  = 211072;     // f32 [128]
constexpr uint32_t CRS_B  = 211584;     // f32 [128]
constexpr uint32_t CSP_B  = 212096;     // f32 [128][4]
constexpr uint32_t CSQ_B  = 214144;     // f32 [128][4]
constexpr uint32_t CCP_B  = 216192;     // f32 [4][256]
constexpr uint32_t CG_B   = 220288;     // f32 [256]
constexpr uint32_t CBE_B  = 221312;     // f32 [256]
constexpr uint32_t CBC_B  = 222336;     // f32 [256]
constexpr uint32_t CBCA_B = 223360;     // f32 [8]
constexpr uint32_t CSUM_B = 223392;     // f32 [8]
constexpr int SM_CONTRACT_BYTES = 223424;
constexpr int N_TILES = Bd * Ld;        // 2048

__device__ __forceinline__ void c_stage_a(uint32_t smb, int t, int tile)
{
#pragma unroll
    for (int s = 0; s < 8; s++) {
        int m = t + s * 512;                 // 4096 granules of 16B
        int y = m >> 5, k16 = m & 31;
        const __half* src = g_llh + (size_t)tile * 32768 + y * 256 + k16 * 8;
        uint32_t dst = smb + CSA_B + y * 528 + k16 * 16;
        CP_ASYNC16(dst, src);
    }
}

__global__ void __launch_bounds__(512, 1)
k_contract(const unsigned* __restrict__ mask,
           const float* __restrict__ bc, const float* __restrict__ gc,
           const float* __restrict__ bec, const float* __restrict__ bca,
           float* __restrict__ out)
{
    extern __shared__ char smc[];
    float* smf = (float*)smc;
    const uint32_t smb = smem_u32(smc);
    const int t = threadIdx.x;
    const int w = t >> 5, lane = t & 31;
    const int wm = w >> 2, wn = w & 3;
    const int qrow = lane >> 2, qcol = lane & 3;

    // B resident
    for (int m = t; m < 8448; m += 512) {
        int n = m >> 5, k16 = m & 31;
        const __half* src = g_Whc + (size_t)n * 256 + k16 * 8;
        CP_ASYNC16(smb + CSB_B + n * 528 + k16 * 16, src);
    }
    // prime A(tile0)
    c_stage_a(smb, t, blockIdx.x);
    CP_COMMIT();

    if (t < 256) {
        smf[(CG_B >> 2) + t]  = gc[t];
        smf[(CBE_B >> 2) + t] = bec[t];
        smf[(CBC_B >> 2) + t] = bc[t];
    }
    if (t < 8) smf[(CBCA_B >> 2) + t] = bca[t];

    CP_WAIT0();
    __syncthreads();

    const uint32_t aAddr0 = smb + CSA_B + (uint32_t)(wm * 32 + (lane & 15)) * 528 + ((lane >> 4) << 4);
    const uint32_t aAddr1 = aAddr0 + 16 * 528;
    const uint32_t bAddrB = smb + CSB_B + (uint32_t)(wn * 64 + (lane & 7)) * 528 + (((lane >> 3) & 1) << 4);
    const uint32_t bAddrL = smb + CSB_B + (uint32_t)(256 + (lane & 7)) * 528 + (((lane >> 3) & 1) << 4);
    const int r0base = wm * 32 + qrow;

    for (int tile = blockIdx.x; tile < N_TILES; tile += gridDim.x) {
        float acc[2][9][4];
#pragma unroll
        for (int mt = 0; mt < 2; mt++)
#pragma unroll
            for (int nt = 0; nt < 9; nt++)
#pragma unroll
                for (int q = 0; q < 4; q++) acc[mt][nt][q] = 0.f;

        // ---- mainloop ----
#pragma unroll 2
        for (int ks = 0; ks < 16; ks++) {
            const uint32_t ko = (uint32_t)ks * 32;
            uint32_t a0[4], a1[4];
            ldsm_x4(a0, aAddr0 + ko);
            ldsm_x4(a1, aAddr1 + ko);
            uint32_t bb[8][2];
#pragma unroll
            for (int nt = 0; nt < 8; nt++)
                ldsm_x2(bb[nt], bAddrB + (uint32_t)nt * (8 * 528) + ko);
#pragma unroll
            for (int nt = 0; nt < 8; nt++) {
                mma_f16(acc[0][nt], a0[0], a0[1], a0[2], a0[3], bb[nt][0], bb[nt][1]);
                mma_f16(acc[1][nt], a1[0], a1[1], a1[2], a1[3], bb[nt][0], bb[nt][1]);
            }
            if (wn == 3) {
                uint32_t cL[2];
                ldsm_x2(cL, bAddrL + ko);
                mma_f16(acc[0][8], a0[0], a0[1], a0[2], a0[3], cL[0], cL[1]);
                mma_f16(acc[1][8], a1[0], a1[1], a1[2], a1[3], cL[0], cL[1]);
            }
        }

        // ---- phase 1: bias, logits, LN partials ----
#pragma unroll
        for (int mt = 0; mt < 2; mt++)
#pragma unroll
            for (int nt = 0; nt < 8; nt++) {
                int col = wn * 64 + nt * 8 + 2 * qcol;
                float b0 = smf[(CBC_B >> 2) + col], b1 = smf[(CBC_B >> 2) + col + 1];
                acc[mt][nt][0] += b0; acc[mt][nt][1] += b1;
                acc[mt][nt][2] += b0; acc[mt][nt][3] += b1;
            }
        if (wn == 3) {
            float ba0 = smf[(CBCA_B >> 2) + 2 * qcol], ba1 = smf[(CBCA_B >> 2) + 2 * qcol + 1];
#pragma unroll
            for (int mt = 0; mt < 2; mt++) {
                int r = r0base + mt * 16;
                smf[(CLG_B >> 2) + r * 8 + 2 * qcol]           = acc[mt][8][0] + ba0;
                smf[(CLG_B >> 2) + r * 8 + 2 * qcol + 1]       = acc[mt][8][1] + ba1;
                smf[(CLG_B >> 2) + (r + 8) * 8 + 2 * qcol]     = acc[mt][8][2] + ba0;
                smf[(CLG_B >> 2) + (r + 8) * 8 + 2 * qcol + 1] = acc[mt][8][3] + ba1;
            }
        }
#pragma unroll
        for (int mt = 0; mt < 2; mt++)
#pragma unroll
            for (int e = 0; e < 2; e++) {
                int r = r0base + mt * 16 + e * 8;
                int qb = e * 2;
                float s = 0.f, sq = 0.f;
#pragma unroll
                for (int nt = 0; nt < 8; nt++) {
                    float v0 = acc[mt][nt][qb], v1 = acc[mt][nt][qb + 1];
                    s += v0 + v1; sq += v0 * v0 + v1 * v1;
                }
                s  += __shfl_xor_sync(0xffffffffu, s, 1);  s  += __shfl_xor_sync(0xffffffffu, s, 2);
                sq += __shfl_xor_sync(0xffffffffu, sq, 1); sq += __shfl_xor_sync(0xffffffffu, sq, 2);
                if (qcol == 0) {
                    smf[(CSP_B >> 2) + r * 4 + wn] = s;
                    smf[(CSQ_B >> 2) + r * 4 + wn] = sq;
                }
            }
        __syncthreads();   // mainloop A reads done; phase1 smem visible

        // issue next tile's A copy (overlaps phases 2/3)
        {
            int next = tile + gridDim.x;
            if (next < N_TILES) c_stage_a(smb, t, next);
            CP_COMMIT();
        }

        // ---- phase 2: row stats + masked softmax ----
        if (t < 128) {
            int r = t;
            float s  = smf[(CSP_B >> 2) + r * 4] + smf[(CSP_B >> 2) + r * 4 + 1]
                     + smf[(CSP_B >> 2) + r * 4 + 2] + smf[(CSP_B >> 2) + r * 4 + 3];
            float sq = smf[(CSQ_B >> 2) + r * 4] + smf[(CSQ_B >> 2) + r * 4 + 1]
                     + smf[(CSQ_B >> 2) + r * 4 + 2] + smf[(CSQ_B >> 2) + r * 4 + 3];
            float mu = s * (1.f / 256.f);
            float var = sq * (1.f / 256.f) - mu * mu;
            smf[(CMU_B >> 2) + r] = mu;
            smf[(CRS_B >> 2) + r] = rsqrtf(var + 1e-5f);
        }
        if (w >= 8) {
            int h = w - 8;
            float lv[4];
#pragma unroll
            for (int q = 0; q < 4; q++) lv[q] = smf[(CLG_B >> 2) + (lane + q * 32) * 8 + h];
            float mx = fmaxf(fmaxf(lv[0], lv[1]), fmaxf(lv[2], lv[3]));
#pragma unroll
            for (int o = 16; o; o >>= 1) mx = fmaxf(mx, __shfl_xor_sync(0xffffffffu, mx, o));
            const unsigned* mrow = mask + (size_t)tile * Ld;
            float e[4], sum = 0.f;
#pragma unroll
            for (int q = 0; q < 4; q++) {
                int y = lane + q * 32;
                float ee = (mrow[y] != 0u) ? expf(lv[q] - mx) : 0.f;
                e[q] = ee; sum += ee;
            }
#pragma unroll
            for (int o = 16; o; o >>= 1) sum += __shfl_xor_sync(0xffffffffu, sum, o);
#pragma unroll
            for (int q = 0; q < 4; q++) smf[(CLG_B >> 2) + (lane + q * 32) * 8 + h] = e[q];
            if (lane == 0) smf[(CSUM_B >> 2) + h] = sum + 1e-10f;
        }
        __syncthreads();

        // ---- phase 3: LN apply + weighted contraction ----
        {
            float psum[16];
#pragma unroll
            for (int i = 0; i < 16; i++) psum[i] = 0.f;
#pragma unroll
            for (int mt = 0; mt < 2; mt++)
#pragma unroll
                for (int e = 0; e < 2; e++) {
                    int r = r0base + mt * 16 + e * 8;
                    int qb = e * 2;
                    float mu = smf[(CMU_B >> 2) + r];
                    float rs = smf[(CRS_B >> 2) + r];
                    float a0 = smf[(CLG_B >> 2) + r * 8 + wn * 2];
                    float a1 = smf[(CLG_B >> 2) + r * 8 + wn * 2 + 1];
#pragma unroll
                    for (int nt = 0; nt < 8; nt++) {
                        int col = wn * 64 + nt * 8 + 2 * qcol;
                        float g0 = smf[(CG_B >> 2) + col],  g1 = smf[(CG_B >> 2) + col + 1];
                        float e0 = smf[(CBE_B >> 2) + col], e1 = smf[(CBE_B >> 2) + col + 1];
                        float of0 = g0 * ((acc[mt][nt][qb] - mu) * rs) + e0;
                        float of1 = g1 * ((acc[mt][nt][qb + 1] - mu) * rs) + e1;
                        float a = (nt < 4) ? a0 : a1;
                        psum[nt * 2]     += a * of0;
                        psum[nt * 2 + 1] += a * of1;
                    }
                }
#pragma unroll
            for (int i = 0; i < 16; i++) {
                psum[i] += __shfl_xor_sync(0xffffffffu, psum[i], 4);
                psum[i] += __shfl_xor_sync(0xffffffffu, psum[i], 8);
                psum[i] += __shfl_xor_sync(0xffffffffu, psum[i], 16);
            }
            if (qrow == 0) {
#pragma unroll
                for (int nt = 0; nt < 8; nt++) {
                    int col = wn * 64 + nt * 8 + 2 * qcol;
                    smf[(CCP_B >> 2) + wm * 256 + col]     = psum[nt * 2];
                    smf[(CCP_B >> 2) + wm * 256 + col + 1] = psum[nt * 2 + 1];
                }
            }
        }
        __syncthreads();

        if (t < 256) {
            int col = t, h = col >> 5;
            float v = smf[(CCP_B >> 2) + col] + smf[(CCP_B >> 2) + 256 + col]
                    + smf[(CCP_B >> 2) + 512 + col] + smf[(CCP_B >> 2) + 768 + col];
            out[(size_t)tile * HFd + col] = v / smf[(CSUM_B >> 2) + h];
        }
        CP_WAIT0();
        __syncthreads();   // next A visible to all
    }
}

// ---------------------------------------------------------------------------
// NormAndLinear via fp16 mma: 64 rows per CTA, N=256, K=256, W resident.
// ---------------------------------------------------------------------------
constexpr uint32_t NSA_B = 0;          // half [64][528B]
constexpr uint32_t NSB_B = 33792;      // half [256][528B]
constexpr uint32_t NMU_B = 168960;     // f32 [64]
constexpr uint32_t NRS_B = 169216;     // f32 [64]
constexpr uint32_t NSP_B = 169472;     // f32 [64][4]
constexpr uint32_t NSQ_B = 170496;     // f32 [64][4]
constexpr uint32_t NG_B  = 171520;     // f32 [256]
constexpr uint32_t NBE_B = 172544;     // f32 [256]
constexpr uint32_t NBC_B = 173568;     // f32 [256]
constexpr int SM_NORMLIN_BYTES = 174592;

__global__ void __launch_bounds__(512, 1)
k_normlin_h(const float* __restrict__ X, const __half* __restrict__ Wh,
            const float* __restrict__ bias, const float* __restrict__ g,
            const float* __restrict__ be, float* __restrict__ out)
{
    extern __shared__ char smc[];
    float* smf = (float*)smc;
    const uint32_t smb = smem_u32(smc);
    const int t = threadIdx.x;
    const int row0 = blockIdx.x * 64;
    const int w = t >> 5, lane = t & 31;
    const int wm = w >> 2, wn = w & 3;
    const int qrow = lane >> 2, qcol = lane & 3;

    for (int m = t; m < 8192; m += 512) {
        int n = m >> 5, k16 = m & 31;
        CP_ASYNC16(smb + NSB_B + n * 528 + k16 * 16, Wh + (size_t)n * 256 + k16 * 8);
    }
    CP_COMMIT();

    if (t < 256) {
        smf[(NG_B >> 2) + t]  = g[t];
        smf[(NBE_B >> 2) + t] = be[t];
        smf[(NBC_B >> 2) + t] = bias[t];
    }

    // stage X rows (lrelu -> half): 64 x 256
#pragma unroll
    for (int s = 0; s < 8; s++) {
        int m = t + s * 512;
        int y = m >> 6, c4 = m & 63;
        float4 v = *(const float4*)(X + (size_t)(row0 + y) * Fd + c4 * 4);
        __half2 h01 = __floats2half2_rn(lrelu(v.x), lrelu(v.y));
        __half2 h23 = __floats2half2_rn(lrelu(v.z), lrelu(v.w));
        uint2 u;
        u.x = *(uint32_t*)&h01; u.y = *(uint32_t*)&h23;
        *(uint2*)(smc + NSA_B + y * 528 + c4 * 8) = u;
    }

    float acc[8][4];
#pragma unroll
    for (int nt = 0; nt < 8; nt++)
#pragma unroll
        for (int q = 0; q < 4; q++) acc[nt][q] = 0.f;

    CP_WAIT0();
    __syncthreads();

    const uint32_t aAddr0 = smb + NSA_B + (uint32_t)(wm * 16 + (lane & 15)) * 528 + ((lane >> 4) << 4);
    const uint32_t bAddrB = smb + NSB_B + (uint32_t)(wn * 64 + (lane & 7)) * 528 + (((lane >> 3) & 1) << 4);
    const int r0base = wm * 16 + qrow;

#pragma unroll 2
    for (int ks = 0; ks < 16; ks++) {
        const uint32_t ko = (uint32_t)ks * 32;
        uint32_t a0[4];
        ldsm_x4(a0, aAddr0 + ko);
        uint32_t bb[8][2];
#pragma unroll
        for (int nt = 0; nt < 8; nt++)
            ldsm_x2(bb[nt], bAddrB + (uint32_t)nt * (8 * 528) + ko);
#pragma unroll
        for (int nt = 0; nt < 8; nt++)
            mma_f16(acc[nt], a0[0], a0[1], a0[2], a0[3], bb[nt][0], bb[nt][1]);
    }

#pragma unroll
    for (int nt = 0; nt < 8; nt++) {
        int col = wn * 64 + nt * 8 + 2 * qcol;
        float b0 = smf[(NBC_B >> 2) + col], b1 = smf[(NBC_B >> 2) + col + 1];
        acc[nt][0] += b0; acc[nt][1] += b1;
        acc[nt][2] += b0; acc[nt][3] += b1;
    }
#pragma unroll
    for (int e = 0; e < 2; e++) {
        int r = r0base + e * 8;
        int qb = e * 2;
        float s = 0.f, sq = 0.f;
#pragma unroll
        for (int nt = 0; nt < 8; nt++) {
            float v0 = acc[nt][qb], v1 = acc[nt][qb + 1];
            s += v0 + v1; sq += v0 * v0 + v1 * v1;
        }
        s  += __shfl_xor_sync(0xffffffffu, s, 1);  s  += __shfl_xor_sync(0xffffffffu, s, 2);
        sq += __shfl_xor_sync(0xffffffffu, sq, 1); sq += __shfl_xor_sync(0xffffffffu, sq, 2);
        if (qcol == 0) {
            smf[(NSP_B >> 2) + r * 4 + wn] = s;
            smf[(NSQ_B >> 2) + r * 4 + wn] = sq;
        }
    }
    __syncthreads();

    if (t < 64) {
        int r = t;
        float s  = smf[(NSP_B >> 2) + r * 4] + smf[(NSP_B >> 2) + r * 4 + 1]
                 + smf[(NSP_B >> 2) + r * 4 + 2] + smf[(NSP_B >> 2) + r * 4 + 3];
        float sq = smf[(NSQ_B >> 2) + r * 4] + smf[(NSQ_B >> 2) + r * 4 + 1]
                 + smf[(NSQ_B >> 2) + r * 4 + 2] + smf[(NSQ_B >> 2) + r * 4 + 3];
        float mu = s * (1.f / 256.f);
        float var = sq * (1.f / 256.f) - mu * mu;
        smf[(NMU_B >> 2) + r] = mu;
        smf[(NRS_B >> 2) + r] = rsqrtf(var + 1e-5f);
    }
    __syncthreads();

#pragma unroll
    for (int e = 0; e < 2; e++) {
        int r = r0base + e * 8;
        int qb = e * 2;
        float mu = smf[(NMU_B >> 2) + r];
        float rs = smf[(NRS_B >> 2) + r];
        float* orow = out + (size_t)(row0 + r) * 256;
#pragma unroll
        for (int nt = 0; nt < 8; nt++) {
            int col = wn * 64 + nt * 8 + 2 * qcol;
            float g0 = smf[(NG_B >> 2) + col],  g1 = smf[(NG_B >> 2) + col + 1];
            float e0 = smf[(NBE_B >> 2) + col], e1 = smf[(NBE_B >> 2) + col + 1];
            float2 o;
            o.x = g0 * ((acc[nt][qb] - mu) * rs) + e0;
            o.y = g1 * ((acc[nt][qb + 1] - mu) * rs) + e1;
            *(float2*)(orow + col) = o;
        }
    }
}

// ---------------------------------------------------------------------------
// Expand: out[b,x,y,h] = sum_f xf[b,x,h,f]*yf[b,y,h,f]
// ---------------------------------------------------------------------------
constexpr int EXP_SMEM_FLOATS = 16 * 8 * 36 + 64 * 8 * 36;
constexpr int EXP_SMEM_BYTES  = EXP_SMEM_FLOATS * 4;

__global__ void __launch_bounds__(256)
k_expand(float* __restrict__ out)
{
    extern __shared__ float es[];
    float* sX = es;
    float* sY = es + 16 * 8 * 36;
    const int t = threadIdx.x;
    const int x0 = blockIdx.x * 16, y0 = blockIdx.y * 64, b = blockIdx.z;

#pragma unroll
    for (int s = 0; s < 4; s++) {
        int m = t + s * 256;
        int xi = m >> 6, c = (m & 63) * 4;
        int h = c >> 5, f = c & 31;
        float4 v = *(const float4*)(g_xf + (size_t)(b * Ld + x0 + xi) * HFd + c);
        float* d = &sX[(xi * 8 + h) * 36 + f];
        d[0] = v.x; d[1] = v.y; d[2] = v.z; d[3] = v.w;
    }
#pragma unroll
    for (int s = 0; s < 16; s++) {
        int m = t + s * 256;
        int yi = m >> 6, c = (m & 63) * 4;
        int h = c >> 5, f = c & 31;
        float4 v = *(const float4*)(g_yf + (size_t)(b * Rd + y0 + yi) * HFd + c);
        float* d = &sY[(yi * 8 + h) * 36 + f];
        d[0] = v.x; d[1] = v.y; d[2] = v.z; d[3] = v.w;
    }
    __syncthreads();

    const int h = t & 7, yy = t >> 3;
    float acc[2][16];
#pragma unroll
    for (int p = 0; p < 2; p++)
#pragma unroll
        for (int xi = 0; xi < 16; xi++) acc[p][xi] = 0.f;
#pragma unroll
    for (int f4 = 0; f4 < 32; f4 += 4) {
        float4 yv0 = *(const float4*)&sY[(yy * 8 + h) * 36 + f4];
        float4 yv1 = *(const float4*)&sY[((yy + 32) * 8 + h) * 36 + f4];
#pragma unroll
        for (int xi = 0; xi < 16; xi++) {
            float4 xv = *(const float4*)&sX[(xi * 8 + h) * 36 + f4];
            acc[0][xi] += xv.x * yv0.x + xv.y * yv0.y + xv.z * yv0.z + xv.w * yv0.w;
            acc[1][xi] += xv.x * yv1.x + xv.y * yv1.y + xv.z * yv1.z + xv.w * yv1.w;
        }
    }
#pragma unroll
    for (int xi = 0; xi < 16; xi++) {
        out[((size_t)(b * Ld + x0 + xi) * Rd + y0 + yy) * Hd + h]      = acc[0][xi];
        out[((size_t)(b * Ld + x0 + xi) * Rd + y0 + yy + 32) * Hd + h] = acc[1][xi];
    }
}

// ---------------------------------------------------------------------------
// Zero llf region
// ---------------------------------------------------------------------------
__global__ void __launch_bounds__(256)
k_zero(float4* __restrict__ p)
{
    size_t base = ((size_t)blockIdx.x * 256 + threadIdx.x) * 4;
#pragma unroll
    for (int i = 0; i < 4; i++) p[base + i] = make_float4(0.f, 0.f, 0.f, 0.f);
}

// ---------------------------------------------------------------------------
// Edge via fp16 mma: 256 CTAs x 64 edges. A = gathered concat feats (half),
// B = We (half). M=64, N=64, K=512. lrelu + atomic scatter epilogue.
// ---------------------------------------------------------------------------
constexpr uint32_t ESA_B = 0;          // half [64][1040B]
constexpr uint32_t ESB_B = 66560;      // half [64][1040B]
constexpr int SM_EDGE_BYTES = 133120;

__global__ void __launch_bounds__(256, 1)
k_edge_h(const float* __restrict__ lig, const int* __restrict__ eb,
         const int* __restrict__ es, const int* __restrict__ ed,
         const float* __restrict__ be, float* __restrict__ llf)
{
    extern __shared__ char smc[];
    const uint32_t smb = smem_u32(smc);
    const int t = threadIdx.x;
    const int w = t >> 5, lane = t & 31;
    const int wm = w >> 1, wn = w & 1;
    const int qrow = lane >> 2, qcol = lane & 3;
    const int e0 = blockIdx.x * 64;

    // stage B (We half) via cp.async: 64 rows x 1024B
#pragma unroll
    for (int s = 0; s < 16; s++) {
        int m = t + s * 256;
        int n = m >> 6, k16 = m & 63;
        CP_ASYNC16(smb + ESB_B + n * 1040 + k16 * 16, g_Weh + (size_t)n * 512 + k16 * 8);
    }
    CP_COMMIT();

    // gather A: 64 edges x 512 f32 (concat src|dst rows) -> half
#pragma unroll
    for (int s = 0; s < 32; s++) {
        int m = t + s * 256;
        int e = m >> 7, kq = m & 127;
        int ee = e0 + e;
        int bb = eb[ee];
        int row = (kq < 64) ? es[ee] : ed[ee];
        int c4  = (kq < 64) ? kq : (kq - 64);
        float4 v = *(const float4*)(lig + (size_t)(bb * Ld + row) * Fd + c4 * 4);
        __half2 h01 = __floats2half2_rn(v.x, v.y);
        __half2 h23 = __floats2half2_rn(v.z, v.w);
        uint2 u;
        u.x = *(uint32_t*)&h01; u.y = *(uint32_t*)&h23;
        *(uint2*)(smc + ESA_B + e * 1040 + kq * 8) = u;
    }
    CP_WAIT0();
    __syncthreads();

    const uint32_t aAddr = smb + ESA_B + (uint32_t)(wm * 16 + (lane & 15)) * 1040 + ((lane >> 4) << 4);
    const uint32_t bAddr = smb + ESB_B + (uint32_t)(wn * 32 + (lane & 7)) * 1040 + (((lane >> 3) & 1) << 4);

    float acc[4][4];
#pragma unroll
    for (int nt = 0; nt < 4; nt++)
#pragma unroll
        for (int q = 0; q < 4; q++) acc[nt][q] = 0.f;

#pragma unroll 4
    for (int ks = 0; ks < 32; ks++) {
        const uint32_t ko = (uint32_t)ks * 32;
        uint32_t a0[4];
        ldsm_x4(a0, aAddr + ko);
        uint32_t bb2[4][2];
#pragma unroll
        for (int nt = 0; nt < 4; nt++)
            ldsm_x2(bb2[nt], bAddr + (uint32_t)nt * (8 * 1040) + ko);
#pragma unroll
        for (int nt = 0; nt < 4; nt++)
            mma_f16(acc[nt], a0[0], a0[1], a0[2], a0[3], bb2[nt][0], bb2[nt][1]);
    }

    // epilogue: lrelu(acc + be) -> atomicAdd
#pragma unroll
    for (int e = 0; e < 2; e++) {
        int er = e0 + wm * 16 + qrow + e * 8;
        int bb = eb[er], ss = es[er], dd = ed[er];
        float* base = llf + ((size_t)(bb * Ld + ss) * Ld + dd) * FEd;
        int qb = e * 2;
#pragma unroll
        for (int nt = 0; nt < 4; nt++) {
            int col = wn * 32 + nt * 8 + 2 * qcol;
            atomicAdd(base + col,     lrelu(acc[nt][qb]     + be[col]));
            atomicAdd(base + col + 1, lrelu(acc[nt][qb + 1] + be[col + 1]));
        }
    }
}

// ---------------------------------------------------------------------------
// Launch
// ---------------------------------------------------------------------------
extern "C" void kernel_launch(void* const* d_in, const int* in_sizes, int n_in,
                              void* d_out, int out_size)
{
    const float*    ll   = (const float*)d_in[0];
    const float*    lig  = (const float*)d_in[1];
    const float*    rec  = (const float*)d_in[2];
    const unsigned* mask = (const unsigned*)d_in[3];
    const int*      eb   = (const int*)d_in[4];
    const int*      es   = (const int*)d_in[5];
    const int*      ed   = (const int*)d_in[6];
    const float*    Wc   = (const float*)d_in[7];
    const float*    bc   = (const float*)d_in[8];
    const float*    gcc  = (const float*)d_in[9];
    const float*    bec  = (const float*)d_in[10];
    const float*    Wca  = (const float*)d_in[11];
    const float*    bca  = (const float*)d_in[12];
    const float*    Wex  = (const float*)d_in[13];
    const float*    bex  = (const float*)d_in[14];
    const float*    gex  = (const float*)d_in[15];
    const float*    beex = (const float*)d_in[16];
    const float*    Wey  = (const float*)d_in[17];
    const float*    bey  = (const float*)d_in[18];
    const float*    gey  = (const float*)d_in[19];
    const float*    beey = (const float*)d_in[20];
    const float*    We   = (const float*)d_in[21];
    const float*    be   = (const float*)d_in[22];

    float* out = (float*)d_out;
    float* oC = out;
    float* oE = out + (size_t)Bd * Ld * HFd;
    float* oL = oE + (size_t)Bd * Ld * Rd * Hd;

    cudaFuncSetAttribute(k_contract, cudaFuncAttributeMaxDynamicSharedMemorySize, SM_CONTRACT_BYTES);
    cudaFuncSetAttribute(k_normlin_h, cudaFuncAttributeMaxDynamicSharedMemorySize, SM_NORMLIN_BYTES);
    cudaFuncSetAttribute(k_edge_h, cudaFuncAttributeMaxDynamicSharedMemorySize, SM_EDGE_BYTES);
    cudaFuncSetAttribute(k_expand, cudaFuncAttributeMaxDynamicSharedMemorySize, EXP_SMEM_BYTES);

    void* pxf = nullptr; void* pyf = nullptr; void* pWhx = nullptr; void* pWhy = nullptr;
    cudaGetSymbolAddress(&pxf, g_xf);
    cudaGetSymbolAddress(&pyf, g_yf);
    cudaGetSymbolAddress(&pWhx, g_Whx);
    cudaGetSymbolAddress(&pWhy, g_Why);

    // prep: weights + activated-A in half
    k_prep_all<<<776, 256>>>(Wc, Wca, Wex, Wey);
    k_prep_we<<<64, 512>>>(We);
    k_prep_ll<<<8192, 512>>>(ll);

    // contract (persistent, cp.async A pipeline, fp16 mma)
    k_contract<<<152, 512, SM_CONTRACT_BYTES>>>(mask, bc, gcc, bec, bca, oC);

    // expand branch
    k_normlin_h<<<32, 512, SM_NORMLIN_BYTES>>>(lig, (const __half*)pWhx, bex, gex, beex, (float*)pxf);
    k_normlin_h<<<128, 512, SM_NORMLIN_BYTES>>>(rec, (const __half*)pWhy, bey, gey, beey, (float*)pyf);
    k_expand<<<dim3(8, 8, 16), 256, EXP_SMEM_BYTES>>>(oE);

    // edge branch
    k_zero<<<4096, 256>>>((float4*)oL);
    k_edge_h<<<256, 256, SM_EDGE_BYTES>>>(lig, eb, es, ed, be, oL);
}

// round 15
// speedup vs baseline: 4.8159x; 1.0322x over previous
#include <cuda_runtime.h>
#include <cuda_fp16.h>
#include <cstdint>
#include <cstddef>

// ---------------------------------------------------------------------------
// Problem dims
// ---------------------------------------------------------------------------
constexpr int Bd = 16, Ld = 128, Rd = 512, Fd = 256, Hd = 8, FHd = 32, FEd = 64, Ed = 16384;
constexpr int HFd = 256;

__device__ __forceinline__ float lrelu(float x) { return x > 0.f ? x : 0.01f * x; }

// Scratch (device globals: allocation-free)
__device__ float  g_xf[Bd * Ld * HFd];        // 2 MB
__device__ float  g_yf[Bd * Rd * HFd];        // 8 MB
__device__ __half g_Whc[264 * 256];           // Wc||Wca half
__device__ __half g_Whx[256 * 256];           // Wex half
__device__ __half g_Why[256 * 256];           // Wey half
__device__ __half g_Weh[64 * 512];            // We half
__device__ __half g_llh[67108864];            // lrelu(ll) half, 134 MB

// fp16 m16n8k16 mma, f32 accum
__device__ __forceinline__ void mma_f16(float* c, uint32_t a0, uint32_t a1, uint32_t a2, uint32_t a3,
                                        uint32_t b0, uint32_t b1)
{
    asm volatile(
        "mma.sync.aligned.m16n8k16.row.col.f32.f16.f16.f32 "
        "{%0,%1,%2,%3}, {%4,%5,%6,%7}, {%8,%9}, {%0,%1,%2,%3};"
        : "+f"(c[0]), "+f"(c[1]), "+f"(c[2]), "+f"(c[3])
        : "r"(a0), "r"(a1), "r"(a2), "r"(a3), "r"(b0), "r"(b1));
}
__device__ __forceinline__ void ldsm_x4(uint32_t* r, uint32_t addr)
{
    asm volatile("ldmatrix.sync.aligned.m8n8.x4.shared.b16 {%0,%1,%2,%3}, [%4];"
                 : "=r"(r[0]), "=r"(r[1]), "=r"(r[2]), "=r"(r[3]) : "r"(addr));
}
__device__ __forceinline__ void ldsm_x2(uint32_t* r, uint32_t addr)
{
    asm volatile("ldmatrix.sync.aligned.m8n8.x2.shared.b16 {%0,%1}, [%2];"
                 : "=r"(r[0]), "=r"(r[1]) : "r"(addr));
}
__device__ __forceinline__ uint32_t smem_u32(const void* p) {
    uint32_t a;
    asm("{ .reg .u64 t; cvta.to.shared.u64 t, %1; cvt.u32.u64 %0, t; }" : "=r"(a) : "l"(p));
    return a;
}
#define CP_ASYNC16(dst, src) \
    asm volatile("cp.async.cg.shared.global [%0], [%1], 16;" :: "r"(dst), "l"(src))
#define CP_COMMIT() asm volatile("cp.async.commit_group;")
#define CP_WAIT0()  asm volatile("cp.async.wait_group 0;")

// ---------------------------------------------------------------------------
// Prep kernels
// ---------------------------------------------------------------------------
__global__ void __launch_bounds__(256)
k_prep_all(const float* __restrict__ Wc, const float* __restrict__ Wca,
           const float* __restrict__ Wex, const float* __restrict__ Wey)
{
    int n = blockIdx.x, k = threadIdx.x;
    const float* src; __half* dst;
    if (n < 264) {
        src = (n < 256) ? (Wc + (size_t)n * 256) : (Wca + (size_t)(n - 256) * 256);
        dst = g_Whc + (size_t)n * 256;
    } else if (n < 520) {
        src = Wex + (size_t)(n - 264) * 256;
        dst = g_Whx + (size_t)(n - 264) * 256;
    } else {
        src = Wey + (size_t)(n - 520) * 256;
        dst = g_Why + (size_t)(n - 520) * 256;
    }
    dst[k] = __float2half_rn(src[k]);
}

__global__ void __launch_bounds__(512)
k_prep_we(const float* __restrict__ We)
{
    int i = blockIdx.x * 512 + threadIdx.x;
    g_Weh[i] = __float2half_rn(We[i]);
}

// lrelu(ll) -> half. lane-contiguous float4 granules.
__global__ void __launch_bounds__(512)
k_prep_ll(const float* __restrict__ ll)
{
    size_t base = (size_t)blockIdx.x * 2048 + threadIdx.x;
#pragma unroll
    for (int it = 0; it < 4; it++) {
        size_t g = base + (size_t)it * 512;
        float4 v = *(const float4*)(ll + g * 4);
        __half2 h01 = __floats2half2_rn(lrelu(v.x), lrelu(v.y));
        __half2 h23 = __floats2half2_rn(lrelu(v.z), lrelu(v.w));
        uint2 u;
        u.x = *(uint32_t*)&h01; u.y = *(uint32_t*)&h23;
        *(uint2*)(g_llh + g * 4) = u;
    }
}

// ---------------------------------------------------------------------------
// Contract kernel: PERSISTENT, A via cp.async pipeline, B resident,
// paired ldmatrix.x4 B fragments, fp16 mma.
// ---------------------------------------------------------------------------
constexpr uint32_t CSA_B  = 0;          // half [128][264]  row stride 528 B
constexpr uint32_t CSB_B  = 67584;      // half [264][264]  row stride 528 B
constexpr uint32_t CLG_B  = 206976;     // f32 [128][8]
constexpr uint32_t CMU_B  = 211072;     // f32 [128]
constexpr uint32_t CRS_B  = 211584;     // f32 [128]
constexpr uint32_t CSP_B  = 212096;     // f32 [128][4]
constexpr uint32_t CSQ_B  = 214144;     // f32 [128][4]
constexpr uint32_t CCP_B  = 216192;     // f32 [4][256]
constexpr uint32_t CG_B   = 220288;     // f32 [256]
constexpr uint32_t CBE_B  = 221312;     // f32 [256]
constexpr uint32_t CBC_B  = 222336;     // f32 [256]
constexpr uint32_t CBCA_B = 223360;     // f32 [8]
constexpr uint32_t CSUM_B = 223392;     // f32 [8]
constexpr int SM_CONTRACT_BYTES = 223424;
constexpr int N_TILES = Bd * Ld;        // 2048

__device__ __forceinline__ void c_stage_a(uint32_t smb, int t, int tile)
{
#pragma unroll
    for (int s = 0; s < 8; s++) {
        int m = t + s * 512;
        int y = m >> 5, k16 = m & 31;
        const __half* src = g_llh + (size_t)tile * 32768 + y * 256 + k16 * 8;
        CP_ASYNC16(smb + CSA_B + y * 528 + k16 * 16, src);
    }
}

__global__ void __launch_bounds__(512, 1)
k_contract(const unsigned* __restrict__ mask,
           const float* __restrict__ bc, const float* __restrict__ gc,
           const float* __restrict__ bec, const float* __restrict__ bca,
           float* __restrict__ out)
{
    extern __shared__ char smc[];
    float* smf = (float*)smc;
    const uint32_t smb = smem_u32(smc);
    const int t = threadIdx.x;
    const int w = t >> 5, lane = t & 31;
    const int wm = w >> 2, wn = w & 3;
    const int qrow = lane >> 2, qcol = lane & 3;

    // B resident
    for (int m = t; m < 8448; m += 512) {
        int n = m >> 5, k16 = m & 31;
        CP_ASYNC16(smb + CSB_B + n * 528 + k16 * 16, g_Whc + (size_t)n * 256 + k16 * 8);
    }
    c_stage_a(smb, t, blockIdx.x);
    CP_COMMIT();

    if (t < 256) {
        smf[(CG_B >> 2) + t]  = gc[t];
        smf[(CBE_B >> 2) + t] = bec[t];
        smf[(CBC_B >> 2) + t] = bc[t];
    }
    if (t < 8) smf[(CBCA_B >> 2) + t] = bca[t];

    CP_WAIT0();
    __syncthreads();

    // A frag addresses (x4: lanes 0-15 rows, 16-31 k-half)
    const uint32_t aAddr0 = smb + CSA_B + (uint32_t)(wm * 32 + (lane & 15)) * 528 + ((lane >> 4) << 4);
    const uint32_t aAddr1 = aAddr0 + 16 * 528;
    // B paired-x4 address: group g=lane>>3: (g>>1) selects n8 sub-tile, (g&1) selects k-half
    const int bg = lane >> 3, blr = lane & 7;
    const uint32_t bAddr4 = smb + CSB_B
        + (uint32_t)(wn * 64 + ((bg >> 1) << 3) + blr) * 528 + ((bg & 1) << 4);
    // logits x2 (lanes 0-15)
    const uint32_t bAddrL = smb + CSB_B + (uint32_t)(256 + (lane & 7)) * 528 + (((lane >> 3) & 1) << 4);
    const int r0base = wm * 32 + qrow;

    for (int tile = blockIdx.x; tile < N_TILES; tile += gridDim.x) {
        float acc[2][9][4];
#pragma unroll
        for (int mt = 0; mt < 2; mt++)
#pragma unroll
            for (int nt = 0; nt < 9; nt++)
#pragma unroll
                for (int q = 0; q < 4; q++) acc[mt][nt][q] = 0.f;

        // ---- mainloop: 16 k-steps; 2 A x4 + 4 paired B x4 (+1 logits x2) ----
#pragma unroll 4
        for (int ks = 0; ks < 16; ks++) {
            const uint32_t ko = (uint32_t)ks * 32;
            uint32_t a0[4], a1[4];
            ldsm_x4(a0, aAddr0 + ko);
            ldsm_x4(a1, aAddr1 + ko);
            uint32_t bb[4][4];                     // pair p -> frags for nt=2p, 2p+1
#pragma unroll
            for (int p = 0; p < 4; p++)
                ldsm_x4(bb[p], bAddr4 + (uint32_t)p * (16 * 528) + ko);
#pragma unroll
            for (int p = 0; p < 4; p++) {
                mma_f16(acc[0][2 * p],     a0[0], a0[1], a0[2], a0[3], bb[p][0], bb[p][1]);
                mma_f16(acc[1][2 * p],     a1[0], a1[1], a1[2], a1[3], bb[p][0], bb[p][1]);
                mma_f16(acc[0][2 * p + 1], a0[0], a0[1], a0[2], a0[3], bb[p][2], bb[p][3]);
                mma_f16(acc[1][2 * p + 1], a1[0], a1[1], a1[2], a1[3], bb[p][2], bb[p][3]);
            }
            if (wn == 3) {
                uint32_t cL[2];
                ldsm_x2(cL, bAddrL + ko);
                mma_f16(acc[0][8], a0[0], a0[1], a0[2], a0[3], cL[0], cL[1]);
                mma_f16(acc[1][8], a1[0], a1[1], a1[2], a1[3], cL[0], cL[1]);
            }
        }

        // ---- phase 1: bias, logits, LN partials ----
#pragma unroll
        for (int mt = 0; mt < 2; mt++)
#pragma unroll
            for (int nt = 0; nt < 8; nt++) {
                int col = wn * 64 + nt * 8 + 2 * qcol;
                float b0 = smf[(CBC_B >> 2) + col], b1 = smf[(CBC_B >> 2) + col + 1];
                acc[mt][nt][0] += b0; acc[mt][nt][1] += b1;
                acc[mt][nt][2] += b0; acc[mt][nt][3] += b1;
            }
        if (wn == 3) {
            float ba0 = smf[(CBCA_B >> 2) + 2 * qcol], ba1 = smf[(CBCA_B >> 2) + 2 * qcol + 1];
#pragma unroll
            for (int mt = 0; mt < 2; mt++) {
                int r = r0base + mt * 16;
                smf[(CLG_B >> 2) + r * 8 + 2 * qcol]           = acc[mt][8][0] + ba0;
                smf[(CLG_B >> 2) + r * 8 + 2 * qcol + 1]       = acc[mt][8][1] + ba1;
                smf[(CLG_B >> 2) + (r + 8) * 8 + 2 * qcol]     = acc[mt][8][2] + ba0;
                smf[(CLG_B >> 2) + (r + 8) * 8 + 2 * qcol + 1] = acc[mt][8][3] + ba1;
            }
        }
#pragma unroll
        for (int mt = 0; mt < 2; mt++)
#pragma unroll
            for (int e = 0; e < 2; e++) {
                int r = r0base + mt * 16 + e * 8;
                int qb = e * 2;
                float s = 0.f, sq = 0.f;
#pragma unroll
                for (int nt = 0; nt < 8; nt++) {
                    float v0 = acc[mt][nt][qb], v1 = acc[mt][nt][qb + 1];
                    s += v0 + v1; sq += v0 * v0 + v1 * v1;
                }
                s  += __shfl_xor_sync(0xffffffffu, s, 1);  s  += __shfl_xor_sync(0xffffffffu, s, 2);
                sq += __shfl_xor_sync(0xffffffffu, sq, 1); sq += __shfl_xor_sync(0xffffffffu, sq, 2);
                if (qcol == 0) {
                    smf[(CSP_B >> 2) + r * 4 + wn] = s;
                    smf[(CSQ_B >> 2) + r * 4 + wn] = sq;
                }
            }
        __syncthreads();

        // issue next tile's A copy (overlaps phases 2/3)
        {
            int next = tile + gridDim.x;
            if (next < N_TILES) c_stage_a(smb, t, next);
            CP_COMMIT();
        }

        // ---- phase 2: row stats + masked softmax ----
        if (t < 128) {
            int r = t;
            float s  = smf[(CSP_B >> 2) + r * 4] + smf[(CSP_B >> 2) + r * 4 + 1]
                     + smf[(CSP_B >> 2) + r * 4 + 2] + smf[(CSP_B >> 2) + r * 4 + 3];
            float sq = smf[(CSQ_B >> 2) + r * 4] + smf[(CSQ_B >> 2) + r * 4 + 1]
                     + smf[(CSQ_B >> 2) + r * 4 + 2] + smf[(CSQ_B >> 2) + r * 4 + 3];
            float mu = s * (1.f / 256.f);
            float var = sq * (1.f / 256.f) - mu * mu;
            smf[(CMU_B >> 2) + r] = mu;
            smf[(CRS_B >> 2) + r] = rsqrtf(var + 1e-5f);
        }
        if (w >= 8) {
            int h = w - 8;
            float lv[4];
#pragma unroll
            for (int q = 0; q < 4; q++) lv[q] = smf[(CLG_B >> 2) + (lane + q * 32) * 8 + h];
            float mx = fmaxf(fmaxf(lv[0], lv[1]), fmaxf(lv[2], lv[3]));
#pragma unroll
            for (int o = 16; o; o >>= 1) mx = fmaxf(mx, __shfl_xor_sync(0xffffffffu, mx, o));
            const unsigned* mrow = mask + (size_t)tile * Ld;
            float e[4], sum = 0.f;
#pragma unroll
            for (int q = 0; q < 4; q++) {
                int y = lane + q * 32;
                float ee = (mrow[y] != 0u) ? expf(lv[q] - mx) : 0.f;
                e[q] = ee; sum += ee;
            }
#pragma unroll
            for (int o = 16; o; o >>= 1) sum += __shfl_xor_sync(0xffffffffu, sum, o);
#pragma unroll
            for (int q = 0; q < 4; q++) smf[(CLG_B >> 2) + (lane + q * 32) * 8 + h] = e[q];
            if (lane == 0) smf[(CSUM_B >> 2) + h] = sum + 1e-10f;
        }
        __syncthreads();

        // ---- phase 3: LN apply + weighted contraction ----
        {
            float psum[16];
#pragma unroll
            for (int i = 0; i < 16; i++) psum[i] = 0.f;
#pragma unroll
            for (int mt = 0; mt < 2; mt++)
#pragma unroll
                for (int e = 0; e < 2; e++) {
                    int r = r0base + mt * 16 + e * 8;
                    int qb = e * 2;
                    float mu = smf[(CMU_B >> 2) + r];
                    float rs = smf[(CRS_B >> 2) + r];
                    float a0 = smf[(CLG_B >> 2) + r * 8 + wn * 2];
                    float a1 = smf[(CLG_B >> 2) + r * 8 + wn * 2 + 1];
#pragma unroll
                    for (int nt = 0; nt < 8; nt++) {
                        int col = wn * 64 + nt * 8 + 2 * qcol;
                        float g0 = smf[(CG_B >> 2) + col],  g1 = smf[(CG_B >> 2) + col + 1];
                        float e0 = smf[(CBE_B >> 2) + col], e1 = smf[(CBE_B >> 2) + col + 1];
                        float of0 = g0 * ((acc[mt][nt][qb] - mu) * rs) + e0;
                        float of1 = g1 * ((acc[mt][nt][qb + 1] - mu) * rs) + e1;
                        float a = (nt < 4) ? a0 : a1;
                        psum[nt * 2]     += a * of0;
                        psum[nt * 2 + 1] += a * of1;
                    }
                }
#pragma unroll
            for (int i = 0; i < 16; i++) {
                psum[i] += __shfl_xor_sync(0xffffffffu, psum[i], 4);
                psum[i] += __shfl_xor_sync(0xffffffffu, psum[i], 8);
                psum[i] += __shfl_xor_sync(0xffffffffu, psum[i], 16);
            }
            if (qrow == 0) {
#pragma unroll
                for (int nt = 0; nt < 8; nt++) {
                    int col = wn * 64 + nt * 8 + 2 * qcol;
                    smf[(CCP_B >> 2) + wm * 256 + col]     = psum[nt * 2];
                    smf[(CCP_B >> 2) + wm * 256 + col + 1] = psum[nt * 2 + 1];
                }
            }
        }
        __syncthreads();

        if (t < 256) {
            int col = t, h = col >> 5;
            float v = smf[(CCP_B >> 2) + col] + smf[(CCP_B >> 2) + 256 + col]
                    + smf[(CCP_B >> 2) + 512 + col] + smf[(CCP_B >> 2) + 768 + col];
            out[(size_t)tile * HFd + col] = v / smf[(CSUM_B >> 2) + h];
        }
        CP_WAIT0();
        __syncthreads();
    }
}

// ---------------------------------------------------------------------------
// NormAndLinear via fp16 mma: 64 rows per CTA, N=256, K=256, W resident.
// ---------------------------------------------------------------------------
constexpr uint32_t NSA_B = 0;
constexpr uint32_t NSB_B = 33792;
constexpr uint32_t NMU_B = 168960;
constexpr uint32_t NRS_B = 169216;
constexpr uint32_t NSP_B = 169472;
constexpr uint32_t NSQ_B = 170496;
constexpr uint32_t NG_B  = 171520;
constexpr uint32_t NBE_B = 172544;
constexpr uint32_t NBC_B = 173568;
constexpr int SM_NORMLIN_BYTES = 174592;

__global__ void __launch_bounds__(512, 1)
k_normlin_h(const float* __restrict__ X, const __half* __restrict__ Wh,
            const float* __restrict__ bias, const float* __restrict__ g,
            const float* __restrict__ be, float* __restrict__ out)
{
    extern __shared__ char smc[];
    float* smf = (float*)smc;
    const uint32_t smb = smem_u32(smc);
    const int t = threadIdx.x;
    const int row0 = blockIdx.x * 64;
    const int w = t >> 5, lane = t & 31;
    const int wm = w >> 2, wn = w & 3;
    const int qrow = lane >> 2, qcol = lane & 3;

    for (int m = t; m < 8192; m += 512) {
        int n = m >> 5, k16 = m & 31;
        CP_ASYNC16(smb + NSB_B + n * 528 + k16 * 16, Wh + (size_t)n * 256 + k16 * 8);
    }
    CP_COMMIT();

    if (t < 256) {
        smf[(NG_B >> 2) + t]  = g[t];
        smf[(NBE_B >> 2) + t] = be[t];
        smf[(NBC_B >> 2) + t] = bias[t];
    }

#pragma unroll
    for (int s = 0; s < 8; s++) {
        int m = t + s * 512;
        int y = m >> 6, c4 = m & 63;
        float4 v = *(const float4*)(X + (size_t)(row0 + y) * Fd + c4 * 4);
        __half2 h01 = __floats2half2_rn(lrelu(v.x), lrelu(v.y));
        __half2 h23 = __floats2half2_rn(lrelu(v.z), lrelu(v.w));
        uint2 u;
        u.x = *(uint32_t*)&h01; u.y = *(uint32_t*)&h23;
        *(uint2*)(smc + NSA_B + y * 528 + c4 * 8) = u;
    }

    float acc[8][4];
#pragma unroll
    for (int nt = 0; nt < 8; nt++)
#pragma unroll
        for (int q = 0; q < 4; q++) acc[nt][q] = 0.f;

    CP_WAIT0();
    __syncthreads();

    const uint32_t aAddr0 = smb + NSA_B + (uint32_t)(wm * 16 + (lane & 15)) * 528 + ((lane >> 4) << 4);
    const int bg = lane >> 3, blr = lane & 7;
    const uint32_t bAddr4 = smb + NSB_B
        + (uint32_t)(wn * 64 + ((bg >> 1) << 3) + blr) * 528 + ((bg & 1) << 4);
    const int r0base = wm * 16 + qrow;

#pragma unroll 4
    for (int ks = 0; ks < 16; ks++) {
        const uint32_t ko = (uint32_t)ks * 32;
        uint32_t a0[4];
        ldsm_x4(a0, aAddr0 + ko);
        uint32_t bb[4][4];
#pragma unroll
        for (int p = 0; p < 4; p++)
            ldsm_x4(bb[p], bAddr4 + (uint32_t)p * (16 * 528) + ko);
#pragma unroll
        for (int p = 0; p < 4; p++) {
            mma_f16(acc[2 * p],     a0[0], a0[1], a0[2], a0[3], bb[p][0], bb[p][1]);
            mma_f16(acc[2 * p + 1], a0[0], a0[1], a0[2], a0[3], bb[p][2], bb[p][3]);
        }
    }

#pragma unroll
    for (int nt = 0; nt < 8; nt++) {
        int col = wn * 64 + nt * 8 + 2 * qcol;
        float b0 = smf[(NBC_B >> 2) + col], b1 = smf[(NBC_B >> 2) + col + 1];
        acc[nt][0] += b0; acc[nt][1] += b1;
        acc[nt][2] += b0; acc[nt][3] += b1;
    }
#pragma unroll
    for (int e = 0; e < 2; e++) {
        int r = r0base + e * 8;
        int qb = e * 2;
        float s = 0.f, sq = 0.f;
#pragma unroll
        for (int nt = 0; nt < 8; nt++) {
            float v0 = acc[nt][qb], v1 = acc[nt][qb + 1];
            s += v0 + v1; sq += v0 * v0 + v1 * v1;
        }
        s  += __shfl_xor_sync(0xffffffffu, s, 1);  s  += __shfl_xor_sync(0xffffffffu, s, 2);
        sq += __shfl_xor_sync(0xffffffffu, sq, 1); sq += __shfl_xor_sync(0xffffffffu, sq, 2);
        if (qcol == 0) {
            smf[(NSP_B >> 2) + r * 4 + wn] = s;
            smf[(NSQ_B >> 2) + r * 4 + wn] = sq;
        }
    }
    __syncthreads();

    if (t < 64) {
        int r = t;
        float s  = smf[(NSP_B >> 2) + r * 4] + smf[(NSP_B >> 2) + r * 4 + 1]
                 + smf[(NSP_B >> 2) + r * 4 + 2] + smf[(NSP_B >> 2) + r * 4 + 3];
        float sq = smf[(NSQ_B >> 2) + r * 4] + smf[(NSQ_B >> 2) + r * 4 + 1]
                 + smf[(NSQ_B >> 2) + r * 4 + 2] + smf[(NSQ_B >> 2) + r * 4 + 3];
        float mu = s * (1.f / 256.f);
        float var = sq * (1.f / 256.f) - mu * mu;
        smf[(NMU_B >> 2) + r] = mu;
        smf[(NRS_B >> 2) + r] = rsqrtf(var + 1e-5f);
    }
    __syncthreads();

#pragma unroll
    for (int e = 0; e < 2; e++) {
        int r = r0base + e * 8;
        int qb = e * 2;
        float mu = smf[(NMU_B >> 2) + r];
        float rs = smf[(NRS_B >> 2) + r];
        float* orow = out + (size_t)(row0 + r) * 256;
#pragma unroll
        for (int nt = 0; nt < 8; nt++) {
            int col = wn * 64 + nt * 8 + 2 * qcol;
            float g0 = smf[(NG_B >> 2) + col],  g1 = smf[(NG_B >> 2) + col + 1];
            float e0 = smf[(NBE_B >> 2) + col], e1 = smf[(NBE_B >> 2) + col + 1];
            float2 o;
            o.x = g0 * ((acc[nt][qb] - mu) * rs) + e0;
            o.y = g1 * ((acc[nt][qb + 1] - mu) * rs) + e1;
            *(float2*)(orow + col) = o;
        }
    }
}

// ---------------------------------------------------------------------------
// Expand: out[b,x,y,h] = sum_f xf[b,x,h,f]*yf[b,y,h,f]
// ---------------------------------------------------------------------------
constexpr int EXP_SMEM_FLOATS = 16 * 8 * 36 + 64 * 8 * 36;
constexpr int EXP_SMEM_BYTES  = EXP_SMEM_FLOATS * 4;

__global__ void __launch_bounds__(256)
k_expand(float* __restrict__ out)
{
    extern __shared__ float es[];
    float* sX = es;
    float* sY = es + 16 * 8 * 36;
    const int t = threadIdx.x;
    const int x0 = blockIdx.x * 16, y0 = blockIdx.y * 64, b = blockIdx.z;

#pragma unroll
    for (int s = 0; s < 4; s++) {
        int m = t + s * 256;
        int xi = m >> 6, c = (m & 63) * 4;
        int h = c >> 5, f = c & 31;
        float4 v = *(const float4*)(g_xf + (size_t)(b * Ld + x0 + xi) * HFd + c);
        float* d = &sX[(xi * 8 + h) * 36 + f];
        d[0] = v.x; d[1] = v.y; d[2] = v.z; d[3] = v.w;
    }
#pragma unroll
    for (int s = 0; s < 16; s++) {
        int m = t + s * 256;
        int yi = m >> 6, c = (m & 63) * 4;
        int h = c >> 5, f = c & 31;
        float4 v = *(const float4*)(g_yf + (size_t)(b * Rd + y0 + yi) * HFd + c);
        float* d = &sY[(yi * 8 + h) * 36 + f];
        d[0] = v.x; d[1] = v.y; d[2] = v.z; d[3] = v.w;
    }
    __syncthreads();

    const int h = t & 7, yy = t >> 3;
    float acc[2][16];
#pragma unroll
    for (int p = 0; p < 2; p++)
#pragma unroll
        for (int xi = 0; xi < 16; xi++) acc[p][xi] = 0.f;
#pragma unroll
    for (int f4 = 0; f4 < 32; f4 += 4) {
        float4 yv0 = *(const float4*)&sY[(yy * 8 + h) * 36 + f4];
        float4 yv1 = *(const float4*)&sY[((yy + 32) * 8 + h) * 36 + f4];
#pragma unroll
        for (int xi = 0; xi < 16; xi++) {
            float4 xv = *(const float4*)&sX[(xi * 8 + h) * 36 + f4];
            acc[0][xi] += xv.x * yv0.x + xv.y * yv0.y + xv.z * yv0.z + xv.w * yv0.w;
            acc[1][xi] += xv.x * yv1.x + xv.y * yv1.y + xv.z * yv1.z + xv.w * yv1.w;
        }
    }
#pragma unroll
    for (int xi = 0; xi < 16; xi++) {
        out[((size_t)(b * Ld + x0 + xi) * Rd + y0 + yy) * Hd + h]      = acc[0][xi];
        out[((size_t)(b * Ld + x0 + xi) * Rd + y0 + yy + 32) * Hd + h] = acc[1][xi];
    }
}

// ---------------------------------------------------------------------------
// Zero llf region — lane-contiguous float4 stores.
// ---------------------------------------------------------------------------
__global__ void __launch_bounds__(256)
k_zero(float4* __restrict__ p)
{
    size_t base = (size_t)blockIdx.x * 1024 + threadIdx.x;
#pragma unroll
    for (int i = 0; i < 4; i++) p[base + i * 256] = make_float4(0.f, 0.f, 0.f, 0.f);
}

// ---------------------------------------------------------------------------
// Edge via fp16 mma: 256 CTAs x 64 edges.
// ---------------------------------------------------------------------------
constexpr uint32_t ESA_B = 0;
constexpr uint32_t ESB_B = 66560;
constexpr int SM_EDGE_BYTES = 133120;

__global__ void __launch_bounds__(256, 1)
k_edge_h(const float* __restrict__ lig, const int* __restrict__ eb,
         const int* __restrict__ es, const int* __restrict__ ed,
         const float* __restrict__ be, float* __restrict__ llf)
{
    extern __shared__ char smc[];
    const uint32_t smb = smem_u32(smc);
    const int t = threadIdx.x;
    const int w = t >> 5, lane = t & 31;
    const int wm = w >> 1, wn = w & 1;
    const int qrow = lane >> 2, qcol = lane & 3;
    const int e0 = blockIdx.x * 64;

#pragma unroll
    for (int s = 0; s < 16; s++) {
        int m = t + s * 256;
        int n = m >> 6, k16 = m & 63;
        CP_ASYNC16(smb + ESB_B + n * 1040 + k16 * 16, g_Weh + (size_t)n * 512 + k16 * 8);
    }
    CP_COMMIT();

#pragma unroll
    for (int s = 0; s < 32; s++) {
        int m = t + s * 256;
        int e = m >> 7, kq = m & 127;
        int ee = e0 + e;
        int bb = eb[ee];
        int row = (kq < 64) ? es[ee] : ed[ee];
        int c4  = (kq < 64) ? kq : (kq - 64);
        float4 v = *(const float4*)(lig + (size_t)(bb * Ld + row) * Fd + c4 * 4);
        __half2 h01 = __floats2half2_rn(v.x, v.y);
        __half2 h23 = __floats2half2_rn(v.z, v.w);
        uint2 u;
        u.x = *(uint32_t*)&h01; u.y = *(uint32_t*)&h23;
        *(uint2*)(smc + ESA_B + e * 1040 + kq * 8) = u;
    }
    CP_WAIT0();
    __syncthreads();

    const uint32_t aAddr = smb + ESA_B + (uint32_t)(wm * 16 + (lane & 15)) * 1040 + ((lane >> 4) << 4);
    const uint32_t bAddr = smb + ESB_B + (uint32_t)(wn * 32 + (lane & 7)) * 1040 + (((lane >> 3) & 1) << 4);

    float acc[4][4];
#pragma unroll
    for (int nt = 0; nt < 4; nt++)
#pragma unroll
        for (int q = 0; q < 4; q++) acc[nt][q] = 0.f;

#pragma unroll 4
    for (int ks = 0; ks < 32; ks++) {
        const uint32_t ko = (uint32_t)ks * 32;
        uint32_t a0[4];
        ldsm_x4(a0, aAddr + ko);
        uint32_t bb2[4][2];
#pragma unroll
        for (int nt = 0; nt < 4; nt++)
            ldsm_x2(bb2[nt], bAddr + (uint32_t)nt * (8 * 1040) + ko);
#pragma unroll
        for (int nt = 0; nt < 4; nt++)
            mma_f16(acc[nt], a0[0], a0[1], a0[2], a0[3], bb2[nt][0], bb2[nt][1]);
    }

#pragma unroll
    for (int e = 0; e < 2; e++) {
        int er = e0 + wm * 16 + qrow + e * 8;
        int bb = eb[er], ss = es[er], dd = ed[er];
        float* base = llf + ((size_t)(bb * Ld + ss) * Ld + dd) * FEd;
        int qb = e * 2;
#pragma unroll
        for (int nt = 0; nt < 4; nt++) {
            int col = wn * 32 + nt * 8 + 2 * qcol;
            atomicAdd(base + col,     lrelu(acc[nt][qb]     + be[col]));
            atomicAdd(base + col + 1, lrelu(acc[nt][qb + 1] + be[col + 1]));
        }
    }
}

// ---------------------------------------------------------------------------
// Launch
// ---------------------------------------------------------------------------
extern "C" void kernel_launch(void* const* d_in, const int* in_sizes, int n_in,
                              void* d_out, int out_size)
{
    const float*    ll   = (const float*)d_in[0];
    const float*    lig  = (const float*)d_in[1];
    const float*    rec  = (const float*)d_in[2];
    const unsigned* mask = (const unsigned*)d_in[3];
    const int*      eb   = (const int*)d_in[4];
    const int*      es   = (const int*)d_in[5];
    const int*      ed   = (const int*)d_in[6];
    const float*    Wc   = (const float*)d_in[7];
    const float*    bc   = (const float*)d_in[8];
    const float*    gcc  = (const float*)d_in[9];
    const float*    bec  = (const float*)d_in[10];
    const float*    Wca  = (const float*)d_in[11];
    const float*    bca  = (const float*)d_in[12];
    const float*    Wex  = (const float*)d_in[13];
    const float*    bex  = (const float*)d_in[14];
    const float*    gex  = (const float*)d_in[15];
    const float*    beex = (const float*)d_in[16];
    const float*    Wey  = (const float*)d_in[17];
    const float*    bey  = (const float*)d_in[18];
    const float*    gey  = (const float*)d_in[19];
    const float*    beey = (const float*)d_in[20];
    const float*    We   = (const float*)d_in[21];
    const float*    be   = (const float*)d_in[22];

    float* out = (float*)d_out;
    float* oC = out;
    float* oE = out + (size_t)Bd * Ld * HFd;
    float* oL = oE + (size_t)Bd * Ld * Rd * Hd;

    cudaFuncSetAttribute(k_contract, cudaFuncAttributeMaxDynamicSharedMemorySize, SM_CONTRACT_BYTES);
    cudaFuncSetAttribute(k_normlin_h, cudaFuncAttributeMaxDynamicSharedMemorySize, SM_NORMLIN_BYTES);
    cudaFuncSetAttribute(k_edge_h, cudaFuncAttributeMaxDynamicSharedMemorySize, SM_EDGE_BYTES);
    cudaFuncSetAttribute(k_expand, cudaFuncAttributeMaxDynamicSharedMemorySize, EXP_SMEM_BYTES);

    void* pxf = nullptr; void* pyf = nullptr; void* pWhx = nullptr; void* pWhy = nullptr;
    cudaGetSymbolAddress(&pxf, g_xf);
    cudaGetSymbolAddress(&pyf, g_yf);
    cudaGetSymbolAddress(&pWhx, g_Whx);
    cudaGetSymbolAddress(&pWhy, g_Why);

    // prep: weights + activated-A in half
    k_prep_all<<<776, 256>>>(Wc, Wca, Wex, Wey);
    k_prep_we<<<64, 512>>>(We);
    k_prep_ll<<<8192, 512>>>(ll);

    // contract (persistent, cp.async A pipeline, fp16 mma, paired x4 B frags)
    k_contract<<<152, 512, SM_CONTRACT_BYTES>>>(mask, bc, gcc, bec, bca, oC);

    // expand branch
    k_normlin_h<<<32, 512, SM_NORMLIN_BYTES>>>(lig, (const __half*)pWhx, bex, gex, beex, (float*)pxf);
    k_normlin_h<<<128, 512, SM_NORMLIN_BYTES>>>(rec, (const __half*)pWhy, bey, gey, beey, (float*)pyf);
    k_expand<<<dim3(8, 8, 16), 256, EXP_SMEM_BYTES>>>(oE);

    // edge branch
    k_zero<<<4096, 256>>>((float4*)oL);
    k_edge_h<<<256, 256, SM_EDGE_BYTES>>>(lig, eb, es, ed, be, oL);
}

// round 16
// speedup vs baseline: 5.2696x; 1.0942x over previous
#include <cuda_runtime.h>
#include <cuda_fp16.h>
#include <cstdint>
#include <cstddef>

// ---------------------------------------------------------------------------
// Problem dims
// ---------------------------------------------------------------------------
constexpr int Bd = 16, Ld = 128, Rd = 512, Fd = 256, Hd = 8, FHd = 32, FEd = 64, Ed = 16384;
constexpr int HFd = 256;

__device__ __forceinline__ float lrelu(float x) { return x > 0.f ? x : 0.01f * x; }

// Scratch (device globals: allocation-free)
__device__ float  g_xf[Bd * Ld * HFd];        // 2 MB
__device__ float  g_yf[Bd * Rd * HFd];        // 8 MB
__device__ __half g_Whc[264 * 256];           // Wc||Wca half
__device__ __half g_Whx[256 * 256];           // Wex half
__device__ __half g_Why[256 * 256];           // Wey half
__device__ __half g_Weh[64 * 512];            // We half
__device__ __half g_llh[67108864];            // lrelu(ll) half, 134 MB

// fp16 m16n8k16 mma, f32 accum
__device__ __forceinline__ void mma_f16(float* c, uint32_t a0, uint32_t a1, uint32_t a2, uint32_t a3,
                                        uint32_t b0, uint32_t b1)
{
    asm volatile(
        "mma.sync.aligned.m16n8k16.row.col.f32.f16.f16.f32 "
        "{%0,%1,%2,%3}, {%4,%5,%6,%7}, {%8,%9}, {%0,%1,%2,%3};"
        : "+f"(c[0]), "+f"(c[1]), "+f"(c[2]), "+f"(c[3])
        : "r"(a0), "r"(a1), "r"(a2), "r"(a3), "r"(b0), "r"(b1));
}
__device__ __forceinline__ void ldsm_x4(uint32_t* r, uint32_t addr)
{
    asm volatile("ldmatrix.sync.aligned.m8n8.x4.shared.b16 {%0,%1,%2,%3}, [%4];"
                 : "=r"(r[0]), "=r"(r[1]), "=r"(r[2]), "=r"(r[3]) : "r"(addr));
}
__device__ __forceinline__ void ldsm_x2(uint32_t* r, uint32_t addr)
{
    asm volatile("ldmatrix.sync.aligned.m8n8.x2.shared.b16 {%0,%1}, [%2];"
                 : "=r"(r[0]), "=r"(r[1]) : "r"(addr));
}
__device__ __forceinline__ uint32_t smem_u32(const void* p) {
    uint32_t a;
    asm("{ .reg .u64 t; cvta.to.shared.u64 t, %1; cvt.u32.u64 %0, t; }" : "=r"(a) : "l"(p));
    return a;
}
#define CP_ASYNC16(dst, src) \
    asm volatile("cp.async.cg.shared.global [%0], [%1], 16;" :: "r"(dst), "l"(src))
#define CP_COMMIT() asm volatile("cp.async.commit_group;")
#define CP_WAIT0()  asm volatile("cp.async.wait_group 0;")

// ---------------------------------------------------------------------------
// Prep kernels
// ---------------------------------------------------------------------------
__global__ void __launch_bounds__(256)
k_prep_all(const float* __restrict__ Wc, const float* __restrict__ Wca,
           const float* __restrict__ Wex, const float* __restrict__ Wey,
           const float* __restrict__ We)
{
    int n = blockIdx.x, k = threadIdx.x;
    if (n >= 776) {   // We rows: 64 rows of 512 -> blocks 776..903, 256 elems each
        int m = (n - 776) * 256 + k;
        g_Weh[m] = __float2half_rn(We[m]);
        return;
    }
    const float* src; __half* dst;
    if (n < 264) {
        src = (n < 256) ? (Wc + (size_t)n * 256) : (Wca + (size_t)(n - 256) * 256);
        dst = g_Whc + (size_t)n * 256;
    } else if (n < 520) {
        src = Wex + (size_t)(n - 264) * 256;
        dst = g_Whx + (size_t)(n - 264) * 256;
    } else {
        src = Wey + (size_t)(n - 520) * 256;
        dst = g_Why + (size_t)(n - 520) * 256;
    }
    dst[k] = __float2half_rn(src[k]);
}

// lrelu(ll) -> half. lane-contiguous float4 granules.
__global__ void __launch_bounds__(512)
k_prep_ll(const float* __restrict__ ll)
{
    size_t base = (size_t)blockIdx.x * 2048 + threadIdx.x;
#pragma unroll
    for (int it = 0; it < 4; it++) {
        size_t g = base + (size_t)it * 512;
        float4 v = *(const float4*)(ll + g * 4);
        __half2 h01 = __floats2half2_rn(lrelu(v.x), lrelu(v.y));
        __half2 h23 = __floats2half2_rn(lrelu(v.z), lrelu(v.w));
        uint2 u;
        u.x = *(uint32_t*)&h01; u.y = *(uint32_t*)&h23;
        *(uint2*)(g_llh + g * 4) = u;
    }
}

// ---------------------------------------------------------------------------
// Contract kernel: PERSISTENT, A via cp.async pipeline, B resident,
// paired ldmatrix.x4 B fragments, fp16 mma.
// ---------------------------------------------------------------------------
constexpr uint32_t CSA_B  = 0;          // half [128][264]  row stride 528 B
constexpr uint32_t CSB_B  = 67584;      // half [264][264]  row stride 528 B
constexpr uint32_t CLG_B  = 206976;     // f32 [128][8]
constexpr uint32_t CMU_B  = 211072;     // f32 [128]
constexpr uint32_t CRS_B  = 211584;     // f32 [128]
constexpr uint32_t CSP_B  = 212096;     // f32 [128][4]
constexpr uint32_t CSQ_B  = 214144;     // f32 [128][4]
constexpr uint32_t CCP_B  = 216192;     // f32 [4][256]
constexpr uint32_t CG_B   = 220288;     // f32 [256]
constexpr uint32_t CBE_B  = 221312;     // f32 [256]
constexpr uint32_t CBC_B  = 222336;     // f32 [256]
constexpr uint32_t CBCA_B = 223360;     // f32 [8]
constexpr uint32_t CSUM_B = 223392;     // f32 [8]
constexpr int SM_CONTRACT_BYTES = 223424;
constexpr int N_TILES = Bd * Ld;        // 2048

__device__ __forceinline__ void c_stage_a(uint32_t smb, int t, int tile)
{
#pragma unroll
    for (int s = 0; s < 8; s++) {
        int m = t + s * 512;
        int y = m >> 5, k16 = m & 31;
        const __half* src = g_llh + (size_t)tile * 32768 + y * 256 + k16 * 8;
        CP_ASYNC16(smb + CSA_B + y * 528 + k16 * 16, src);
    }
}

__global__ void __launch_bounds__(512, 1)
k_contract(const unsigned* __restrict__ mask,
           const float* __restrict__ bc, const float* __restrict__ gc,
           const float* __restrict__ bec, const float* __restrict__ bca,
           float* __restrict__ out)
{
    extern __shared__ char smc[];
    float* smf = (float*)smc;
    const uint32_t smb = smem_u32(smc);
    const int t = threadIdx.x;
    const int w = t >> 5, lane = t & 31;
    const int wm = w >> 2, wn = w & 3;
    const int qrow = lane >> 2, qcol = lane & 3;

    // B resident
    for (int m = t; m < 8448; m += 512) {
        int n = m >> 5, k16 = m & 31;
        CP_ASYNC16(smb + CSB_B + n * 528 + k16 * 16, g_Whc + (size_t)n * 256 + k16 * 8);
    }
    c_stage_a(smb, t, blockIdx.x);
    CP_COMMIT();

    if (t < 256) {
        smf[(CG_B >> 2) + t]  = gc[t];
        smf[(CBE_B >> 2) + t] = bec[t];
        smf[(CBC_B >> 2) + t] = bc[t];
    }
    if (t < 8) smf[(CBCA_B >> 2) + t] = bca[t];

    CP_WAIT0();
    __syncthreads();

    const uint32_t aAddr0 = smb + CSA_B + (uint32_t)(wm * 32 + (lane & 15)) * 528 + ((lane >> 4) << 4);
    const uint32_t aAddr1 = aAddr0 + 16 * 528;
    const int bg = lane >> 3, blr = lane & 7;
    const uint32_t bAddr4 = smb + CSB_B
        + (uint32_t)(wn * 64 + ((bg >> 1) << 3) + blr) * 528 + ((bg & 1) << 4);
    const uint32_t bAddrL = smb + CSB_B + (uint32_t)(256 + (lane & 7)) * 528 + (((lane >> 3) & 1) << 4);
    const int r0base = wm * 32 + qrow;

    for (int tile = blockIdx.x; tile < N_TILES; tile += gridDim.x) {
        float acc[2][9][4];
#pragma unroll
        for (int mt = 0; mt < 2; mt++)
#pragma unroll
            for (int nt = 0; nt < 9; nt++)
#pragma unroll
                for (int q = 0; q < 4; q++) acc[mt][nt][q] = 0.f;

#pragma unroll 4
        for (int ks = 0; ks < 16; ks++) {
            const uint32_t ko = (uint32_t)ks * 32;
            uint32_t a0[4], a1[4];
            ldsm_x4(a0, aAddr0 + ko);
            ldsm_x4(a1, aAddr1 + ko);
            uint32_t bb[4][4];
#pragma unroll
            for (int p = 0; p < 4; p++)
                ldsm_x4(bb[p], bAddr4 + (uint32_t)p * (16 * 528) + ko);
#pragma unroll
            for (int p = 0; p < 4; p++) {
                mma_f16(acc[0][2 * p],     a0[0], a0[1], a0[2], a0[3], bb[p][0], bb[p][1]);
                mma_f16(acc[1][2 * p],     a1[0], a1[1], a1[2], a1[3], bb[p][0], bb[p][1]);
                mma_f16(acc[0][2 * p + 1], a0[0], a0[1], a0[2], a0[3], bb[p][2], bb[p][3]);
                mma_f16(acc[1][2 * p + 1], a1[0], a1[1], a1[2], a1[3], bb[p][2], bb[p][3]);
            }
            if (wn == 3) {
                uint32_t cL[2];
                ldsm_x2(cL, bAddrL + ko);
                mma_f16(acc[0][8], a0[0], a0[1], a0[2], a0[3], cL[0], cL[1]);
                mma_f16(acc[1][8], a1[0], a1[1], a1[2], a1[3], cL[0], cL[1]);
            }
        }

        // ---- phase 1: bias, logits, LN partials ----
#pragma unroll
        for (int mt = 0; mt < 2; mt++)
#pragma unroll
            for (int nt = 0; nt < 8; nt++) {
                int col = wn * 64 + nt * 8 + 2 * qcol;
                float b0 = smf[(CBC_B >> 2) + col], b1 = smf[(CBC_B >> 2) + col + 1];
                acc[mt][nt][0] += b0; acc[mt][nt][1] += b1;
                acc[mt][nt][2] += b0; acc[mt][nt][3] += b1;
            }
        if (wn == 3) {
            float ba0 = smf[(CBCA_B >> 2) + 2 * qcol], ba1 = smf[(CBCA_B >> 2) + 2 * qcol + 1];
#pragma unroll
            for (int mt = 0; mt < 2; mt++) {
                int r = r0base + mt * 16;
                smf[(CLG_B >> 2) + r * 8 + 2 * qcol]           = acc[mt][8][0] + ba0;
                smf[(CLG_B >> 2) + r * 8 + 2 * qcol + 1]       = acc[mt][8][1] + ba1;
                smf[(CLG_B >> 2) + (r + 8) * 8 + 2 * qcol]     = acc[mt][8][2] + ba0;
                smf[(CLG_B >> 2) + (r + 8) * 8 + 2 * qcol + 1] = acc[mt][8][3] + ba1;
            }
        }
#pragma unroll
        for (int mt = 0; mt < 2; mt++)
#pragma unroll
            for (int e = 0; e < 2; e++) {
                int r = r0base + mt * 16 + e * 8;
                int qb = e * 2;
                float s = 0.f, sq = 0.f;
#pragma unroll
                for (int nt = 0; nt < 8; nt++) {
                    float v0 = acc[mt][nt][qb], v1 = acc[mt][nt][qb + 1];
                    s += v0 + v1; sq += v0 * v0 + v1 * v1;
                }
                s  += __shfl_xor_sync(0xffffffffu, s, 1);  s  += __shfl_xor_sync(0xffffffffu, s, 2);
                sq += __shfl_xor_sync(0xffffffffu, sq, 1); sq += __shfl_xor_sync(0xffffffffu, sq, 2);
                if (qcol == 0) {
                    smf[(CSP_B >> 2) + r * 4 + wn] = s;
                    smf[(CSQ_B >> 2) + r * 4 + wn] = sq;
                }
            }
        __syncthreads();

        {
            int next = tile + gridDim.x;
            if (next < N_TILES) c_stage_a(smb, t, next);
            CP_COMMIT();
        }

        // ---- phase 2: row stats + masked softmax ----
        if (t < 128) {
            int r = t;
            float s  = smf[(CSP_B >> 2) + r * 4] + smf[(CSP_B >> 2) + r * 4 + 1]
                     + smf[(CSP_B >> 2) + r * 4 + 2] + smf[(CSP_B >> 2) + r * 4 + 3];
            float sq = smf[(CSQ_B >> 2) + r * 4] + smf[(CSQ_B >> 2) + r * 4 + 1]
                     + smf[(CSQ_B >> 2) + r * 4 + 2] + smf[(CSQ_B >> 2) + r * 4 + 3];
            float mu = s * (1.f / 256.f);
            float var = sq * (1.f / 256.f) - mu * mu;
            smf[(CMU_B >> 2) + r] = mu;
            smf[(CRS_B >> 2) + r] = rsqrtf(var + 1e-5f);
        }
        if (w >= 8) {
            int h = w - 8;
            float lv[4];
#pragma unroll
            for (int q = 0; q < 4; q++) lv[q] = smf[(CLG_B >> 2) + (lane + q * 32) * 8 + h];
            float mx = fmaxf(fmaxf(lv[0], lv[1]), fmaxf(lv[2], lv[3]));
#pragma unroll
            for (int o = 16; o; o >>= 1) mx = fmaxf(mx, __shfl_xor_sync(0xffffffffu, mx, o));
            const unsigned* mrow = mask + (size_t)tile * Ld;
            float e[4], sum = 0.f;
#pragma unroll
            for (int q = 0; q < 4; q++) {
                int y = lane + q * 32;
                float ee = (mrow[y] != 0u) ? expf(lv[q] - mx) : 0.f;
                e[q] = ee; sum += ee;
            }
#pragma unroll
            for (int o = 16; o; o >>= 1) sum += __shfl_xor_sync(0xffffffffu, sum, o);
#pragma unroll
            for (int q = 0; q < 4; q++) smf[(CLG_B >> 2) + (lane + q * 32) * 8 + h] = e[q];
            if (lane == 0) smf[(CSUM_B >> 2) + h] = sum + 1e-10f;
        }
        __syncthreads();

        // ---- phase 3: LN apply + weighted contraction ----
        {
            float psum[16];
#pragma unroll
            for (int i = 0; i < 16; i++) psum[i] = 0.f;
#pragma unroll
            for (int mt = 0; mt < 2; mt++)
#pragma unroll
                for (int e = 0; e < 2; e++) {
                    int r = r0base + mt * 16 + e * 8;
                    int qb = e * 2;
                    float mu = smf[(CMU_B >> 2) + r];
                    float rs = smf[(CRS_B >> 2) + r];
                    float a0 = smf[(CLG_B >> 2) + r * 8 + wn * 2];
                    float a1 = smf[(CLG_B >> 2) + r * 8 + wn * 2 + 1];
#pragma unroll
                    for (int nt = 0; nt < 8; nt++) {
                        int col = wn * 64 + nt * 8 + 2 * qcol;
                        float g0 = smf[(CG_B >> 2) + col],  g1 = smf[(CG_B >> 2) + col + 1];
                        float e0 = smf[(CBE_B >> 2) + col], e1 = smf[(CBE_B >> 2) + col + 1];
                        float of0 = g0 * ((acc[mt][nt][qb] - mu) * rs) + e0;
                        float of1 = g1 * ((acc[mt][nt][qb + 1] - mu) * rs) + e1;
                        float a = (nt < 4) ? a0 : a1;
                        psum[nt * 2]     += a * of0;
                        psum[nt * 2 + 1] += a * of1;
                    }
                }
#pragma unroll
            for (int i = 0; i < 16; i++) {
                psum[i] += __shfl_xor_sync(0xffffffffu, psum[i], 4);
                psum[i] += __shfl_xor_sync(0xffffffffu, psum[i], 8);
                psum[i] += __shfl_xor_sync(0xffffffffu, psum[i], 16);
            }
            if (qrow == 0) {
#pragma unroll
                for (int nt = 0; nt < 8; nt++) {
                    int col = wn * 64 + nt * 8 + 2 * qcol;
                    smf[(CCP_B >> 2) + wm * 256 + col]     = psum[nt * 2];
                    smf[(CCP_B >> 2) + wm * 256 + col + 1] = psum[nt * 2 + 1];
                }
            }
        }
        __syncthreads();

        if (t < 256) {
            int col = t, h = col >> 5;
            float v = smf[(CCP_B >> 2) + col] + smf[(CCP_B >> 2) + 256 + col]
                    + smf[(CCP_B >> 2) + 512 + col] + smf[(CCP_B >> 2) + 768 + col];
            out[(size_t)tile * HFd + col] = v / smf[(CSUM_B >> 2) + h];
        }
        CP_WAIT0();
        __syncthreads();
    }
}

// ---------------------------------------------------------------------------
// NormAndLinear via fp16 mma: 64 rows per CTA, N=256, K=256, W resident.
// ---------------------------------------------------------------------------
constexpr uint32_t NSA_B = 0;
constexpr uint32_t NSB_B = 33792;
constexpr uint32_t NMU_B = 168960;
constexpr uint32_t NRS_B = 169216;
constexpr uint32_t NSP_B = 169472;
constexpr uint32_t NSQ_B = 170496;
constexpr uint32_t NG_B  = 171520;
constexpr uint32_t NBE_B = 172544;
constexpr uint32_t NBC_B = 173568;
constexpr int SM_NORMLIN_BYTES = 174592;

__global__ void __launch_bounds__(512, 1)
k_normlin_h(const float* __restrict__ X, const __half* __restrict__ Wh,
            const float* __restrict__ bias, const float* __restrict__ g,
            const float* __restrict__ be, float* __restrict__ out)
{
    extern __shared__ char smc[];
    float* smf = (float*)smc;
    const uint32_t smb = smem_u32(smc);
    const int t = threadIdx.x;
    const int row0 = blockIdx.x * 64;
    const int w = t >> 5, lane = t & 31;
    const int wm = w >> 2, wn = w & 3;
    const int qrow = lane >> 2, qcol = lane & 3;

    for (int m = t; m < 8192; m += 512) {
        int n = m >> 5, k16 = m & 31;
        CP_ASYNC16(smb + NSB_B + n * 528 + k16 * 16, Wh + (size_t)n * 256 + k16 * 8);
    }
    CP_COMMIT();

    if (t < 256) {
        smf[(NG_B >> 2) + t]  = g[t];
        smf[(NBE_B >> 2) + t] = be[t];
        smf[(NBC_B >> 2) + t] = bias[t];
    }

#pragma unroll
    for (int s = 0; s < 8; s++) {
        int m = t + s * 512;
        int y = m >> 6, c4 = m & 63;
        float4 v = *(const float4*)(X + (size_t)(row0 + y) * Fd + c4 * 4);
        __half2 h01 = __floats2half2_rn(lrelu(v.x), lrelu(v.y));
        __half2 h23 = __floats2half2_rn(lrelu(v.z), lrelu(v.w));
        uint2 u;
        u.x = *(uint32_t*)&h01; u.y = *(uint32_t*)&h23;
        *(uint2*)(smc + NSA_B + y * 528 + c4 * 8) = u;
    }

    float acc[8][4];
#pragma unroll
    for (int nt = 0; nt < 8; nt++)
#pragma unroll
        for (int q = 0; q < 4; q++) acc[nt][q] = 0.f;

    CP_WAIT0();
    __syncthreads();

    const uint32_t aAddr0 = smb + NSA_B + (uint32_t)(wm * 16 + (lane & 15)) * 528 + ((lane >> 4) << 4);
    const int bg = lane >> 3, blr = lane & 7;
    const uint32_t bAddr4 = smb + NSB_B
        + (uint32_t)(wn * 64 + ((bg >> 1) << 3) + blr) * 528 + ((bg & 1) << 4);
    const int r0base = wm * 16 + qrow;

#pragma unroll 4
    for (int ks = 0; ks < 16; ks++) {
        const uint32_t ko = (uint32_t)ks * 32;
        uint32_t a0[4];
        ldsm_x4(a0, aAddr0 + ko);
        uint32_t bb[4][4];
#pragma unroll
        for (int p = 0; p < 4; p++)
            ldsm_x4(bb[p], bAddr4 + (uint32_t)p * (16 * 528) + ko);
#pragma unroll
        for (int p = 0; p < 4; p++) {
            mma_f16(acc[2 * p],     a0[0], a0[1], a0[2], a0[3], bb[p][0], bb[p][1]);
            mma_f16(acc[2 * p + 1], a0[0], a0[1], a0[2], a0[3], bb[p][2], bb[p][3]);
        }
    }

#pragma unroll
    for (int nt = 0; nt < 8; nt++) {
        int col = wn * 64 + nt * 8 + 2 * qcol;
        float b0 = smf[(NBC_B >> 2) + col], b1 = smf[(NBC_B >> 2) + col + 1];
        acc[nt][0] += b0; acc[nt][1] += b1;
        acc[nt][2] += b0; acc[nt][3] += b1;
    }
#pragma unroll
    for (int e = 0; e < 2; e++) {
        int r = r0base + e * 8;
        int qb = e * 2;
        float s = 0.f, sq = 0.f;
#pragma unroll
        for (int nt = 0; nt < 8; nt++) {
            float v0 = acc[nt][qb], v1 = acc[nt][qb + 1];
            s += v0 + v1; sq += v0 * v0 + v1 * v1;
        }
        s  += __shfl_xor_sync(0xffffffffu, s, 1);  s  += __shfl_xor_sync(0xffffffffu, s, 2);
        sq += __shfl_xor_sync(0xffffffffu, sq, 1); sq += __shfl_xor_sync(0xffffffffu, sq, 2);
        if (qcol == 0) {
            smf[(NSP_B >> 2) + r * 4 + wn] = s;
            smf[(NSQ_B >> 2) + r * 4 + wn] = sq;
        }
    }
    __syncthreads();

    if (t < 64) {
        int r = t;
        float s  = smf[(NSP_B >> 2) + r * 4] + smf[(NSP_B >> 2) + r * 4 + 1]
                 + smf[(NSP_B >> 2) + r * 4 + 2] + smf[(NSP_B >> 2) + r * 4 + 3];
        float sq = smf[(NSQ_B >> 2) + r * 4] + smf[(NSQ_B >> 2) + r * 4 + 1]
                 + smf[(NSQ_B >> 2) + r * 4 + 2] + smf[(NSQ_B >> 2) + r * 4 + 3];
        float mu = s * (1.f / 256.f);
        float var = sq * (1.f / 256.f) - mu * mu;
        smf[(NMU_B >> 2) + r] = mu;
        smf[(NRS_B >> 2) + r] = rsqrtf(var + 1e-5f);
    }
    __syncthreads();

#pragma unroll
    for (int e = 0; e < 2; e++) {
        int r = r0base + e * 8;
        int qb = e * 2;
        float mu = smf[(NMU_B >> 2) + r];
        float rs = smf[(NRS_B >> 2) + r];
        float* orow = out + (size_t)(row0 + r) * 256;
#pragma unroll
        for (int nt = 0; nt < 8; nt++) {
            int col = wn * 64 + nt * 8 + 2 * qcol;
            float g0 = smf[(NG_B >> 2) + col],  g1 = smf[(NG_B >> 2) + col + 1];
            float e0 = smf[(NBE_B >> 2) + col], e1 = smf[(NBE_B >> 2) + col + 1];
            float2 o;
            o.x = g0 * ((acc[nt][qb] - mu) * rs) + e0;
            o.y = g1 * ((acc[nt][qb + 1] - mu) * rs) + e1;
            *(float2*)(orow + col) = o;
        }
    }
}

// ---------------------------------------------------------------------------
// Expand: out[b,x,y,h] = sum_f xf[b,x,h,f]*yf[b,y,h,f]
// ---------------------------------------------------------------------------
constexpr int EXP_SMEM_FLOATS = 16 * 8 * 36 + 64 * 8 * 36;
constexpr int EXP_SMEM_BYTES  = EXP_SMEM_FLOATS * 4;

__global__ void __launch_bounds__(256)
k_expand(float* __restrict__ out)
{
    extern __shared__ float es[];
    float* sX = es;
    float* sY = es + 16 * 8 * 36;
    const int t = threadIdx.x;
    const int x0 = blockIdx.x * 16, y0 = blockIdx.y * 64, b = blockIdx.z;

#pragma unroll
    for (int s = 0; s < 4; s++) {
        int m = t + s * 256;
        int xi = m >> 6, c = (m & 63) * 4;
        int h = c >> 5, f = c & 31;
        float4 v = *(const float4*)(g_xf + (size_t)(b * Ld + x0 + xi) * HFd + c);
        float* d = &sX[(xi * 8 + h) * 36 + f];
        d[0] = v.x; d[1] = v.y; d[2] = v.z; d[3] = v.w;
    }
#pragma unroll
    for (int s = 0; s < 16; s++) {
        int m = t + s * 256;
        int yi = m >> 6, c = (m & 63) * 4;
        int h = c >> 5, f = c & 31;
        float4 v = *(const float4*)(g_yf + (size_t)(b * Rd + y0 + yi) * HFd + c);
        float* d = &sY[(yi * 8 + h) * 36 + f];
        d[0] = v.x; d[1] = v.y; d[2] = v.z; d[3] = v.w;
    }
    __syncthreads();

    const int h = t & 7, yy = t >> 3;
    float acc[2][16];
#pragma unroll
    for (int p = 0; p < 2; p++)
#pragma unroll
        for (int xi = 0; xi < 16; xi++) acc[p][xi] = 0.f;
#pragma unroll
    for (int f4 = 0; f4 < 32; f4 += 4) {
        float4 yv0 = *(const float4*)&sY[(yy * 8 + h) * 36 + f4];
        float4 yv1 = *(const float4*)&sY[((yy + 32) * 8 + h) * 36 + f4];
#pragma unroll
        for (int xi = 0; xi < 16; xi++) {
            float4 xv = *(const float4*)&sX[(xi * 8 + h) * 36 + f4];
            acc[0][xi] += xv.x * yv0.x + xv.y * yv0.y + xv.z * yv0.z + xv.w * yv0.w;
            acc[1][xi] += xv.x * yv1.x + xv.y * yv1.y + xv.z * yv1.z + xv.w * yv1.w;
        }
    }
#pragma unroll
    for (int xi = 0; xi < 16; xi++) {
        out[((size_t)(b * Ld + x0 + xi) * Rd + y0 + yy) * Hd + h]      = acc[0][xi];
        out[((size_t)(b * Ld + x0 + xi) * Rd + y0 + yy + 32) * Hd + h] = acc[1][xi];
    }
}

// ---------------------------------------------------------------------------
// Zero llf region — lane-contiguous float4 stores.
// ---------------------------------------------------------------------------
__global__ void __launch_bounds__(256)
k_zero(float4* __restrict__ p)
{
    size_t base = (size_t)blockIdx.x * 1024 + threadIdx.x;
#pragma unroll
    for (int i = 0; i < 4; i++) p[base + i * 256] = make_float4(0.f, 0.f, 0.f, 0.f);
}

// ---------------------------------------------------------------------------
// Edge via fp16 mma: 256 CTAs x 64 edges.
// ---------------------------------------------------------------------------
constexpr uint32_t ESA_B = 0;
constexpr uint32_t ESB_B = 66560;
constexpr int SM_EDGE_BYTES = 133120;

__global__ void __launch_bounds__(256, 1)
k_edge_h(const float* __restrict__ lig, const int* __restrict__ eb,
         const int* __restrict__ es, const int* __restrict__ ed,
         const float* __restrict__ be, float* __restrict__ llf)
{
    extern __shared__ char smc[];
    const uint32_t smb = smem_u32(smc);
    const int t = threadIdx.x;
    const int w = t >> 5, lane = t & 31;
    const int wm = w >> 1, wn = w & 1;
    const int qrow = lane >> 2, qcol = lane & 3;
    const int e0 = blockIdx.x * 64;

#pragma unroll
    for (int s = 0; s < 16; s++) {
        int m = t + s * 256;
        int n = m >> 6, k16 = m & 63;
        CP_ASYNC16(smb + ESB_B + n * 1040 + k16 * 16, g_Weh + (size_t)n * 512 + k16 * 8);
    }
    CP_COMMIT();

#pragma unroll
    for (int s = 0; s < 32; s++) {
        int m = t + s * 256;
        int e = m >> 7, kq = m & 127;
        int ee = e0 + e;
        int bb = eb[ee];
        int row = (kq < 64) ? es[ee] : ed[ee];
        int c4  = (kq < 64) ? kq : (kq - 64);
        float4 v = *(const float4*)(lig + (size_t)(bb * Ld + row) * Fd + c4 * 4);
        __half2 h01 = __floats2half2_rn(v.x, v.y);
        __half2 h23 = __floats2half2_rn(v.z, v.w);
        uint2 u;
        u.x = *(uint32_t*)&h01; u.y = *(uint32_t*)&h23;
        *(uint2*)(smc + ESA_B + e * 1040 + kq * 8) = u;
    }
    CP_WAIT0();
    __syncthreads();

    const uint32_t aAddr = smb + ESA_B + (uint32_t)(wm * 16 + (lane & 15)) * 1040 + ((lane >> 4) << 4);
    const uint32_t bAddr = smb + ESB_B + (uint32_t)(wn * 32 + (lane & 7)) * 1040 + (((lane >> 3) & 1) << 4);

    float acc[4][4];
#pragma unroll
    for (int nt = 0; nt < 4; nt++)
#pragma unroll
        for (int q = 0; q < 4; q++) acc[nt][q] = 0.f;

#pragma unroll 4
    for (int ks = 0; ks < 32; ks++) {
        const uint32_t ko = (uint32_t)ks * 32;
        uint32_t a0[4];
        ldsm_x4(a0, aAddr + ko);
        uint32_t bb2[4][2];
#pragma unroll
        for (int nt = 0; nt < 4; nt++)
            ldsm_x2(bb2[nt], bAddr + (uint32_t)nt * (8 * 1040) + ko);
#pragma unroll
        for (int nt = 0; nt < 4; nt++)
            mma_f16(acc[nt], a0[0], a0[1], a0[2], a0[3], bb2[nt][0], bb2[nt][1]);
    }

#pragma unroll
    for (int e = 0; e < 2; e++) {
        int er = e0 + wm * 16 + qrow + e * 8;
        int bb = eb[er], ss = es[er], dd = ed[er];
        float* base = llf + ((size_t)(bb * Ld + ss) * Ld + dd) * FEd;
        int qb = e * 2;
#pragma unroll
        for (int nt = 0; nt < 4; nt++) {
            int col = wn * 32 + nt * 8 + 2 * qcol;
            atomicAdd(base + col,     lrelu(acc[nt][qb]     + be[col]));
            atomicAdd(base + col + 1, lrelu(acc[nt][qb + 1] + be[col + 1]));
        }
    }
}

// ---------------------------------------------------------------------------
// Launch: forked multi-stream graph.
//   s0 (capture/legacy): prep_all -> prep_ll -> contract
//   s1: normlin x2 -> expand        s2: zero -> edge
// Streams/events created once on the first (uncaptured) correctness call.
// ---------------------------------------------------------------------------
extern "C" void kernel_launch(void* const* d_in, const int* in_sizes, int n_in,
                              void* d_out, int out_size)
{
    const float*    ll   = (const float*)d_in[0];
    const float*    lig  = (const float*)d_in[1];
    const float*    rec  = (const float*)d_in[2];
    const unsigned* mask = (const unsigned*)d_in[3];
    const int*      eb   = (const int*)d_in[4];
    const int*      es   = (const int*)d_in[5];
    const int*      ed   = (const int*)d_in[6];
    const float*    Wc   = (const float*)d_in[7];
    const float*    bc   = (const float*)d_in[8];
    const float*    gcc  = (const float*)d_in[9];
    const float*    bec  = (const float*)d_in[10];
    const float*    Wca  = (const float*)d_in[11];
    const float*    bca  = (const float*)d_in[12];
    const float*    Wex  = (const float*)d_in[13];
    const float*    bex  = (const float*)d_in[14];
    const float*    gex  = (const float*)d_in[15];
    const float*    beex = (const float*)d_in[16];
    const float*    Wey  = (const float*)d_in[17];
    const float*    bey  = (const float*)d_in[18];
    const float*    gey  = (const float*)d_in[19];
    const float*    beey = (const float*)d_in[20];
    const float*    We   = (const float*)d_in[21];
    const float*    be   = (const float*)d_in[22];

    float* out = (float*)d_out;
    float* oC = out;
    float* oE = out + (size_t)Bd * Ld * HFd;
    float* oL = oE + (size_t)Bd * Ld * Rd * Hd;

    cudaFuncSetAttribute(k_contract, cudaFuncAttributeMaxDynamicSharedMemorySize, SM_CONTRACT_BYTES);
    cudaFuncSetAttribute(k_normlin_h, cudaFuncAttributeMaxDynamicSharedMemorySize, SM_NORMLIN_BYTES);
    cudaFuncSetAttribute(k_edge_h, cudaFuncAttributeMaxDynamicSharedMemorySize, SM_EDGE_BYTES);
    cudaFuncSetAttribute(k_expand, cudaFuncAttributeMaxDynamicSharedMemorySize, EXP_SMEM_BYTES);

    void* pxf = nullptr; void* pyf = nullptr; void* pWhx = nullptr; void* pWhy = nullptr;
    cudaGetSymbolAddress(&pxf, g_xf);
    cudaGetSymbolAddress(&pyf, g_yf);
    cudaGetSymbolAddress(&pWhx, g_Whx);
    cudaGetSymbolAddress(&pWhy, g_Why);

    // one-time side streams + fork/join events (created on the uncaptured
    // correctness call; reused as graph dependencies during capture)
    static cudaStream_t s1 = nullptr, s2 = nullptr;
    static cudaEvent_t evPrep = nullptr, ev1 = nullptr, ev2 = nullptr;
    if (!s1) {
        cudaStreamCreateWithFlags(&s1, cudaStreamNonBlocking);
        cudaStreamCreateWithFlags(&s2, cudaStreamNonBlocking);
        cudaEventCreateWithFlags(&evPrep, cudaEventDisableTiming);
        cudaEventCreateWithFlags(&ev1, cudaEventDisableTiming);
        cudaEventCreateWithFlags(&ev2, cudaEventDisableTiming);
    }

    // s0: weight preps, then fork
    k_prep_all<<<904, 256>>>(Wc, Wca, Wex, Wey, We);
    cudaEventRecord(evPrep, 0);

    // s1: expand branch
    cudaStreamWaitEvent(s1, evPrep, 0);
    k_normlin_h<<<32, 512, SM_NORMLIN_BYTES, s1>>>(lig, (const __half*)pWhx, bex, gex, beex, (float*)pxf);
    k_normlin_h<<<128, 512, SM_NORMLIN_BYTES, s1>>>(rec, (const __half*)pWhy, bey, gey, beey, (float*)pyf);
    k_expand<<<dim3(8, 8, 16), 256, EXP_SMEM_BYTES, s1>>>(oE);
    cudaEventRecord(ev1, s1);

    // s2: edge branch
    cudaStreamWaitEvent(s2, evPrep, 0);
    k_zero<<<4096, 256, 0, s2>>>((float4*)oL);
    k_edge_h<<<256, 256, SM_EDGE_BYTES, s2>>>(lig, eb, es, ed, be, oL);
    cudaEventRecord(ev2, s2);

    // s0: contract chain (the critical path)
    k_prep_ll<<<8192, 512>>>(ll);
    k_contract<<<152, 512, SM_CONTRACT_BYTES>>>(mask, bc, gcc, bec, bca, oC);

    // join
    cudaStreamWaitEvent(0, ev1, 0);
    cudaStreamWaitEvent(0, ev2, 0);
}